// round 1
// baseline (speedup 1.0000x reference)
#include <cuda_runtime.h>
#include <math.h>

// ---------------- problem constants ----------------
#define BSZ   8
#define SEQL  512
#define NSC   4096
#define FD    512
#define ROWS  (BSZ*SEQL)        // 4096
#define KVROWS (BSZ*NSC)        // 32768

// ---------------- scratch (device globals; no allocation allowed) ----------
__device__ float g_h   [ROWS*FD];
__device__ float g_qkv [ROWS*3*FD];
__device__ float g_o   [ROWS*FD];
__device__ float g_x   [ROWS*FD];
__device__ float g_h2  [ROWS*FD];
__device__ float g_ff  [ROWS*FD];
__device__ float g_msca[ROWS*FD];
__device__ float g_qsa [ROWS*FD];
__device__ float g_kv  [KVROWS*2*FD];
__device__ float g_sm  [ROWS*FD];
__device__ float g_smf [ROWS*FD];
__device__ float g_cat [ROWS*2*FD];
__device__ float g_mh  [ROWS*4*FD];

// ---------------- f32x2 helpers (Blackwell packed fp32: 2x FFMA throughput) --
__device__ __forceinline__ unsigned long long pack2(float lo, float hi) {
    unsigned long long r;
    asm("mov.b64 %0, {%1, %2};" : "=l"(r) : "f"(lo), "f"(hi));
    return r;
}
__device__ __forceinline__ void unpack2(unsigned long long v, float& lo, float& hi) {
    asm("mov.b64 {%0, %1}, %2;" : "=f"(lo), "=f"(hi) : "l"(v));
}
__device__ __forceinline__ unsigned long long ffma2(unsigned long long a,
                                                    unsigned long long b,
                                                    unsigned long long c) {
    unsigned long long d;
    asm("fma.rn.f32x2 %0, %1, %2, %3;" : "=l"(d) : "l"(a), "l"(b), "l"(c));
    return d;
}

__device__ __forceinline__ float gelu_exact(float x) {
    return 0.5f * x * (1.0f + erff(x * 0.70710678118654752f));
}

// ---------------- tiled SGEMM:  C[M,N] = epi( A[M,K] @ W[N,K]^T ) -----------
// BM=128, BN=64, BK=16, 256 threads, 8x4 micro-tile via f32x2 row pairs.
// Requires M%128==0, N%64==0, K%16==0 (true for every call here).
template<bool GELU>
__global__ void __launch_bounds__(256)
sgemm_kernel(const float* __restrict__ A, const float* __restrict__ W,
             const float* __restrict__ bias, const float* __restrict__ res,
             float* __restrict__ C, int M, int N, int K, float alpha) {
    __shared__ __align__(16) float As[16*132];   // padded stride 132
    __shared__ __align__(16) float Bs[16*68];    // padded stride 68

    const int n0 = blockIdx.x * 64;
    const int m0 = blockIdx.y * 128;
    const int tid = threadIdx.x;
    const int tx = tid & 15;     // 16 col-groups
    const int ty = tid >> 4;     // 16 row-groups

    unsigned long long acc2[4][4];
    #pragma unroll
    for (int r = 0; r < 4; r++)
        #pragma unroll
        for (int j = 0; j < 4; j++) acc2[r][j] = 0ULL;

    for (int k0 = 0; k0 < K; k0 += 16) {
        // load A tile (128x16) transposed into As[k][m]
        #pragma unroll
        for (int i = tid; i < 128*16; i += 256) {
            int m = i >> 4, k = i & 15;
            As[k*132 + m] = A[(size_t)(m0 + m) * K + k0 + k];
        }
        // load B tile (64x16) into Bs[k][n]
        #pragma unroll
        for (int i = tid; i < 64*16; i += 256) {
            int n = i >> 4, k = i & 15;
            Bs[k*68 + n] = W[(size_t)(n0 + n) * K + k0 + k];
        }
        __syncthreads();

        #pragma unroll
        for (int k = 0; k < 16; k++) {
            unsigned long long a2[4];
            #pragma unroll
            for (int r = 0; r < 4; r++)
                a2[r] = *reinterpret_cast<const unsigned long long*>(
                            As + k*132 + ty*8 + 2*r);
            unsigned long long b2[4];
            #pragma unroll
            for (int j = 0; j < 4; j++) {
                float bv = Bs[k*68 + tx*4 + j];
                b2[j] = pack2(bv, bv);
            }
            #pragma unroll
            for (int r = 0; r < 4; r++)
                #pragma unroll
                for (int j = 0; j < 4; j++)
                    acc2[r][j] = ffma2(a2[r], b2[j], acc2[r][j]);
        }
        __syncthreads();
    }

    // epilogue: v = (acc + bias)*alpha -> [gelu] -> [+res]
    #pragma unroll
    for (int r = 0; r < 4; r++) {
        #pragma unroll
        for (int j = 0; j < 4; j++) {
            float lo, hi;
            unpack2(acc2[r][j], lo, hi);
            int col = n0 + tx*4 + j;
            float bcol = bias[col];
            #pragma unroll
            for (int u = 0; u < 2; u++) {
                int row = m0 + ty*8 + 2*r + u;
                float v = ((u == 0 ? lo : hi) + bcol) * alpha;
                if (GELU) v = gelu_exact(v);
                if (res) v += res[(size_t)row * N + col];
                C[(size_t)row * N + col] = v;
            }
        }
    }
}

// ---------------- LayerNorm over last dim (512), one block per row ----------
__global__ void __launch_bounds__(128)
ln_kernel(const float* __restrict__ x, const float* __restrict__ g,
          const float* __restrict__ b, float* __restrict__ out) {
    __shared__ float red[4];
    const int row = blockIdx.x;
    const float* xr = x + (size_t)row * 512;
    float v[4];
    float s = 0.f;
    #pragma unroll
    for (int i = 0; i < 4; i++) { v[i] = xr[threadIdx.x + 128*i]; s += v[i]; }
    #pragma unroll
    for (int off = 16; off; off >>= 1) s += __shfl_xor_sync(0xffffffffu, s, off);
    if ((threadIdx.x & 31) == 0) red[threadIdx.x >> 5] = s;
    __syncthreads();
    s = red[0] + red[1] + red[2] + red[3];
    const float mean = s * (1.f/512.f);
    __syncthreads();
    float ss = 0.f;
    #pragma unroll
    for (int i = 0; i < 4; i++) { float d = v[i] - mean; ss += d*d; }
    #pragma unroll
    for (int off = 16; off; off >>= 1) ss += __shfl_xor_sync(0xffffffffu, ss, off);
    if ((threadIdx.x & 31) == 0) red[threadIdx.x >> 5] = ss;
    __syncthreads();
    ss = red[0] + red[1] + red[2] + red[3];
    const float rstd = rsqrtf(ss * (1.f/512.f) + 1e-5f);
    float* orow = out + (size_t)row * 512;
    #pragma unroll
    for (int i = 0; i < 4; i++) {
        int c = threadIdx.x + 128*i;
        orow[c] = (v[i] - mean) * rstd * g[c] + b[c];
    }
}

// ---------------- encoder self-attention (flash, fp32) ----------------------
// H=8, dh=64, L=512. grid: (qtile=8, b*8+h=64), 256 thr.
// smem: Qs,Ks,Vs,Ps each 64x65.
#define ENC_SMEM_BYTES (4*64*65*4)
__global__ void __launch_bounds__(256)
enc_attn_kernel(const float* __restrict__ qkv, float* __restrict__ o_out) {
    extern __shared__ float smem[];
    float* Qs = smem;
    float* Ks = Qs + 64*65;
    float* Vs = Ks + 64*65;
    float* Ps = Vs + 64*65;

    const int b  = blockIdx.y >> 3;
    const int h  = blockIdx.y & 7;
    const int q0 = blockIdx.x * 64;
    const int tid = threadIdx.x;
    const int tx = tid & 15, ty = tid >> 4;
    const float scale = 0.125f;  // 64^-0.5

    const float* qbase = qkv + (size_t)(b*512 + q0) * 1536 + h*64;
    for (int i = tid; i < 64*64; i += 256) {
        int r = i >> 6, c = i & 63;
        Qs[r*65 + c] = qbase[(size_t)r*1536 + c] * scale;
    }

    float m_i[4], l_i[4], acc[4][4];
    #pragma unroll
    for (int i = 0; i < 4; i++) {
        m_i[i] = -1e30f; l_i[i] = 0.f;
        #pragma unroll
        for (int j = 0; j < 4; j++) acc[i][j] = 0.f;
    }

    for (int kt = 0; kt < 8; kt++) {
        __syncthreads();
        const float* kbase = qkv + (size_t)(b*512 + kt*64) * 1536 + 512 + h*64;
        for (int i = tid; i < 64*64; i += 256) {
            int r = i >> 6, c = i & 63;
            Ks[r*65 + c] = kbase[(size_t)r*1536 + c];
            Vs[r*65 + c] = kbase[(size_t)r*1536 + 512 + c];
        }
        __syncthreads();

        float s[4][4];
        #pragma unroll
        for (int i = 0; i < 4; i++)
            #pragma unroll
            for (int j = 0; j < 4; j++) s[i][j] = 0.f;

        #pragma unroll 8
        for (int kk = 0; kk < 64; kk++) {
            float qv[4], kv_[4];
            #pragma unroll
            for (int i = 0; i < 4; i++) qv[i]  = Qs[(ty*4 + i)*65 + kk];
            #pragma unroll
            for (int j = 0; j < 4; j++) kv_[j] = Ks[(tx*4 + j)*65 + kk];
            #pragma unroll
            for (int i = 0; i < 4; i++)
                #pragma unroll
                for (int j = 0; j < 4; j++) s[i][j] += qv[i] * kv_[j];
        }

        #pragma unroll
        for (int i = 0; i < 4; i++) {
            float rm = s[i][0];
            #pragma unroll
            for (int j = 1; j < 4; j++) rm = fmaxf(rm, s[i][j]);
            #pragma unroll
            for (int off = 8; off; off >>= 1)
                rm = fmaxf(rm, __shfl_xor_sync(0xffffffffu, rm, off));
            float mn = fmaxf(m_i[i], rm);
            float corr = __expf(m_i[i] - mn);
            float rs = 0.f;
            #pragma unroll
            for (int j = 0; j < 4; j++) {
                float p = __expf(s[i][j] - mn);
                s[i][j] = p; rs += p;
            }
            #pragma unroll
            for (int off = 8; off; off >>= 1)
                rs += __shfl_xor_sync(0xffffffffu, rs, off);
            l_i[i] = l_i[i] * corr + rs;
            m_i[i] = mn;
            #pragma unroll
            for (int j = 0; j < 4; j++) acc[i][j] *= corr;
            #pragma unroll
            for (int j = 0; j < 4; j++) Ps[(ty*4 + i)*65 + tx*4 + j] = s[i][j];
        }
        __syncthreads();

        #pragma unroll 8
        for (int kk = 0; kk < 64; kk++) {
            float pv[4], vv[4];
            #pragma unroll
            for (int i = 0; i < 4; i++) pv[i] = Ps[(ty*4 + i)*65 + kk];
            #pragma unroll
            for (int j = 0; j < 4; j++) vv[j] = Vs[kk*65 + tx*4 + j];
            #pragma unroll
            for (int i = 0; i < 4; i++)
                #pragma unroll
                for (int j = 0; j < 4; j++) acc[i][j] += pv[i] * vv[j];
        }
    }

    #pragma unroll
    for (int i = 0; i < 4; i++) {
        float inv = 1.f / l_i[i];
        #pragma unroll
        for (int j = 0; j < 4; j++)
            o_out[(size_t)(b*512 + q0 + ty*4 + i)*512 + h*64 + tx*4 + j] =
                acc[i][j] * inv;
    }
}

// ---------------- semantic-aware cross-attention (flash, fp32) --------------
// H=4, dh=128, L=512, NKV=4096, + spatial prior added to logits.
// Q layout is the torch-faithful flat view: q[b][h*65536 + l*128 + c].
// grid: (qtile=8, b*4+h=32), 256 thr.
#define SA_SMEM_BYTES ((3*64*129 + 64*65)*4)
__global__ void __launch_bounds__(256)
sa_attn_kernel(const float* __restrict__ qf, const float* __restrict__ kvf,
               const float* __restrict__ prior, float* __restrict__ sm_out) {
    extern __shared__ float smem[];
    float* Qs = smem;             // 64 x 129
    float* Ks = Qs + 64*129;      // 64 x 129
    float* Vs = Ks + 64*129;      // 64 x 129
    float* Ps = Vs + 64*129;      // 64 x 65

    const int b  = blockIdx.y >> 2;
    const int h  = blockIdx.y & 3;
    const int q0 = blockIdx.x * 64;
    const int tid = threadIdx.x;
    const int tx = tid & 15, ty = tid >> 4;

    const float* qb = qf + (size_t)b*262144 + (size_t)h*65536 + (size_t)q0*128;
    for (int i = tid; i < 64*128; i += 256)
        Qs[(i >> 7)*129 + (i & 127)] = qb[i];

    float m_i[4], l_i[4], acc[4][8];
    #pragma unroll
    for (int i = 0; i < 4; i++) {
        m_i[i] = -1e30f; l_i[i] = 0.f;
        #pragma unroll
        for (int j = 0; j < 8; j++) acc[i][j] = 0.f;
    }

    for (int kt = 0; kt < 64; kt++) {
        __syncthreads();
        const float* kb = kvf + (size_t)(b*4096 + kt*64) * 1024 + h*128;
        for (int i = tid; i < 64*128; i += 256) {
            int r = i >> 7, c = i & 127;
            Ks[r*129 + c] = kb[(size_t)r*1024 + c];
            Vs[r*129 + c] = kb[(size_t)r*1024 + 512 + c];
        }
        __syncthreads();

        float s[4][4];
        const float* pb = prior + (size_t)(b*512 + q0) * 4096 + kt*64;
        #pragma unroll
        for (int i = 0; i < 4; i++)
            #pragma unroll
            for (int j = 0; j < 4; j++)
                s[i][j] = pb[(size_t)(ty*4 + i)*4096 + tx*4 + j];

        #pragma unroll 8
        for (int kk = 0; kk < 128; kk++) {
            float qv[4], kv_[4];
            #pragma unroll
            for (int i = 0; i < 4; i++) qv[i]  = Qs[(ty*4 + i)*129 + kk];
            #pragma unroll
            for (int j = 0; j < 4; j++) kv_[j] = Ks[(tx*4 + j)*129 + kk];
            #pragma unroll
            for (int i = 0; i < 4; i++)
                #pragma unroll
                for (int j = 0; j < 4; j++) s[i][j] += qv[i] * kv_[j];
        }

        #pragma unroll
        for (int i = 0; i < 4; i++) {
            float rm = s[i][0];
            #pragma unroll
            for (int j = 1; j < 4; j++) rm = fmaxf(rm, s[i][j]);
            #pragma unroll
            for (int off = 8; off; off >>= 1)
                rm = fmaxf(rm, __shfl_xor_sync(0xffffffffu, rm, off));
            float mn = fmaxf(m_i[i], rm);
            float corr = __expf(m_i[i] - mn);
            float rs = 0.f;
            #pragma unroll
            for (int j = 0; j < 4; j++) {
                float p = __expf(s[i][j] - mn);
                s[i][j] = p; rs += p;
            }
            #pragma unroll
            for (int off = 8; off; off >>= 1)
                rs += __shfl_xor_sync(0xffffffffu, rs, off);
            l_i[i] = l_i[i] * corr + rs;
            m_i[i] = mn;
            #pragma unroll
            for (int j = 0; j < 8; j++) acc[i][j] *= corr;
            #pragma unroll
            for (int j = 0; j < 4; j++) Ps[(ty*4 + i)*65 + tx*4 + j] = s[i][j];
        }
        __syncthreads();

        #pragma unroll 8
        for (int kk = 0; kk < 64; kk++) {
            float pv[4], vv[8];
            #pragma unroll
            for (int i = 0; i < 4; i++) pv[i] = Ps[(ty*4 + i)*65 + kk];
            #pragma unroll
            for (int j = 0; j < 8; j++) vv[j] = Vs[kk*129 + tx + 16*j];
            #pragma unroll
            for (int i = 0; i < 4; i++)
                #pragma unroll
                for (int j = 0; j < 8; j++) acc[i][j] += pv[i] * vv[j];
        }
    }

    #pragma unroll
    for (int i = 0; i < 4; i++) {
        float inv = 1.f / l_i[i];
        #pragma unroll
        for (int j = 0; j < 8; j++)
            sm_out[(size_t)(b*512 + q0 + ty*4 + i)*512 + h*128 + tx + 16*j] =
                acc[i][j] * inv;
    }
}

// ---------------- concat [msca | smf] -> cat (row 1024 wide) ----------------
__global__ void __launch_bounds__(256)
concat_kernel(const float* __restrict__ a, const float* __restrict__ b,
              float* __restrict__ cat) {
    const int row = blockIdx.x;
    #pragma unroll
    for (int c = threadIdx.x; c < 1024; c += 256)
        cat[(size_t)row*1024 + c] = (c < 512) ? a[(size_t)row*512 + c]
                                              : b[(size_t)row*512 + c - 512];
}

// ---------------- launch --------------------------------------------------
extern "C" void kernel_launch(void* const* d_in, const int* in_sizes, int n_in,
                              void* d_out, int out_size) {
    const float* motion      = (const float*)d_in[0];
    const float* scene_feats = (const float*)d_in[2];
    const float* prior       = (const float*)d_in[3];
    const float* ln1g = (const float*)d_in[4];
    const float* ln1b = (const float*)d_in[5];
    const float* qkvw = (const float*)d_in[6];
    const float* qkvb = (const float*)d_in[7];
    const float* outw = (const float*)d_in[8];
    const float* outb = (const float*)d_in[9];
    const float* ln2g = (const float*)d_in[10];
    const float* ln2b = (const float*)d_in[11];
    const float* ff1w = (const float*)d_in[12];
    const float* ff1b = (const float*)d_in[13];
    const float* ff2w = (const float*)d_in[14];
    const float* ff2b = (const float*)d_in[15];
    const float* saqw = (const float*)d_in[16];
    const float* saqb = (const float*)d_in[17];
    const float* sakvw = (const float*)d_in[18];
    const float* sakvb = (const float*)d_in[19];
    const float* saow = (const float*)d_in[20];
    const float* saob = (const float*)d_in[21];
    const float* fc1w = (const float*)d_in[22];
    const float* fc1b = (const float*)d_in[23];
    const float* fc2w = (const float*)d_in[24];
    const float* fc2b = (const float*)d_in[25];
    float* out = (float*)d_out;

    float *p_h, *p_qkv, *p_o, *p_x, *p_h2, *p_ff, *p_msca, *p_qsa, *p_kv,
          *p_sm, *p_smf, *p_cat, *p_mh;
    cudaGetSymbolAddress((void**)&p_h,    g_h);
    cudaGetSymbolAddress((void**)&p_qkv,  g_qkv);
    cudaGetSymbolAddress((void**)&p_o,    g_o);
    cudaGetSymbolAddress((void**)&p_x,    g_x);
    cudaGetSymbolAddress((void**)&p_h2,   g_h2);
    cudaGetSymbolAddress((void**)&p_ff,   g_ff);
    cudaGetSymbolAddress((void**)&p_msca, g_msca);
    cudaGetSymbolAddress((void**)&p_qsa,  g_qsa);
    cudaGetSymbolAddress((void**)&p_kv,   g_kv);
    cudaGetSymbolAddress((void**)&p_sm,   g_sm);
    cudaGetSymbolAddress((void**)&p_smf,  g_smf);
    cudaGetSymbolAddress((void**)&p_cat,  g_cat);
    cudaGetSymbolAddress((void**)&p_mh,   g_mh);

    cudaFuncSetAttribute(enc_attn_kernel,
                         cudaFuncAttributeMaxDynamicSharedMemorySize,
                         ENC_SMEM_BYTES);
    cudaFuncSetAttribute(sa_attn_kernel,
                         cudaFuncAttributeMaxDynamicSharedMemorySize,
                         SA_SMEM_BYTES);

    const float sa_scale = 0.044194173824159216f;  // 512^-0.5

    // motion encoder: pre-norm MHA + residual
    ln_kernel<<<ROWS, 128>>>(motion, ln1g, ln1b, p_h);
    sgemm_kernel<false><<<dim3(1536/64, ROWS/128), 256>>>(
        p_h, qkvw, qkvb, nullptr, p_qkv, ROWS, 1536, 512, 1.f);
    enc_attn_kernel<<<dim3(8, 64), 256, ENC_SMEM_BYTES>>>(p_qkv, p_o);
    sgemm_kernel<false><<<dim3(512/64, ROWS/128), 256>>>(
        p_o, outw, outb, motion, p_x, ROWS, 512, 512, 1.f);

    // pre-norm MLP + residual
    ln_kernel<<<ROWS, 128>>>(p_x, ln2g, ln2b, p_h2);
    sgemm_kernel<true><<<dim3(512/64, ROWS/128), 256>>>(
        p_h2, ff1w, ff1b, nullptr, p_ff, ROWS, 512, 512, 1.f);
    sgemm_kernel<false><<<dim3(512/64, ROWS/128), 256>>>(
        p_ff, ff2w, ff2b, p_x, p_msca, ROWS, 512, 512, 1.f);

    // semantic-aware attention
    sgemm_kernel<false><<<dim3(512/64, ROWS/128), 256>>>(
        p_msca, saqw, saqb, nullptr, p_qsa, ROWS, 512, 512, sa_scale);
    sgemm_kernel<false><<<dim3(1024/64, KVROWS/128), 256>>>(
        scene_feats, sakvw, sakvb, nullptr, p_kv, KVROWS, 1024, 512, 1.f);
    sa_attn_kernel<<<dim3(8, 32), 256, SA_SMEM_BYTES>>>(p_qsa, p_kv, prior, p_sm);
    sgemm_kernel<false><<<dim3(512/64, ROWS/128), 256>>>(
        p_sm, saow, saob, nullptr, p_smf, ROWS, 512, 512, 1.f);

    // concat + MLP
    concat_kernel<<<ROWS, 256>>>(p_msca, p_smf, p_cat);
    sgemm_kernel<true><<<dim3(2048/64, ROWS/128), 256>>>(
        p_cat, fc1w, fc1b, nullptr, p_mh, ROWS, 2048, 1024, 1.f);
    sgemm_kernel<false><<<dim3(512/64, ROWS/128), 256>>>(
        p_mh, fc2w, fc2b, nullptr, out, ROWS, 512, 2048, 1.f);
}

// round 3
// speedup vs baseline: 1.5200x; 1.5200x over previous
#include <cuda_runtime.h>
#include <cuda_bf16.h>
#include <math.h>

// ---------------- problem constants ----------------
#define BSZ   8
#define SEQL  512
#define NSC   4096
#define FD    512
#define ROWS  (BSZ*SEQL)        // 4096
#define KVROWS (BSZ*NSC)        // 32768

// ---------------- scratch (device globals; no allocation allowed) ----------
__device__ float g_h   [ROWS*FD];
__device__ float g_qkv [ROWS*3*FD];
__device__ float g_o   [ROWS*FD];
__device__ float g_x   [ROWS*FD];
__device__ float g_h2  [ROWS*FD];
__device__ float g_ff  [ROWS*FD];
__device__ float g_msca[ROWS*FD];
__device__ float g_qsa [ROWS*FD];
__device__ float g_kv  [KVROWS*2*FD];
__device__ float g_sm  [ROWS*FD];
__device__ float g_smf [ROWS*FD];
__device__ float g_cat [ROWS*2*FD];
__device__ float g_mh  [ROWS*4*FD];

// ---------------- helpers ----------------
__device__ __forceinline__ unsigned smem_u32(const void* p) {
    unsigned r;
    asm("{ .reg .u64 t; cvta.to.shared.u64 t, %1; cvt.u32.u64 %0, t; }"
        : "=r"(r) : "l"(p));
    return r;
}

// split fp32 pair -> bf16x2 hi + bf16x2 lo (cvt.rn.bf16x2.f32 packs %1 high, %2 low)
__device__ __forceinline__ void split2(float x0, float x1,
                                       unsigned& hi2, unsigned& lo2) {
    asm("cvt.rn.bf16x2.f32 %0, %1, %2;" : "=r"(hi2) : "f"(x1), "f"(x0));
    float h0 = __uint_as_float(hi2 << 16);
    float h1 = __uint_as_float(hi2 & 0xffff0000u);
    float l0 = x0 - h0;
    float l1 = x1 - h1;
    asm("cvt.rn.bf16x2.f32 %0, %1, %2;" : "=r"(lo2) : "f"(l1), "f"(l0));
}

__device__ __forceinline__ float gelu_exact(float x) {
    return 0.5f * x * (1.0f + erff(x * 0.70710678118654752f));
}

#define LDSM4(r, addr) \
    asm volatile("ldmatrix.sync.aligned.m8n8.x4.shared.b16 {%0,%1,%2,%3}, [%4];" \
        : "=r"((r)[0]), "=r"((r)[1]), "=r"((r)[2]), "=r"((r)[3]) : "r"(addr))

#define MMA16816(d, a, b0, b1) \
    asm volatile("mma.sync.aligned.m16n8k16.row.col.f32.bf16.bf16.f32 " \
        "{%0,%1,%2,%3}, {%4,%5,%6,%7}, {%8,%9}, {%0,%1,%2,%3};" \
        : "+f"((d)[0]), "+f"((d)[1]), "+f"((d)[2]), "+f"((d)[3]) \
        : "r"((a)[0]), "r"((a)[1]), "r"((a)[2]), "r"((a)[3]), \
          "r"(b0), "r"(b1))

// ========== HMMA bf16-split GEMM:  C[M,N] = epi( A[M,K] @ W[N,K]^T ) ========
// Block 128x64, BK=32, 8 warps (4m x 2n), warp tile 32x32.
// D = Ah@Bh + Ah@Bl + Al@Bh (fp32 accum). Needs M%128==0, N%64==0, K%32==0.
#define PADW 40   // smem row stride in bf16 units (80B) -> conflict-free ldmatrix

template<bool GELU>
__global__ void __launch_bounds__(256, 2)
tmma_gemm(const float* __restrict__ A, const float* __restrict__ W,
          const float* __restrict__ bias, const float* __restrict__ res,
          float* __restrict__ C, int M, int N, int K, float alpha) {
    __shared__ __align__(16) unsigned short sAh[128*PADW];
    __shared__ __align__(16) unsigned short sAl[128*PADW];
    __shared__ __align__(16) unsigned short sBh[64*PADW];
    __shared__ __align__(16) unsigned short sBl[64*PADW];

    const int tid = threadIdx.x;
    const int lane = tid & 31;
    const int wid = tid >> 5;
    const int wm = wid & 3;          // 4 m-slabs of 32
    const int wn = wid >> 2;         // 2 n-slabs of 32
    const int m0 = blockIdx.y * 128;
    const int n0 = blockIdx.x * 64;

    float acc[2][4][4];
    #pragma unroll
    for (int mt = 0; mt < 2; mt++)
        #pragma unroll
        for (int nt = 0; nt < 4; nt++)
            #pragma unroll
            for (int e = 0; e < 4; e++) acc[mt][nt][e] = 0.f;

    const unsigned aH = smem_u32(sAh), aL = smem_u32(sAl);
    const unsigned bH = smem_u32(sBh), bL = smem_u32(sBl);

    // ldmatrix lane -> row/col offsets
    const int lr = lane & 7;
    const int arow = lr + ((lane >> 3) & 1) * 8;   // row within 16-row tile
    const int acol = (lane >> 4) * 8;              // k offset 0 / 8
    const int brow = (lane >> 4) * 8 + lr;         // n-row within 16 (2 n-tiles)
    const int bcol = ((lane >> 3) & 1) * 8;        // k offset 0 / 8

    for (int k0 = 0; k0 < K; k0 += 32) {
        __syncthreads();
        // ---- load & convert A (128x32) and W (64x32) into hi/lo planes ----
        {
            const float* Ab = A + (size_t)m0 * K + k0;
            #pragma unroll
            for (int i = 0; i < 4; i++) {
                int u = tid + i * 256;
                int r = u >> 3, q = u & 7;
                float4 v = *(const float4*)(Ab + (size_t)r * K + q * 4);
                unsigned h01, l01, h23, l23;
                split2(v.x, v.y, h01, l01);
                split2(v.z, v.w, h23, l23);
                *(uint2*)(sAh + r*PADW + q*4) = make_uint2(h01, h23);
                *(uint2*)(sAl + r*PADW + q*4) = make_uint2(l01, l23);
            }
            const float* Wb = W + (size_t)n0 * K + k0;
            #pragma unroll
            for (int i = 0; i < 2; i++) {
                int u = tid + i * 256;
                int r = u >> 3, q = u & 7;
                float4 v = *(const float4*)(Wb + (size_t)r * K + q * 4);
                unsigned h01, l01, h23, l23;
                split2(v.x, v.y, h01, l01);
                split2(v.z, v.w, h23, l23);
                *(uint2*)(sBh + r*PADW + q*4) = make_uint2(h01, h23);
                *(uint2*)(sBl + r*PADW + q*4) = make_uint2(l01, l23);
            }
        }
        __syncthreads();

        // ---- 2 k16 steps of MMA ----
        #pragma unroll
        for (int ks = 0; ks < 2; ks++) {
            unsigned ah[2][4], al[2][4], bh[2][4], bl[2][4];
            #pragma unroll
            for (int mt = 0; mt < 2; mt++) {
                unsigned off =
                    (unsigned)((wm*32 + mt*16 + arow) * PADW + ks*16 + acol) * 2u;
                LDSM4(ah[mt], aH + off);
                LDSM4(al[mt], aL + off);
            }
            #pragma unroll
            for (int np = 0; np < 2; np++) {
                unsigned off =
                    (unsigned)((wn*32 + np*16 + brow) * PADW + ks*16 + bcol) * 2u;
                LDSM4(bh[np], bH + off);
                LDSM4(bl[np], bL + off);
            }
            #pragma unroll
            for (int mt = 0; mt < 2; mt++) {
                #pragma unroll
                for (int nt = 0; nt < 4; nt++) {
                    const int p = nt >> 1, o = (nt & 1) * 2;
                    MMA16816(acc[mt][nt], ah[mt], bh[p][o], bh[p][o+1]);
                    MMA16816(acc[mt][nt], ah[mt], bl[p][o], bl[p][o+1]);
                    MMA16816(acc[mt][nt], al[mt], bh[p][o], bh[p][o+1]);
                }
            }
        }
    }

    // ---- epilogue ----
    const int erow = lane >> 2;
    const int ecol = (lane & 3) * 2;
    #pragma unroll
    for (int mt = 0; mt < 2; mt++) {
        #pragma unroll
        for (int nt = 0; nt < 4; nt++) {
            int row = m0 + wm*32 + mt*16 + erow;
            int col = n0 + wn*32 + nt*8 + ecol;
            float2 bv = *(const float2*)(bias + col);
            #pragma unroll
            for (int half = 0; half < 2; half++) {
                int r = row + half * 8;
                float v0 = (acc[mt][nt][half*2 + 0] + bv.x) * alpha;
                float v1 = (acc[mt][nt][half*2 + 1] + bv.y) * alpha;
                if (GELU) { v0 = gelu_exact(v0); v1 = gelu_exact(v1); }
                if (res) {
                    float2 rv = *(const float2*)(res + (size_t)r * N + col);
                    v0 += rv.x; v1 += rv.y;
                }
                *(float2*)(C + (size_t)r * N + col) = make_float2(v0, v1);
            }
        }
    }
}

// ---------------- LayerNorm over last dim (512), one block per row ----------
__global__ void __launch_bounds__(128)
ln_kernel(const float* __restrict__ x, const float* __restrict__ g,
          const float* __restrict__ b, float* __restrict__ out) {
    __shared__ float red[4];
    const int row = blockIdx.x;
    const float* xr = x + (size_t)row * 512;
    float v[4];
    float s = 0.f;
    #pragma unroll
    for (int i = 0; i < 4; i++) { v[i] = xr[threadIdx.x + 128*i]; s += v[i]; }
    #pragma unroll
    for (int off = 16; off; off >>= 1) s += __shfl_xor_sync(0xffffffffu, s, off);
    if ((threadIdx.x & 31) == 0) red[threadIdx.x >> 5] = s;
    __syncthreads();
    s = red[0] + red[1] + red[2] + red[3];
    const float mean = s * (1.f/512.f);
    __syncthreads();
    float ss = 0.f;
    #pragma unroll
    for (int i = 0; i < 4; i++) { float d = v[i] - mean; ss += d*d; }
    #pragma unroll
    for (int off = 16; off; off >>= 1) ss += __shfl_xor_sync(0xffffffffu, ss, off);
    if ((threadIdx.x & 31) == 0) red[threadIdx.x >> 5] = ss;
    __syncthreads();
    ss = red[0] + red[1] + red[2] + red[3];
    const float rstd = rsqrtf(ss * (1.f/512.f) + 1e-5f);
    float* orow = out + (size_t)row * 512;
    #pragma unroll
    for (int i = 0; i < 4; i++) {
        int c = threadIdx.x + 128*i;
        orow[c] = (v[i] - mean) * rstd * g[c] + b[c];
    }
}

// ---------------- encoder self-attention (flash, fp32) ----------------------
#define ENC_SMEM_BYTES (4*64*65*4)
__global__ void __launch_bounds__(256)
enc_attn_kernel(const float* __restrict__ qkv, float* __restrict__ o_out) {
    extern __shared__ float smemf[];
    float* Qs = smemf;
    float* Ks = Qs + 64*65;
    float* Vs = Ks + 64*65;
    float* Ps = Vs + 64*65;

    const int b  = blockIdx.y >> 3;
    const int h  = blockIdx.y & 7;
    const int q0 = blockIdx.x * 64;
    const int tid = threadIdx.x;
    const int tx = tid & 15, ty = tid >> 4;
    const float scale = 0.125f;

    const float* qbase = qkv + (size_t)(b*512 + q0) * 1536 + h*64;
    for (int i = tid; i < 64*64; i += 256) {
        int r = i >> 6, c = i & 63;
        Qs[r*65 + c] = qbase[(size_t)r*1536 + c] * scale;
    }

    float m_i[4], l_i[4], acc[4][4];
    #pragma unroll
    for (int i = 0; i < 4; i++) {
        m_i[i] = -1e30f; l_i[i] = 0.f;
        #pragma unroll
        for (int j = 0; j < 4; j++) acc[i][j] = 0.f;
    }

    for (int kt = 0; kt < 8; kt++) {
        __syncthreads();
        const float* kbase = qkv + (size_t)(b*512 + kt*64) * 1536 + 512 + h*64;
        for (int i = tid; i < 64*64; i += 256) {
            int r = i >> 6, c = i & 63;
            Ks[r*65 + c] = kbase[(size_t)r*1536 + c];
            Vs[r*65 + c] = kbase[(size_t)r*1536 + 512 + c];
        }
        __syncthreads();

        float s[4][4];
        #pragma unroll
        for (int i = 0; i < 4; i++)
            #pragma unroll
            for (int j = 0; j < 4; j++) s[i][j] = 0.f;

        #pragma unroll 8
        for (int kk = 0; kk < 64; kk++) {
            float qv[4], kv_[4];
            #pragma unroll
            for (int i = 0; i < 4; i++) qv[i]  = Qs[(ty*4 + i)*65 + kk];
            #pragma unroll
            for (int j = 0; j < 4; j++) kv_[j] = Ks[(tx*4 + j)*65 + kk];
            #pragma unroll
            for (int i = 0; i < 4; i++)
                #pragma unroll
                for (int j = 0; j < 4; j++) s[i][j] += qv[i] * kv_[j];
        }

        #pragma unroll
        for (int i = 0; i < 4; i++) {
            float rm = s[i][0];
            #pragma unroll
            for (int j = 1; j < 4; j++) rm = fmaxf(rm, s[i][j]);
            #pragma unroll
            for (int off = 8; off; off >>= 1)
                rm = fmaxf(rm, __shfl_xor_sync(0xffffffffu, rm, off));
            float mn = fmaxf(m_i[i], rm);
            float corr = __expf(m_i[i] - mn);
            float rs = 0.f;
            #pragma unroll
            for (int j = 0; j < 4; j++) {
                float p = __expf(s[i][j] - mn);
                s[i][j] = p; rs += p;
            }
            #pragma unroll
            for (int off = 8; off; off >>= 1)
                rs += __shfl_xor_sync(0xffffffffu, rs, off);
            l_i[i] = l_i[i] * corr + rs;
            m_i[i] = mn;
            #pragma unroll
            for (int j = 0; j < 4; j++) acc[i][j] *= corr;
            #pragma unroll
            for (int j = 0; j < 4; j++) Ps[(ty*4 + i)*65 + tx*4 + j] = s[i][j];
        }
        __syncthreads();

        #pragma unroll 8
        for (int kk = 0; kk < 64; kk++) {
            float pv[4], vv[4];
            #pragma unroll
            for (int i = 0; i < 4; i++) pv[i] = Ps[(ty*4 + i)*65 + kk];
            #pragma unroll
            for (int j = 0; j < 4; j++) vv[j] = Vs[kk*65 + tx*4 + j];
            #pragma unroll
            for (int i = 0; i < 4; i++)
                #pragma unroll
                for (int j = 0; j < 4; j++) acc[i][j] += pv[i] * vv[j];
        }
    }

    #pragma unroll
    for (int i = 0; i < 4; i++) {
        float inv = 1.f / l_i[i];
        #pragma unroll
        for (int j = 0; j < 4; j++)
            o_out[(size_t)(b*512 + q0 + ty*4 + i)*512 + h*64 + tx*4 + j] =
                acc[i][j] * inv;
    }
}

// ---------------- semantic-aware cross-attention (flash, fp32) --------------
#define SA_SMEM_BYTES ((3*64*129 + 64*65)*4)
__global__ void __launch_bounds__(256)
sa_attn_kernel(const float* __restrict__ qf, const float* __restrict__ kvf,
               const float* __restrict__ prior, float* __restrict__ sm_out) {
    extern __shared__ float smemf[];
    float* Qs = smemf;            // 64 x 129
    float* Ks = Qs + 64*129;      // 64 x 129
    float* Vs = Ks + 64*129;      // 64 x 129
    float* Ps = Vs + 64*129;      // 64 x 65

    const int b  = blockIdx.y >> 2;
    const int h  = blockIdx.y & 3;
    const int q0 = blockIdx.x * 64;
    const int tid = threadIdx.x;
    const int tx = tid & 15, ty = tid >> 4;

    const float* qb = qf + (size_t)b*262144 + (size_t)h*65536 + (size_t)q0*128;
    for (int i = tid; i < 64*128; i += 256)
        Qs[(i >> 7)*129 + (i & 127)] = qb[i];

    float m_i[4], l_i[4], acc[4][8];
    #pragma unroll
    for (int i = 0; i < 4; i++) {
        m_i[i] = -1e30f; l_i[i] = 0.f;
        #pragma unroll
        for (int j = 0; j < 8; j++) acc[i][j] = 0.f;
    }

    for (int kt = 0; kt < 64; kt++) {
        __syncthreads();
        const float* kb = kvf + (size_t)(b*4096 + kt*64) * 1024 + h*128;
        for (int i = tid; i < 64*128; i += 256) {
            int r = i >> 7, c = i & 127;
            Ks[r*129 + c] = kb[(size_t)r*1024 + c];
            Vs[r*129 + c] = kb[(size_t)r*1024 + 512 + c];
        }
        __syncthreads();

        float s[4][4];
        const float* pb = prior + (size_t)(b*512 + q0) * 4096 + kt*64;
        #pragma unroll
        for (int i = 0; i < 4; i++)
            #pragma unroll
            for (int j = 0; j < 4; j++)
                s[i][j] = pb[(size_t)(ty*4 + i)*4096 + tx*4 + j];

        #pragma unroll 8
        for (int kk = 0; kk < 128; kk++) {
            float qv[4], kv_[4];
            #pragma unroll
            for (int i = 0; i < 4; i++) qv[i]  = Qs[(ty*4 + i)*129 + kk];
            #pragma unroll
            for (int j = 0; j < 4; j++) kv_[j] = Ks[(tx*4 + j)*129 + kk];
            #pragma unroll
            for (int i = 0; i < 4; i++)
                #pragma unroll
                for (int j = 0; j < 4; j++) s[i][j] += qv[i] * kv_[j];
        }

        #pragma unroll
        for (int i = 0; i < 4; i++) {
            float rm = s[i][0];
            #pragma unroll
            for (int j = 1; j < 4; j++) rm = fmaxf(rm, s[i][j]);
            #pragma unroll
            for (int off = 8; off; off >>= 1)
                rm = fmaxf(rm, __shfl_xor_sync(0xffffffffu, rm, off));
            float mn = fmaxf(m_i[i], rm);
            float corr = __expf(m_i[i] - mn);
            float rs = 0.f;
            #pragma unroll
            for (int j = 0; j < 4; j++) {
                float p = __expf(s[i][j] - mn);
                s[i][j] = p; rs += p;
            }
            #pragma unroll
            for (int off = 8; off; off >>= 1)
                rs += __shfl_xor_sync(0xffffffffu, rs, off);
            l_i[i] = l_i[i] * corr + rs;
            m_i[i] = mn;
            #pragma unroll
            for (int j = 0; j < 8; j++) acc[i][j] *= corr;
            #pragma unroll
            for (int j = 0; j < 4; j++) Ps[(ty*4 + i)*65 + tx*4 + j] = s[i][j];
        }
        __syncthreads();

        #pragma unroll 8
        for (int kk = 0; kk < 64; kk++) {
            float pv[4], vv[8];
            #pragma unroll
            for (int i = 0; i < 4; i++) pv[i] = Ps[(ty*4 + i)*65 + kk];
            #pragma unroll
            for (int j = 0; j < 8; j++) vv[j] = Vs[kk*129 + tx + 16*j];
            #pragma unroll
            for (int i = 0; i < 4; i++)
                #pragma unroll
                for (int j = 0; j < 8; j++) acc[i][j] += pv[i] * vv[j];
        }
    }

    #pragma unroll
    for (int i = 0; i < 4; i++) {
        float inv = 1.f / l_i[i];
        #pragma unroll
        for (int j = 0; j < 8; j++)
            sm_out[(size_t)(b*512 + q0 + ty*4 + i)*512 + h*128 + tx + 16*j] =
                acc[i][j] * inv;
    }
}

// ---------------- concat [msca | smf] -> cat (row 1024 wide) ----------------
__global__ void __launch_bounds__(256)
concat_kernel(const float* __restrict__ a, const float* __restrict__ b,
              float* __restrict__ cat) {
    const int row = blockIdx.x;
    #pragma unroll
    for (int c = threadIdx.x; c < 1024; c += 256)
        cat[(size_t)row*1024 + c] = (c < 512) ? a[(size_t)row*512 + c]
                                              : b[(size_t)row*512 + c - 512];
}

// ---------------- launch --------------------------------------------------
extern "C" void kernel_launch(void* const* d_in, const int* in_sizes, int n_in,
                              void* d_out, int out_size) {
    const float* motion      = (const float*)d_in[0];
    const float* scene_feats = (const float*)d_in[2];
    const float* prior       = (const float*)d_in[3];
    const float* ln1g = (const float*)d_in[4];
    const float* ln1b = (const float*)d_in[5];
    const float* qkvw = (const float*)d_in[6];
    const float* qkvb = (const float*)d_in[7];
    const float* outw = (const float*)d_in[8];
    const float* outb = (const float*)d_in[9];
    const float* ln2g = (const float*)d_in[10];
    const float* ln2b = (const float*)d_in[11];
    const float* ff1w = (const float*)d_in[12];
    const float* ff1b = (const float*)d_in[13];
    const float* ff2w = (const float*)d_in[14];
    const float* ff2b = (const float*)d_in[15];
    const float* saqw = (const float*)d_in[16];
    const float* saqb = (const float*)d_in[17];
    const float* sakvw = (const float*)d_in[18];
    const float* sakvb = (const float*)d_in[19];
    const float* saow = (const float*)d_in[20];
    const float* saob = (const float*)d_in[21];
    const float* fc1w = (const float*)d_in[22];
    const float* fc1b = (const float*)d_in[23];
    const float* fc2w = (const float*)d_in[24];
    const float* fc2b = (const float*)d_in[25];
    float* out = (float*)d_out;

    float *p_h, *p_qkv, *p_o, *p_x, *p_h2, *p_ff, *p_msca, *p_qsa, *p_kv,
          *p_sm, *p_smf, *p_cat, *p_mh;
    cudaGetSymbolAddress((void**)&p_h,    g_h);
    cudaGetSymbolAddress((void**)&p_qkv,  g_qkv);
    cudaGetSymbolAddress((void**)&p_o,    g_o);
    cudaGetSymbolAddress((void**)&p_x,    g_x);
    cudaGetSymbolAddress((void**)&p_h2,   g_h2);
    cudaGetSymbolAddress((void**)&p_ff,   g_ff);
    cudaGetSymbolAddress((void**)&p_msca, g_msca);
    cudaGetSymbolAddress((void**)&p_qsa,  g_qsa);
    cudaGetSymbolAddress((void**)&p_kv,   g_kv);
    cudaGetSymbolAddress((void**)&p_sm,   g_sm);
    cudaGetSymbolAddress((void**)&p_smf,  g_smf);
    cudaGetSymbolAddress((void**)&p_cat,  g_cat);
    cudaGetSymbolAddress((void**)&p_mh,   g_mh);

    cudaFuncSetAttribute(enc_attn_kernel,
                         cudaFuncAttributeMaxDynamicSharedMemorySize,
                         ENC_SMEM_BYTES);
    cudaFuncSetAttribute(sa_attn_kernel,
                         cudaFuncAttributeMaxDynamicSharedMemorySize,
                         SA_SMEM_BYTES);

    const float sa_scale = 0.044194173824159216f;  // 512^-0.5

    // motion encoder: pre-norm MHA + residual
    ln_kernel<<<ROWS, 128>>>(motion, ln1g, ln1b, p_h);
    tmma_gemm<false><<<dim3(1536/64, ROWS/128), 256>>>(
        p_h, qkvw, qkvb, nullptr, p_qkv, ROWS, 1536, 512, 1.f);
    enc_attn_kernel<<<dim3(8, 64), 256, ENC_SMEM_BYTES>>>(p_qkv, p_o);
    tmma_gemm<false><<<dim3(512/64, ROWS/128), 256>>>(
        p_o, outw, outb, motion, p_x, ROWS, 512, 512, 1.f);

    // pre-norm MLP + residual
    ln_kernel<<<ROWS, 128>>>(p_x, ln2g, ln2b, p_h2);
    tmma_gemm<true><<<dim3(512/64, ROWS/128), 256>>>(
        p_h2, ff1w, ff1b, nullptr, p_ff, ROWS, 512, 512, 1.f);
    tmma_gemm<false><<<dim3(512/64, ROWS/128), 256>>>(
        p_ff, ff2w, ff2b, p_x, p_msca, ROWS, 512, 512, 1.f);

    // semantic-aware attention
    tmma_gemm<false><<<dim3(512/64, ROWS/128), 256>>>(
        p_msca, saqw, saqb, nullptr, p_qsa, ROWS, 512, 512, sa_scale);
    tmma_gemm<false><<<dim3(1024/64, KVROWS/128), 256>>>(
        scene_feats, sakvw, sakvb, nullptr, p_kv, KVROWS, 1024, 512, 1.f);
    sa_attn_kernel<<<dim3(8, 32), 256, SA_SMEM_BYTES>>>(p_qsa, p_kv, prior, p_sm);
    tmma_gemm<false><<<dim3(512/64, ROWS/128), 256>>>(
        p_sm, saow, saob, nullptr, p_smf, ROWS, 512, 512, 1.f);

    // concat + MLP
    concat_kernel<<<ROWS, 256>>>(p_msca, p_smf, p_cat);
    tmma_gemm<true><<<dim3(2048/64, ROWS/128), 256>>>(
        p_cat, fc1w, fc1b, nullptr, p_mh, ROWS, 2048, 1024, 1.f);
    tmma_gemm<false><<<dim3(512/64, ROWS/128), 256>>>(
        p_mh, fc2w, fc2b, nullptr, out, ROWS, 512, 2048, 1.f);
}

// round 4
// speedup vs baseline: 2.7400x; 1.8026x over previous
#include <cuda_runtime.h>
#include <cuda_bf16.h>
#include <math.h>

typedef unsigned short u16;

// ---------------- problem constants ----------------
#define BSZ   8
#define SEQL  512
#define NSC   4096
#define FD    512
#define ROWS  (BSZ*SEQL)        // 4096
#define KVROWS (BSZ*NSC)        // 32768

// ---------------- scratch (device globals; no allocation allowed) ----------
__device__ float g_qkv[ROWS*3*FD];
__device__ float g_x  [ROWS*FD];

// split bf16 plane bundles (hi/lo)
// weights: qkv 786432 | out 262144 | ff1 262144 | ff2 262144 | saq 262144 |
//          sakv 524288 | saout 262144 | fc1 2097152 | fc2 1048576  = 5767168
#define WO_QKV   0
#define WO_OUT   786432
#define WO_FF1   1048576
#define WO_FF2   1310720
#define WO_SAQ   1572864
#define WO_SAKV  1835008
#define WO_SAOUT 2359296
#define WO_FC1   2621440
#define WO_FC2   4718592
__device__ u16 w_hi[5767168];
__device__ u16 w_lo[5767168];

// activations: h 0 | o 2097152 | h2 4194304 | ff 6291456 | msca 8388608 |
//              sm 10485760 | smf 12582912 | mh 14680064 (8388608) | sf 23068672 (16777216)
#define AO_H    0
#define AO_O    2097152
#define AO_H2   4194304
#define AO_FF   6291456
#define AO_MSCA 8388608
#define AO_SM   10485760
#define AO_SMF  12582912
#define AO_MH   14680064
#define AO_SF   23068672
__device__ u16 a_hi[39845888];
__device__ u16 a_lo[39845888];

// single-bf16 planes: qsa 0 (2097152) | kv 2097152 (33554432)
#define BO_QSA 0
#define BO_KV  2097152
__device__ u16 a_b16[35651584];

// ---------------- helpers ----------------
__device__ __forceinline__ unsigned smem_u32(const void* p) {
    unsigned r;
    asm("{ .reg .u64 t; cvta.to.shared.u64 t, %1; cvt.u32.u64 %0, t; }"
        : "=r"(r) : "l"(p));
    return r;
}
__device__ __forceinline__ void split2(float x0, float x1,
                                       unsigned& hi2, unsigned& lo2) {
    asm("cvt.rn.bf16x2.f32 %0, %1, %2;" : "=r"(hi2) : "f"(x1), "f"(x0));
    float h0 = __uint_as_float(hi2 << 16);
    float h1 = __uint_as_float(hi2 & 0xffff0000u);
    float l0 = x0 - h0;
    float l1 = x1 - h1;
    asm("cvt.rn.bf16x2.f32 %0, %1, %2;" : "=r"(lo2) : "f"(l1), "f"(l0));
}
__device__ __forceinline__ unsigned pkbf(float lo, float hi) {
    unsigned r;
    asm("cvt.rn.bf16x2.f32 %0, %1, %2;" : "=r"(r) : "f"(hi), "f"(lo));
    return r;
}
__device__ __forceinline__ float gelu_exact(float x) {
    return 0.5f * x * (1.0f + erff(x * 0.70710678118654752f));
}
__device__ __forceinline__ void cp16(unsigned dst, const void* src) {
    asm volatile("cp.async.cg.shared.global [%0], [%1], 16;" :: "r"(dst), "l"(src));
}
#define CP_COMMIT() asm volatile("cp.async.commit_group;" ::: "memory")
#define CP_WAIT1()  asm volatile("cp.async.wait_group 1;" ::: "memory")
#define CP_WAIT0()  asm volatile("cp.async.wait_group 0;" ::: "memory")

#define LDSM4(r, addr) \
    asm volatile("ldmatrix.sync.aligned.m8n8.x4.shared.b16 {%0,%1,%2,%3}, [%4];" \
        : "=r"((r)[0]), "=r"((r)[1]), "=r"((r)[2]), "=r"((r)[3]) : "r"(addr))
#define LDSM4T(r, addr) \
    asm volatile("ldmatrix.sync.aligned.m8n8.x4.trans.shared.b16 {%0,%1,%2,%3}, [%4];" \
        : "=r"((r)[0]), "=r"((r)[1]), "=r"((r)[2]), "=r"((r)[3]) : "r"(addr))
#define MMA16816(d, a, b0, b1) \
    asm volatile("mma.sync.aligned.m16n8k16.row.col.f32.bf16.bf16.f32 " \
        "{%0,%1,%2,%3}, {%4,%5,%6,%7}, {%8,%9}, {%0,%1,%2,%3};" \
        : "+f"((d)[0]), "+f"((d)[1]), "+f"((d)[2]), "+f"((d)[3]) \
        : "r"((a)[0]), "r"((a)[1]), "r"((a)[2]), "r"((a)[3]), \
          "r"(b0), "r"(b1))

// ---------------- fp32 -> split planes converter ---------------------------
__global__ void __launch_bounds__(256)
conv_split(const float* __restrict__ src, u16* __restrict__ hi,
           u16* __restrict__ lo, int n4) {
    int i = blockIdx.x * 256 + threadIdx.x;
    if (i >= n4) return;
    float4 v = *(const float4*)(src + (size_t)i * 4);
    unsigned h01, l01, h23, l23;
    split2(v.x, v.y, h01, l01);
    split2(v.z, v.w, h23, l23);
    *(uint2*)(hi + (size_t)i * 4) = make_uint2(h01, h23);
    *(uint2*)(lo + (size_t)i * 4) = make_uint2(l01, l23);
}

// ====== pipelined HMMA bf16-split GEMM:  C[M,N] = epi( A @ W^T ) ============
// A, W given as pre-split bf16 planes. Block 128x64, BK=32, 8 warps, 2-stage
// cp.async double buffer. 3 accumulation passes (AhBh + AhBl + AlBh).
// OMODE: 0 = fp32 out, 1 = split-plane out, 2 = single-bf16 out.
#define PADW 40
#define GSTAGE_U16 15360        // Ah(5120) Al(5120) Bh(2560) Bl(2560)
#define G_SMEM_BYTES (2*GSTAGE_U16*2)

template<int OMODE, bool GELU, bool CAT>
__global__ void __launch_bounds__(256, 2)
gemm_bf16(const u16* __restrict__ Ah, const u16* __restrict__ Al,
          const u16* __restrict__ A2h, const u16* __restrict__ A2l,
          const u16* __restrict__ Wh, const u16* __restrict__ Wl,
          const float* __restrict__ bias, const float* __restrict__ res,
          float* __restrict__ Cf, u16* __restrict__ Chi, u16* __restrict__ Clo,
          int M, int N, int K, float alpha) {
    extern __shared__ __align__(16) u16 smu[];
    const unsigned sb = smem_u32(smu);
    const int tid = threadIdx.x;
    const int lane = tid & 31;
    const int wid = tid >> 5;
    const int wm = wid & 3;
    const int wn = wid >> 2;
    const int m0 = blockIdx.y * 128;
    const int n0 = blockIdx.x * 64;

    float acc[2][4][4];
    #pragma unroll
    for (int mt = 0; mt < 2; mt++)
        #pragma unroll
        for (int nt = 0; nt < 4; nt++)
            #pragma unroll
            for (int e = 0; e < 4; e++) acc[mt][nt][e] = 0.f;

    const int lr = lane & 7;
    const int arow = lr + ((lane >> 3) & 1) * 8;
    const int acol = (lane >> 4) * 8;
    const int brow = (lane >> 4) * 8 + lr;
    const int bcol = ((lane >> 3) & 1) * 8;

    auto issue = [&](int ch, int st) {
        const int k0 = ch * 32;
        const unsigned base = sb + st * (GSTAGE_U16 * 2);
        const u16 *pAh, *pAl;
        int astr, ac;
        if (CAT) {
            if (k0 < 512) { pAh = Ah;  pAl = Al;  ac = k0; }
            else          { pAh = A2h; pAl = A2l; ac = k0 - 512; }
            astr = 512;
        } else { pAh = Ah; pAl = Al; ac = k0; astr = K; }
        #pragma unroll
        for (int i = 0; i < 2; i++) {
            int u = tid + i * 256;
            int r = u >> 2, q = u & 3;
            unsigned d = base + (r * PADW + q * 8) * 2;
            size_t so = (size_t)(m0 + r) * astr + ac + q * 8;
            cp16(d, pAh + so);
            cp16(d + 10240, pAl + so);
        }
        {
            int r = tid >> 2, q = tid & 3;
            unsigned d = base + 20480 + (r * PADW + q * 8) * 2;
            size_t so = (size_t)(n0 + r) * K + k0 + q * 8;
            cp16(d, Wh + so);
            cp16(d + 5120, Wl + so);
        }
        CP_COMMIT();
    };

    const int chunks = K >> 5;
    issue(0, 0);
    for (int ch = 0; ch < chunks; ch++) {
        const int st = ch & 1;
        if (ch + 1 < chunks) { issue(ch + 1, st ^ 1); CP_WAIT1(); }
        else CP_WAIT0();
        __syncthreads();

        const unsigned aH = sb + st * (GSTAGE_U16 * 2);
        const unsigned aL = aH + 10240;
        const unsigned bH = aH + 20480;
        const unsigned bL = bH + 5120;

        #pragma unroll
        for (int ks = 0; ks < 2; ks++) {
            unsigned ah[2][4], al[2][4], bh[2][4], bl[2][4];
            #pragma unroll
            for (int mt = 0; mt < 2; mt++) {
                unsigned off =
                    (unsigned)((wm*32 + mt*16 + arow) * PADW + ks*16 + acol) * 2u;
                LDSM4(ah[mt], aH + off);
                LDSM4(al[mt], aL + off);
            }
            #pragma unroll
            for (int np = 0; np < 2; np++) {
                unsigned off =
                    (unsigned)((wn*32 + np*16 + brow) * PADW + ks*16 + bcol) * 2u;
                LDSM4(bh[np], bH + off);
                LDSM4(bl[np], bL + off);
            }
            #pragma unroll
            for (int mt = 0; mt < 2; mt++) {
                #pragma unroll
                for (int nt = 0; nt < 4; nt++) {
                    const int p = nt >> 1, o = (nt & 1) * 2;
                    MMA16816(acc[mt][nt], ah[mt], bh[p][o], bh[p][o+1]);
                    MMA16816(acc[mt][nt], ah[mt], bl[p][o], bl[p][o+1]);
                    MMA16816(acc[mt][nt], al[mt], bh[p][o], bh[p][o+1]);
                }
            }
        }
        __syncthreads();
    }

    // epilogue
    const int erow = lane >> 2;
    const int ecol = (lane & 3) * 2;
    #pragma unroll
    for (int mt = 0; mt < 2; mt++) {
        #pragma unroll
        for (int nt = 0; nt < 4; nt++) {
            int row = m0 + wm*32 + mt*16 + erow;
            int col = n0 + wn*32 + nt*8 + ecol;
            float2 bv = *(const float2*)(bias + col);
            #pragma unroll
            for (int half = 0; half < 2; half++) {
                int r = row + half * 8;
                float v0 = (acc[mt][nt][half*2 + 0] + bv.x) * alpha;
                float v1 = (acc[mt][nt][half*2 + 1] + bv.y) * alpha;
                if (GELU) { v0 = gelu_exact(v0); v1 = gelu_exact(v1); }
                if (res) {
                    float2 rv = *(const float2*)(res + (size_t)r * N + col);
                    v0 += rv.x; v1 += rv.y;
                }
                if (OMODE == 0) {
                    *(float2*)(Cf + (size_t)r * N + col) = make_float2(v0, v1);
                } else {
                    unsigned h2, l2;
                    split2(v0, v1, h2, l2);
                    *(unsigned*)(Chi + (size_t)r * N + col) = h2;
                    if (OMODE == 1)
                        *(unsigned*)(Clo + (size_t)r * N + col) = l2;
                }
            }
        }
    }
}

// ---------------- LayerNorm (512) -> split planes ---------------------------
__global__ void __launch_bounds__(128)
ln_split(const float* __restrict__ x, const float* __restrict__ g,
         const float* __restrict__ b, u16* __restrict__ oh,
         u16* __restrict__ ol) {
    __shared__ float red[4];
    const int row = blockIdx.x;
    const int t = threadIdx.x;
    const float* xr = x + (size_t)row * 512;
    float4 v = *(const float4*)(xr + t * 4);
    float s = v.x + v.y + v.z + v.w;
    #pragma unroll
    for (int off = 16; off; off >>= 1) s += __shfl_xor_sync(0xffffffffu, s, off);
    if ((t & 31) == 0) red[t >> 5] = s;
    __syncthreads();
    s = red[0] + red[1] + red[2] + red[3];
    const float mean = s * (1.f / 512.f);
    __syncthreads();
    float d0 = v.x - mean, d1 = v.y - mean, d2 = v.z - mean, d3 = v.w - mean;
    float ss = d0*d0 + d1*d1 + d2*d2 + d3*d3;
    #pragma unroll
    for (int off = 16; off; off >>= 1) ss += __shfl_xor_sync(0xffffffffu, ss, off);
    if ((t & 31) == 0) red[t >> 5] = ss;
    __syncthreads();
    ss = red[0] + red[1] + red[2] + red[3];
    const float rstd = rsqrtf(ss * (1.f / 512.f) + 1e-5f);
    float4 g4 = *(const float4*)(g + t * 4);
    float4 b4 = *(const float4*)(b + t * 4);
    float n0 = d0 * rstd * g4.x + b4.x;
    float n1 = d1 * rstd * g4.y + b4.y;
    float n2 = d2 * rstd * g4.z + b4.z;
    float n3 = d3 * rstd * g4.w + b4.w;
    size_t off = (size_t)row * 512 + t * 4;
    unsigned h2, l2;
    split2(n0, n1, h2, l2);
    *(unsigned*)(oh + off) = h2;  *(unsigned*)(ol + off) = l2;
    split2(n2, n3, h2, l2);
    *(unsigned*)(oh + off + 2) = h2;  *(unsigned*)(ol + off + 2) = l2;
}

// ---------------- encoder self-attention (flash, fp32 -> split planes) -----
#define ENC_SMEM_BYTES (4*64*65*4)
__global__ void __launch_bounds__(256)
enc_attn_kernel(const float* __restrict__ qkv, u16* __restrict__ ohi,
                u16* __restrict__ olo) {
    extern __shared__ float smemf[];
    float* Qs = smemf;
    float* Ks = Qs + 64*65;
    float* Vs = Ks + 64*65;
    float* Ps = Vs + 64*65;

    const int b  = blockIdx.y >> 3;
    const int h  = blockIdx.y & 7;
    const int q0 = blockIdx.x * 64;
    const int tid = threadIdx.x;
    const int tx = tid & 15, ty = tid >> 4;
    const float scale = 0.125f;

    const float* qbase = qkv + (size_t)(b*512 + q0) * 1536 + h*64;
    for (int i = tid; i < 64*64; i += 256) {
        int r = i >> 6, c = i & 63;
        Qs[r*65 + c] = qbase[(size_t)r*1536 + c] * scale;
    }

    float m_i[4], l_i[4], acc[4][4];
    #pragma unroll
    for (int i = 0; i < 4; i++) {
        m_i[i] = -1e30f; l_i[i] = 0.f;
        #pragma unroll
        for (int j = 0; j < 4; j++) acc[i][j] = 0.f;
    }

    for (int kt = 0; kt < 8; kt++) {
        __syncthreads();
        const float* kbase = qkv + (size_t)(b*512 + kt*64) * 1536 + 512 + h*64;
        for (int i = tid; i < 64*64; i += 256) {
            int r = i >> 6, c = i & 63;
            Ks[r*65 + c] = kbase[(size_t)r*1536 + c];
            Vs[r*65 + c] = kbase[(size_t)r*1536 + 512 + c];
        }
        __syncthreads();

        float s[4][4];
        #pragma unroll
        for (int i = 0; i < 4; i++)
            #pragma unroll
            for (int j = 0; j < 4; j++) s[i][j] = 0.f;

        #pragma unroll 8
        for (int kk = 0; kk < 64; kk++) {
            float qv[4], kv_[4];
            #pragma unroll
            for (int i = 0; i < 4; i++) qv[i]  = Qs[(ty*4 + i)*65 + kk];
            #pragma unroll
            for (int j = 0; j < 4; j++) kv_[j] = Ks[(tx*4 + j)*65 + kk];
            #pragma unroll
            for (int i = 0; i < 4; i++)
                #pragma unroll
                for (int j = 0; j < 4; j++) s[i][j] += qv[i] * kv_[j];
        }

        #pragma unroll
        for (int i = 0; i < 4; i++) {
            float rm = s[i][0];
            #pragma unroll
            for (int j = 1; j < 4; j++) rm = fmaxf(rm, s[i][j]);
            #pragma unroll
            for (int off = 8; off; off >>= 1)
                rm = fmaxf(rm, __shfl_xor_sync(0xffffffffu, rm, off));
            float mn = fmaxf(m_i[i], rm);
            float corr = __expf(m_i[i] - mn);
            float rs = 0.f;
            #pragma unroll
            for (int j = 0; j < 4; j++) {
                float p = __expf(s[i][j] - mn);
                s[i][j] = p; rs += p;
            }
            #pragma unroll
            for (int off = 8; off; off >>= 1)
                rs += __shfl_xor_sync(0xffffffffu, rs, off);
            l_i[i] = l_i[i] * corr + rs;
            m_i[i] = mn;
            #pragma unroll
            for (int j = 0; j < 4; j++) acc[i][j] *= corr;
            #pragma unroll
            for (int j = 0; j < 4; j++) Ps[(ty*4 + i)*65 + tx*4 + j] = s[i][j];
        }
        __syncthreads();

        #pragma unroll 8
        for (int kk = 0; kk < 64; kk++) {
            float pv[4], vv[4];
            #pragma unroll
            for (int i = 0; i < 4; i++) pv[i] = Ps[(ty*4 + i)*65 + kk];
            #pragma unroll
            for (int j = 0; j < 4; j++) vv[j] = Vs[kk*65 + tx*4 + j];
            #pragma unroll
            for (int i = 0; i < 4; i++)
                #pragma unroll
                for (int j = 0; j < 4; j++) acc[i][j] += pv[i] * vv[j];
        }
    }

    #pragma unroll
    for (int i = 0; i < 4; i++) {
        float inv = 1.f / l_i[i];
        size_t off = (size_t)(b*512 + q0 + ty*4 + i)*512 + h*64 + tx*4;
        unsigned h2, l2;
        split2(acc[i][0]*inv, acc[i][1]*inv, h2, l2);
        *(unsigned*)(ohi + off) = h2;  *(unsigned*)(olo + off) = l2;
        split2(acc[i][2]*inv, acc[i][3]*inv, h2, l2);
        *(unsigned*)(ohi + off + 2) = h2;  *(unsigned*)(olo + off + 2) = l2;
    }
}

// ---------------- semantic-aware cross-attention (HMMA flash) ---------------
// BQ=128 (8 warps x 16 rows), BKV=64, dh=128. bf16 Q,K,V; fp32 prior in acc.
#define SA_QU   17408                   // Q: 128 x 136 u16
#define SA_KVST 8704                    // 64 x 136 u16 per K or V plane
#define SA_SMEM_BYTES ((SA_QU + 4*SA_KVST)*2)   // Q + 2 stages of (K,V)

__global__ void __launch_bounds__(256, 1)
sa_attn_mma(const u16* __restrict__ q, const u16* __restrict__ kv,
            const float* __restrict__ prior, u16* __restrict__ smh,
            u16* __restrict__ sml) {
    extern __shared__ __align__(16) u16 smu[];
    const unsigned sb = smem_u32(smu);
    const int tid = threadIdx.x;
    const int lane = tid & 31;
    const int wid = tid >> 5;
    const int b = blockIdx.y >> 2;
    const int h = blockIdx.y & 3;
    const int q0 = blockIdx.x * 128;

    // stage Q (whole CTA tile, once)
    {
        const u16* qb = q + (size_t)b*262144 + h*65536 + (size_t)q0*128;
        #pragma unroll
        for (int i = 0; i < 8; i++) {
            int u = tid + i * 256;
            int r = u >> 4, c = (u & 15) * 8;
            cp16(sb + (r*136 + c)*2, qb + (size_t)r*128 + c);
        }
        CP_COMMIT();
    }

    auto loadKV = [&](int kt, int st) {
        const u16* kb = kv + ((size_t)(b*4096 + kt*64))*1024 + h*128;
        unsigned kbase = sb + (SA_QU + st * 2 * SA_KVST) * 2;
        unsigned vbase = kbase + SA_KVST * 2;
        #pragma unroll
        for (int i = 0; i < 4; i++) {
            int u = tid + i * 256;
            int r = u >> 4, c = (u & 15) * 8;
            size_t so = (size_t)r * 1024 + c;
            cp16(kbase + (r*136 + c)*2, kb + so);
            cp16(vbase + (r*136 + c)*2, kb + so + 512);
        }
        CP_COMMIT();
    };

    loadKV(0, 0);

    float m0r = -1e30f, m1r = -1e30f, l0 = 0.f, l1 = 0.f;
    float acc[16][4];
    #pragma unroll
    for (int dn = 0; dn < 16; dn++)
        #pragma unroll
        for (int e = 0; e < 4; e++) acc[dn][e] = 0.f;

    const int r0 = lane >> 2;
    const int qrow_g = b*512 + q0 + wid*16;
    // ldmatrix source offsets
    const unsigned qoff =
        (unsigned)((wid*16 + (lane & 15)) * 136 + (lane >> 4) * 8) * 2;
    const unsigned koff_row = (unsigned)((lane >> 4) * 8 + (lane & 7));
    const unsigned kcol = (unsigned)(((lane >> 3) & 1) * 8);
    const unsigned vrow = (unsigned)((lane & 7) + ((lane >> 4) << 3));

    for (int kt = 0; kt < 64; kt++) {
        const int st = kt & 1;
        if (kt + 1 < 64) { loadKV(kt + 1, st ^ 1); CP_WAIT1(); }
        else CP_WAIT0();
        __syncthreads();

        const unsigned Kb = sb + (SA_QU + st * 2 * SA_KVST) * 2;
        const unsigned Vb = Kb + SA_KVST * 2;

        // S = prior + Q K^T
        float s[8][4];
        {
            const float* pb = prior + (size_t)(qrow_g + r0) * 4096
                              + kt*64 + (lane & 3) * 2;
            const float* pb2 = pb + (size_t)8 * 4096;
            #pragma unroll
            for (int jn = 0; jn < 8; jn++) {
                float2 a = *(const float2*)(pb + jn * 8);
                float2 c = *(const float2*)(pb2 + jn * 8);
                s[jn][0] = a.x; s[jn][1] = a.y;
                s[jn][2] = c.x; s[jn][3] = c.y;
            }
        }
        #pragma unroll
        for (int kk = 0; kk < 8; kk++) {
            unsigned aq[4];
            LDSM4(aq, sb + qoff + kk * 32);
            #pragma unroll
            for (int jn2 = 0; jn2 < 4; jn2++) {
                unsigned bk[4];
                LDSM4(bk, Kb + ((jn2*16 + koff_row) * 136 + kk*16 + kcol) * 2);
                MMA16816(s[jn2*2],     aq, bk[0], bk[1]);
                MMA16816(s[jn2*2 + 1], aq, bk[2], bk[3]);
            }
        }

        // online softmax (2 rows per thread: r0 and r0+8)
        float mx0 = s[0][0], mx1 = s[0][2];
        #pragma unroll
        for (int jn = 0; jn < 8; jn++) {
            mx0 = fmaxf(mx0, fmaxf(s[jn][0], s[jn][1]));
            mx1 = fmaxf(mx1, fmaxf(s[jn][2], s[jn][3]));
        }
        mx0 = fmaxf(mx0, __shfl_xor_sync(0xffffffffu, mx0, 1));
        mx0 = fmaxf(mx0, __shfl_xor_sync(0xffffffffu, mx0, 2));
        mx1 = fmaxf(mx1, __shfl_xor_sync(0xffffffffu, mx1, 1));
        mx1 = fmaxf(mx1, __shfl_xor_sync(0xffffffffu, mx1, 2));
        float mn0 = fmaxf(m0r, mx0), mn1 = fmaxf(m1r, mx1);
        float c0 = __expf(m0r - mn0), c1 = __expf(m1r - mn1);
        float sum0 = 0.f, sum1 = 0.f;
        #pragma unroll
        for (int jn = 0; jn < 8; jn++) {
            s[jn][0] = __expf(s[jn][0] - mn0);
            s[jn][1] = __expf(s[jn][1] - mn0);
            s[jn][2] = __expf(s[jn][2] - mn1);
            s[jn][3] = __expf(s[jn][3] - mn1);
            sum0 += s[jn][0] + s[jn][1];
            sum1 += s[jn][2] + s[jn][3];
        }
        sum0 += __shfl_xor_sync(0xffffffffu, sum0, 1);
        sum0 += __shfl_xor_sync(0xffffffffu, sum0, 2);
        sum1 += __shfl_xor_sync(0xffffffffu, sum1, 1);
        sum1 += __shfl_xor_sync(0xffffffffu, sum1, 2);
        l0 = l0 * c0 + sum0;  l1 = l1 * c1 + sum1;
        m0r = mn0;  m1r = mn1;
        #pragma unroll
        for (int dn = 0; dn < 16; dn++) {
            acc[dn][0] *= c0; acc[dn][1] *= c0;
            acc[dn][2] *= c1; acc[dn][3] *= c1;
        }

        // P fragments from S accumulators
        unsigned ap[4][4];
        #pragma unroll
        for (int ks = 0; ks < 4; ks++) {
            ap[ks][0] = pkbf(s[2*ks][0],     s[2*ks][1]);
            ap[ks][1] = pkbf(s[2*ks][2],     s[2*ks][3]);
            ap[ks][2] = pkbf(s[2*ks + 1][0], s[2*ks + 1][1]);
            ap[ks][3] = pkbf(s[2*ks + 1][2], s[2*ks + 1][3]);
        }

        // O += P V
        #pragma unroll
        for (int ks = 0; ks < 4; ks++) {
            #pragma unroll
            for (int dn2 = 0; dn2 < 8; dn2++) {
                unsigned bv[4];
                LDSM4T(bv, Vb + ((ks*16 + vrow) * 136 + dn2*16 + kcol) * 2);
                MMA16816(acc[dn2*2],     ap[ks], bv[0], bv[2]);
                MMA16816(acc[dn2*2 + 1], ap[ks], bv[1], bv[3]);
            }
        }
        __syncthreads();
    }

    const float inv0 = 1.f / l0, inv1 = 1.f / l1;
    const size_t orow0 = (size_t)(qrow_g + r0) * 512 + h*128;
    const size_t orow1 = orow0 + (size_t)8 * 512;
    #pragma unroll
    for (int dn = 0; dn < 16; dn++) {
        int col = dn*8 + (lane & 3)*2;
        unsigned h2, l2;
        split2(acc[dn][0]*inv0, acc[dn][1]*inv0, h2, l2);
        *(unsigned*)(smh + orow0 + col) = h2;
        *(unsigned*)(sml + orow0 + col) = l2;
        split2(acc[dn][2]*inv1, acc[dn][3]*inv1, h2, l2);
        *(unsigned*)(smh + orow1 + col) = h2;
        *(unsigned*)(sml + orow1 + col) = l2;
    }
}

// ---------------- launch --------------------------------------------------
extern "C" void kernel_launch(void* const* d_in, const int* in_sizes, int n_in,
                              void* d_out, int out_size) {
    const float* motion      = (const float*)d_in[0];
    const float* scene_feats = (const float*)d_in[2];
    const float* prior       = (const float*)d_in[3];
    const float* ln1g = (const float*)d_in[4];
    const float* ln1b = (const float*)d_in[5];
    const float* qkvw = (const float*)d_in[6];
    const float* qkvb = (const float*)d_in[7];
    const float* outw = (const float*)d_in[8];
    const float* outb = (const float*)d_in[9];
    const float* ln2g = (const float*)d_in[10];
    const float* ln2b = (const float*)d_in[11];
    const float* ff1w = (const float*)d_in[12];
    const float* ff1b = (const float*)d_in[13];
    const float* ff2w = (const float*)d_in[14];
    const float* ff2b = (const float*)d_in[15];
    const float* saqw = (const float*)d_in[16];
    const float* saqb = (const float*)d_in[17];
    const float* sakvw = (const float*)d_in[18];
    const float* sakvb = (const float*)d_in[19];
    const float* saow = (const float*)d_in[20];
    const float* saob = (const float*)d_in[21];
    const float* fc1w = (const float*)d_in[22];
    const float* fc1b = (const float*)d_in[23];
    const float* fc2w = (const float*)d_in[24];
    const float* fc2b = (const float*)d_in[25];
    float* out = (float*)d_out;

    float *p_qkv, *p_x;
    u16 *p_whi, *p_wlo, *p_ahi, *p_alo, *p_b16;
    cudaGetSymbolAddress((void**)&p_qkv, g_qkv);
    cudaGetSymbolAddress((void**)&p_x,   g_x);
    cudaGetSymbolAddress((void**)&p_whi, w_hi);
    cudaGetSymbolAddress((void**)&p_wlo, w_lo);
    cudaGetSymbolAddress((void**)&p_ahi, a_hi);
    cudaGetSymbolAddress((void**)&p_alo, a_lo);
    cudaGetSymbolAddress((void**)&p_b16, a_b16);

    cudaFuncSetAttribute(gemm_bf16<0, false, false>,
        cudaFuncAttributeMaxDynamicSharedMemorySize, G_SMEM_BYTES);
    cudaFuncSetAttribute(gemm_bf16<1, false, false>,
        cudaFuncAttributeMaxDynamicSharedMemorySize, G_SMEM_BYTES);
    cudaFuncSetAttribute(gemm_bf16<1, true, false>,
        cudaFuncAttributeMaxDynamicSharedMemorySize, G_SMEM_BYTES);
    cudaFuncSetAttribute(gemm_bf16<2, false, false>,
        cudaFuncAttributeMaxDynamicSharedMemorySize, G_SMEM_BYTES);
    cudaFuncSetAttribute(gemm_bf16<1, true, true>,
        cudaFuncAttributeMaxDynamicSharedMemorySize, G_SMEM_BYTES);
    cudaFuncSetAttribute(enc_attn_kernel,
        cudaFuncAttributeMaxDynamicSharedMemorySize, ENC_SMEM_BYTES);
    cudaFuncSetAttribute(sa_attn_mma,
        cudaFuncAttributeMaxDynamicSharedMemorySize, SA_SMEM_BYTES);

    const float sa_scale = 0.044194173824159216f;  // 512^-0.5

    // ---- weight + scene_feats split conversion ----
    #define CONV(src, off, n) \
        conv_split<<<((n)/4 + 255)/256, 256>>>(src, p_whi + (off), p_wlo + (off), (n)/4)
    CONV(qkvw, WO_QKV, 1536*512);
    CONV(outw, WO_OUT, 512*512);
    CONV(ff1w, WO_FF1, 512*512);
    CONV(ff2w, WO_FF2, 512*512);
    CONV(saqw, WO_SAQ, 512*512);
    CONV(sakvw, WO_SAKV, 1024*512);
    CONV(saow, WO_SAOUT, 512*512);
    CONV(fc1w, WO_FC1, 2048*1024);
    CONV(fc2w, WO_FC2, 512*2048);
    #undef CONV
    conv_split<<<(KVROWS*512/4 + 255)/256, 256>>>(
        scene_feats, p_ahi + AO_SF, p_alo + AO_SF, KVROWS*512/4);

    // ---- motion encoder: pre-norm MHA + residual ----
    ln_split<<<ROWS, 128>>>(motion, ln1g, ln1b, p_ahi + AO_H, p_alo + AO_H);
    gemm_bf16<0, false, false><<<dim3(1536/64, ROWS/128), 256, G_SMEM_BYTES>>>(
        p_ahi + AO_H, p_alo + AO_H, nullptr, nullptr,
        p_whi + WO_QKV, p_wlo + WO_QKV, qkvb, nullptr,
        p_qkv, nullptr, nullptr, ROWS, 1536, 512, 1.f);
    enc_attn_kernel<<<dim3(8, 64), 256, ENC_SMEM_BYTES>>>(
        p_qkv, p_ahi + AO_O, p_alo + AO_O);
    gemm_bf16<0, false, false><<<dim3(512/64, ROWS/128), 256, G_SMEM_BYTES>>>(
        p_ahi + AO_O, p_alo + AO_O, nullptr, nullptr,
        p_whi + WO_OUT, p_wlo + WO_OUT, outb, motion,
        p_x, nullptr, nullptr, ROWS, 512, 512, 1.f);

    // ---- pre-norm MLP + residual ----
    ln_split<<<ROWS, 128>>>(p_x, ln2g, ln2b, p_ahi + AO_H2, p_alo + AO_H2);
    gemm_bf16<1, true, false><<<dim3(512/64, ROWS/128), 256, G_SMEM_BYTES>>>(
        p_ahi + AO_H2, p_alo + AO_H2, nullptr, nullptr,
        p_whi + WO_FF1, p_wlo + WO_FF1, ff1b, nullptr,
        nullptr, p_ahi + AO_FF, p_alo + AO_FF, ROWS, 512, 512, 1.f);
    gemm_bf16<1, false, false><<<dim3(512/64, ROWS/128), 256, G_SMEM_BYTES>>>(
        p_ahi + AO_FF, p_alo + AO_FF, nullptr, nullptr,
        p_whi + WO_FF2, p_wlo + WO_FF2, ff2b, p_x,
        nullptr, p_ahi + AO_MSCA, p_alo + AO_MSCA, ROWS, 512, 512, 1.f);

    // ---- semantic-aware attention ----
    gemm_bf16<2, false, false><<<dim3(512/64, ROWS/128), 256, G_SMEM_BYTES>>>(
        p_ahi + AO_MSCA, p_alo + AO_MSCA, nullptr, nullptr,
        p_whi + WO_SAQ, p_wlo + WO_SAQ, saqb, nullptr,
        nullptr, p_b16 + BO_QSA, nullptr, ROWS, 512, 512, sa_scale);
    gemm_bf16<2, false, false><<<dim3(1024/64, KVROWS/128), 256, G_SMEM_BYTES>>>(
        p_ahi + AO_SF, p_alo + AO_SF, nullptr, nullptr,
        p_whi + WO_SAKV, p_wlo + WO_SAKV, sakvb, nullptr,
        nullptr, p_b16 + BO_KV, nullptr, KVROWS, 1024, 512, 1.f);
    sa_attn_mma<<<dim3(4, 32), 256, SA_SMEM_BYTES>>>(
        p_b16 + BO_QSA, p_b16 + BO_KV, prior,
        p_ahi + AO_SM, p_alo + AO_SM);
    gemm_bf16<1, false, false><<<dim3(512/64, ROWS/128), 256, G_SMEM_BYTES>>>(
        p_ahi + AO_SM, p_alo + AO_SM, nullptr, nullptr,
        p_whi + WO_SAOUT, p_wlo + WO_SAOUT, saob, nullptr,
        nullptr, p_ahi + AO_SMF, p_alo + AO_SMF, ROWS, 512, 512, 1.f);

    // ---- concat-free fc1 + fc2 ----
    gemm_bf16<1, true, true><<<dim3(2048/64, ROWS/128), 256, G_SMEM_BYTES>>>(
        p_ahi + AO_MSCA, p_alo + AO_MSCA, p_ahi + AO_SMF, p_alo + AO_SMF,
        p_whi + WO_FC1, p_wlo + WO_FC1, fc1b, nullptr,
        nullptr, p_ahi + AO_MH, p_alo + AO_MH, ROWS, 2048, 1024, 1.f);
    gemm_bf16<0, false, false><<<dim3(512/64, ROWS/128), 256, G_SMEM_BYTES>>>(
        p_ahi + AO_MH, p_alo + AO_MH, nullptr, nullptr,
        p_whi + WO_FC2, p_wlo + WO_FC2, fc2b, nullptr,
        out, nullptr, nullptr, ROWS, 512, 2048, 1.f);
}

// round 6
// speedup vs baseline: 3.4913x; 1.2742x over previous
#include <cuda_runtime.h>
#include <cuda_bf16.h>
#include <math.h>

typedef unsigned short u16;

// ---------------- problem constants ----------------
#define BSZ   8
#define SEQL  512
#define NSC   4096
#define FD    512
#define ROWS  (BSZ*SEQL)        // 4096
#define KVROWS (BSZ*NSC)        // 32768

// ---------------- scratch (device globals; no allocation allowed) ----------
__device__ float g_x[ROWS*FD];

// split bf16 plane bundles (hi/lo)
#define WO_QKV   0
#define WO_OUT   786432
#define WO_FF1   1048576
#define WO_FF2   1310720
#define WO_SAQ   1572864
#define WO_SAKV  1835008
#define WO_SAOUT 2359296
#define WO_FC1   2621440
#define WO_FC2   4718592
__device__ u16 w_hi[5767168];
__device__ u16 w_lo[5767168];

#define AO_H    0
#define AO_O    2097152
#define AO_H2   4194304
#define AO_FF   6291456
#define AO_MSCA 8388608
#define AO_SM   10485760
#define AO_SMF  12582912
#define AO_MH   14680064
#define AO_SF   23068672
__device__ u16 a_hi[39845888];
__device__ u16 a_lo[39845888];

// single-bf16 planes
#define BO_QSA 0
#define BO_KV  2097152
#define BO_QKV 35651584           // ROWS*1536
__device__ u16 a_b16[41943040];

// ---------------- helpers ----------------
__device__ __forceinline__ unsigned smem_u32(const void* p) {
    unsigned r;
    asm("{ .reg .u64 t; cvta.to.shared.u64 t, %1; cvt.u32.u64 %0, t; }"
        : "=r"(r) : "l"(p));
    return r;
}
__device__ __forceinline__ void split2(float x0, float x1,
                                       unsigned& hi2, unsigned& lo2) {
    asm("cvt.rn.bf16x2.f32 %0, %1, %2;" : "=r"(hi2) : "f"(x1), "f"(x0));
    float h0 = __uint_as_float(hi2 << 16);
    float h1 = __uint_as_float(hi2 & 0xffff0000u);
    float l0 = x0 - h0;
    float l1 = x1 - h1;
    asm("cvt.rn.bf16x2.f32 %0, %1, %2;" : "=r"(lo2) : "f"(l1), "f"(l0));
}
__device__ __forceinline__ unsigned pkbf(float lo, float hi) {
    unsigned r;
    asm("cvt.rn.bf16x2.f32 %0, %1, %2;" : "=r"(r) : "f"(hi), "f"(lo));
    return r;
}
__device__ __forceinline__ float gelu_exact(float x) {
    return 0.5f * x * (1.0f + erff(x * 0.70710678118654752f));
}
__device__ __forceinline__ void cp16(unsigned dst, const void* src) {
    asm volatile("cp.async.cg.shared.global [%0], [%1], 16;" :: "r"(dst), "l"(src));
}
#define CP_COMMIT() asm volatile("cp.async.commit_group;" ::: "memory")
#define CP_WAIT1()  asm volatile("cp.async.wait_group 1;" ::: "memory")
#define CP_WAIT0()  asm volatile("cp.async.wait_group 0;" ::: "memory")

#define LDSM4(r, addr) \
    asm volatile("ldmatrix.sync.aligned.m8n8.x4.shared.b16 {%0,%1,%2,%3}, [%4];" \
        : "=r"((r)[0]), "=r"((r)[1]), "=r"((r)[2]), "=r"((r)[3]) : "r"(addr))
#define LDSM4T(r, addr) \
    asm volatile("ldmatrix.sync.aligned.m8n8.x4.trans.shared.b16 {%0,%1,%2,%3}, [%4];" \
        : "=r"((r)[0]), "=r"((r)[1]), "=r"((r)[2]), "=r"((r)[3]) : "r"(addr))
#define MMA16816(d, a, b0, b1) \
    asm volatile("mma.sync.aligned.m16n8k16.row.col.f32.bf16.bf16.f32 " \
        "{%0,%1,%2,%3}, {%4,%5,%6,%7}, {%8,%9}, {%0,%1,%2,%3};" \
        : "+f"((d)[0]), "+f"((d)[1]), "+f"((d)[2]), "+f"((d)[3]) \
        : "r"((a)[0]), "r"((a)[1]), "r"((a)[2]), "r"((a)[3]), \
          "r"(b0), "r"(b1))

// ---------------- merged fp32 -> split planes converter --------------------
struct ConvSeg { const float* src; u16* hi; u16* lo; int n4; int blk0; };
struct ConvTab { ConvSeg s[10]; };

__global__ void __launch_bounds__(256)
conv_multi(ConvTab t, int nseg) {
    const int blk = blockIdx.x;
    int si = 0;
    #pragma unroll
    for (int k = 1; k < 10; k++)
        if (k < nseg && blk >= t.s[k].blk0) si = k;
    const ConvSeg sg = t.s[si];
    int i = (blk - sg.blk0) * 256 + threadIdx.x;
    if (i >= sg.n4) return;
    float4 v = *(const float4*)(sg.src + (size_t)i * 4);
    unsigned h01, l01, h23, l23;
    split2(v.x, v.y, h01, l01);
    split2(v.z, v.w, h23, l23);
    *(uint2*)(sg.hi + (size_t)i * 4) = make_uint2(h01, h23);
    *(uint2*)(sg.lo + (size_t)i * 4) = make_uint2(l01, l23);
}

// ====== pipelined HMMA bf16-split GEMM:  C[M,N] = epi( A @ W^T ) ============
// PASSES=3: AhBh + AhBl + AlBh.  PASSES=2: AhBh + AhBl (A-lo never loaded).
// OMODE: 0 = fp32 out, 1 = split-plane out, 2 = single-bf16 out.
// alpha applies to cols < ncut (else 1).
#define PADW 40

template<int OMODE, bool GELU, bool CAT, int PASSES>
__global__ void __launch_bounds__(256, 2)
gemm_bf16(const u16* __restrict__ Ah, const u16* __restrict__ Al,
          const u16* __restrict__ A2h, const u16* __restrict__ A2l,
          const u16* __restrict__ Wh, const u16* __restrict__ Wl,
          const float* __restrict__ bias, const float* __restrict__ res,
          float* __restrict__ Cf, u16* __restrict__ Chi, u16* __restrict__ Clo,
          int M, int N, int K, float alpha, int ncut) {
    constexpr unsigned ALB  = 10240;                          // bytes
    constexpr unsigned BHB  = (PASSES == 3) ? 20480u : 10240u;
    constexpr unsigned BLB  = BHB + 5120u;
    constexpr unsigned STGB = BLB + 5120u;

    extern __shared__ __align__(16) u16 smu[];
    const unsigned sb = smem_u32(smu);
    const int tid = threadIdx.x;
    const int lane = tid & 31;
    const int wid = tid >> 5;
    const int wm = wid & 3;
    const int wn = wid >> 2;
    const int m0 = blockIdx.y * 128;
    const int n0 = blockIdx.x * 64;

    float acc[2][4][4];
    #pragma unroll
    for (int mt = 0; mt < 2; mt++)
        #pragma unroll
        for (int nt = 0; nt < 4; nt++)
            #pragma unroll
            for (int e = 0; e < 4; e++) acc[mt][nt][e] = 0.f;

    const int lr = lane & 7;
    const int arow = lr + ((lane >> 3) & 1) * 8;
    const int acol = (lane >> 4) * 8;
    const int brow = (lane >> 4) * 8 + lr;
    const int bcol = ((lane >> 3) & 1) * 8;

    auto issue = [&](int ch, int st) {
        const int k0 = ch * 32;
        const unsigned base = sb + st * STGB;
        const u16 *pAh, *pAl;
        int astr, ac;
        if (CAT) {
            if (k0 < 512) { pAh = Ah;  pAl = Al;  ac = k0; }
            else          { pAh = A2h; pAl = A2l; ac = k0 - 512; }
            astr = 512;
        } else { pAh = Ah; pAl = Al; ac = k0; astr = K; }
        #pragma unroll
        for (int i = 0; i < 2; i++) {
            int u = tid + i * 256;
            int r = u >> 2, q = u & 3;
            unsigned d = base + (r * PADW + q * 8) * 2;
            size_t so = (size_t)(m0 + r) * astr + ac + q * 8;
            cp16(d, pAh + so);
            if (PASSES == 3) cp16(d + ALB, pAl + so);
        }
        {
            int r = tid >> 2, q = tid & 3;
            unsigned d = base + BHB + (r * PADW + q * 8) * 2;
            size_t so = (size_t)(n0 + r) * K + k0 + q * 8;
            cp16(d, Wh + so);
            cp16(d + 5120, Wl + so);
        }
        CP_COMMIT();
    };

    const int chunks = K >> 5;
    issue(0, 0);
    for (int ch = 0; ch < chunks; ch++) {
        const int st = ch & 1;
        if (ch + 1 < chunks) { issue(ch + 1, st ^ 1); CP_WAIT1(); }
        else CP_WAIT0();
        __syncthreads();

        const unsigned aH = sb + st * STGB;
        const unsigned aL = aH + ALB;
        const unsigned bH = aH + BHB;
        const unsigned bL = bH + 5120;

        #pragma unroll
        for (int ks = 0; ks < 2; ks++) {
            unsigned ah[2][4], al[2][4], bh[2][4], bl[2][4];
            #pragma unroll
            for (int mt = 0; mt < 2; mt++) {
                unsigned off =
                    (unsigned)((wm*32 + mt*16 + arow) * PADW + ks*16 + acol) * 2u;
                LDSM4(ah[mt], aH + off);
                if (PASSES == 3) LDSM4(al[mt], aL + off);
            }
            #pragma unroll
            for (int np = 0; np < 2; np++) {
                unsigned off =
                    (unsigned)((wn*32 + np*16 + brow) * PADW + ks*16 + bcol) * 2u;
                LDSM4(bh[np], bH + off);
                LDSM4(bl[np], bL + off);
            }
            #pragma unroll
            for (int mt = 0; mt < 2; mt++) {
                #pragma unroll
                for (int nt = 0; nt < 4; nt++) {
                    const int p = nt >> 1, o = (nt & 1) * 2;
                    MMA16816(acc[mt][nt], ah[mt], bh[p][o], bh[p][o+1]);
                    MMA16816(acc[mt][nt], ah[mt], bl[p][o], bl[p][o+1]);
                    if (PASSES == 3)
                        MMA16816(acc[mt][nt], al[mt], bh[p][o], bh[p][o+1]);
                }
            }
        }
        __syncthreads();
    }

    // epilogue
    const int erow = lane >> 2;
    const int ecol = (lane & 3) * 2;
    #pragma unroll
    for (int mt = 0; mt < 2; mt++) {
        #pragma unroll
        for (int nt = 0; nt < 4; nt++) {
            int row = m0 + wm*32 + mt*16 + erow;
            int col = n0 + wn*32 + nt*8 + ecol;
            float aeff = (col < ncut) ? alpha : 1.f;
            float2 bv = *(const float2*)(bias + col);
            #pragma unroll
            for (int half = 0; half < 2; half++) {
                int r = row + half * 8;
                float v0 = (acc[mt][nt][half*2 + 0] + bv.x) * aeff;
                float v1 = (acc[mt][nt][half*2 + 1] + bv.y) * aeff;
                if (GELU) { v0 = gelu_exact(v0); v1 = gelu_exact(v1); }
                if (res) {
                    float2 rv = *(const float2*)(res + (size_t)r * N + col);
                    v0 += rv.x; v1 += rv.y;
                }
                if (OMODE == 0) {
                    *(float2*)(Cf + (size_t)r * N + col) = make_float2(v0, v1);
                } else if (OMODE == 1) {
                    unsigned h2, l2;
                    split2(v0, v1, h2, l2);
                    *(unsigned*)(Chi + (size_t)r * N + col) = h2;
                    *(unsigned*)(Clo + (size_t)r * N + col) = l2;
                } else {
                    *(unsigned*)(Chi + (size_t)r * N + col) = pkbf(v0, v1);
                }
            }
        }
    }
}

// ---------------- LayerNorm (512) -> split planes ---------------------------
__global__ void __launch_bounds__(128)
ln_split(const float* __restrict__ x, const float* __restrict__ g,
         const float* __restrict__ b, u16* __restrict__ oh,
         u16* __restrict__ ol) {
    __shared__ float red[4];
    const int row = blockIdx.x;
    const int t = threadIdx.x;
    const float* xr = x + (size_t)row * 512;
    float4 v = *(const float4*)(xr + t * 4);
    float s = v.x + v.y + v.z + v.w;
    #pragma unroll
    for (int off = 16; off; off >>= 1) s += __shfl_xor_sync(0xffffffffu, s, off);
    if ((t & 31) == 0) red[t >> 5] = s;
    __syncthreads();
    s = red[0] + red[1] + red[2] + red[3];
    const float mean = s * (1.f / 512.f);
    __syncthreads();
    float d0 = v.x - mean, d1 = v.y - mean, d2 = v.z - mean, d3 = v.w - mean;
    float ss = d0*d0 + d1*d1 + d2*d2 + d3*d3;
    #pragma unroll
    for (int off = 16; off; off >>= 1) ss += __shfl_xor_sync(0xffffffffu, ss, off);
    if ((t & 31) == 0) red[t >> 5] = ss;
    __syncthreads();
    ss = red[0] + red[1] + red[2] + red[3];
    const float rstd = rsqrtf(ss * (1.f / 512.f) + 1e-5f);
    float4 g4 = *(const float4*)(g + t * 4);
    float4 b4 = *(const float4*)(b + t * 4);
    float n0 = d0 * rstd * g4.x + b4.x;
    float n1 = d1 * rstd * g4.y + b4.y;
    float n2 = d2 * rstd * g4.z + b4.z;
    float n3 = d3 * rstd * g4.w + b4.w;
    size_t off = (size_t)row * 512 + t * 4;
    unsigned h2, l2;
    split2(n0, n1, h2, l2);
    *(unsigned*)(oh + off) = h2;  *(unsigned*)(ol + off) = l2;
    split2(n2, n3, h2, l2);
    *(unsigned*)(oh + off + 2) = h2;  *(unsigned*)(ol + off + 2) = l2;
}

// ---------------- encoder self-attention (HMMA flash, dh=64) ----------------
// BQ=128 (8 warps x 16 rows), BKV=64. q pre-scaled by 0.125 at qkv GEMM.
#define ENC_QU   (128*72)
#define ENC_KVST (64*72)
#define ENC_SMEM_BYTES ((ENC_QU + 4*ENC_KVST)*2)

__global__ void __launch_bounds__(256, 2)
enc_attn_mma(const u16* __restrict__ qkv, u16* __restrict__ ohi,
             u16* __restrict__ olo) {
    extern __shared__ __align__(16) u16 smu[];
    const unsigned sb = smem_u32(smu);
    const int tid = threadIdx.x;
    const int lane = tid & 31;
    const int wid = tid >> 5;
    const int b = blockIdx.y >> 3;
    const int h = blockIdx.y & 7;
    const int q0 = blockIdx.x * 128;

    {
        const u16* qb = qkv + (size_t)(b*512 + q0) * 1536 + h*64;
        #pragma unroll
        for (int i = 0; i < 4; i++) {
            int u = tid + i * 256;
            int r = u >> 3, c = (u & 7) * 8;
            cp16(sb + (r*72 + c)*2, qb + (size_t)r*1536 + c);
        }
        CP_COMMIT();
    }

    auto loadKV = [&](int kt, int st) {
        const u16* kb = qkv + (size_t)(b*512 + kt*64) * 1536 + 512 + h*64;
        unsigned kbase = sb + (ENC_QU + st * 2 * ENC_KVST) * 2;
        unsigned vbase = kbase + ENC_KVST * 2;
        #pragma unroll
        for (int i = 0; i < 2; i++) {
            int u = tid + i * 256;
            int r = u >> 3, c = (u & 7) * 8;
            size_t so = (size_t)r * 1536 + c;
            cp16(kbase + (r*72 + c)*2, kb + so);
            cp16(vbase + (r*72 + c)*2, kb + so + 512);
        }
        CP_COMMIT();
    };

    loadKV(0, 0);

    float m0r = -1e30f, m1r = -1e30f, l0 = 0.f, l1 = 0.f;
    float acc[8][4];
    #pragma unroll
    for (int dn = 0; dn < 8; dn++)
        #pragma unroll
        for (int e = 0; e < 4; e++) acc[dn][e] = 0.f;

    const int r0 = lane >> 2;
    const int qrow_g = b*512 + q0 + wid*16;
    const unsigned qoff =
        (unsigned)((wid*16 + (lane & 15)) * 72 + (lane >> 4) * 8) * 2;
    const unsigned koff_row = (unsigned)((lane >> 4) * 8 + (lane & 7));
    const unsigned kcol = (unsigned)(((lane >> 3) & 1) * 8);
    const unsigned vrow = (unsigned)((lane & 7) + ((lane >> 4) << 3));

    for (int kt = 0; kt < 8; kt++) {
        const int st = kt & 1;
        if (kt + 1 < 8) { loadKV(kt + 1, st ^ 1); CP_WAIT1(); }
        else CP_WAIT0();
        __syncthreads();

        const unsigned Kb = sb + (ENC_QU + st * 2 * ENC_KVST) * 2;
        const unsigned Vb = Kb + ENC_KVST * 2;

        float s[8][4];
        #pragma unroll
        for (int jn = 0; jn < 8; jn++)
            #pragma unroll
            for (int e = 0; e < 4; e++) s[jn][e] = 0.f;

        #pragma unroll
        for (int kk = 0; kk < 4; kk++) {
            unsigned aq[4];
            LDSM4(aq, sb + qoff + kk * 32);
            #pragma unroll
            for (int jn2 = 0; jn2 < 4; jn2++) {
                unsigned bk[4];
                LDSM4(bk, Kb + ((jn2*16 + koff_row) * 72 + kk*16 + kcol) * 2);
                MMA16816(s[jn2*2],     aq, bk[0], bk[1]);
                MMA16816(s[jn2*2 + 1], aq, bk[2], bk[3]);
            }
        }

        float mx0 = s[0][0], mx1 = s[0][2];
        #pragma unroll
        for (int jn = 0; jn < 8; jn++) {
            mx0 = fmaxf(mx0, fmaxf(s[jn][0], s[jn][1]));
            mx1 = fmaxf(mx1, fmaxf(s[jn][2], s[jn][3]));
        }
        mx0 = fmaxf(mx0, __shfl_xor_sync(0xffffffffu, mx0, 1));
        mx0 = fmaxf(mx0, __shfl_xor_sync(0xffffffffu, mx0, 2));
        mx1 = fmaxf(mx1, __shfl_xor_sync(0xffffffffu, mx1, 1));
        mx1 = fmaxf(mx1, __shfl_xor_sync(0xffffffffu, mx1, 2));
        float mn0 = fmaxf(m0r, mx0), mn1 = fmaxf(m1r, mx1);
        float c0 = __expf(m0r - mn0), c1 = __expf(m1r - mn1);
        float sum0 = 0.f, sum1 = 0.f;
        #pragma unroll
        for (int jn = 0; jn < 8; jn++) {
            s[jn][0] = __expf(s[jn][0] - mn0);
            s[jn][1] = __expf(s[jn][1] - mn0);
            s[jn][2] = __expf(s[jn][2] - mn1);
            s[jn][3] = __expf(s[jn][3] - mn1);
            sum0 += s[jn][0] + s[jn][1];
            sum1 += s[jn][2] + s[jn][3];
        }
        sum0 += __shfl_xor_sync(0xffffffffu, sum0, 1);
        sum0 += __shfl_xor_sync(0xffffffffu, sum0, 2);
        sum1 += __shfl_xor_sync(0xffffffffu, sum1, 1);
        sum1 += __shfl_xor_sync(0xffffffffu, sum1, 2);
        l0 = l0 * c0 + sum0;  l1 = l1 * c1 + sum1;
        m0r = mn0;  m1r = mn1;
        #pragma unroll
        for (int dn = 0; dn < 8; dn++) {
            acc[dn][0] *= c0; acc[dn][1] *= c0;
            acc[dn][2] *= c1; acc[dn][3] *= c1;
        }

        unsigned ap[4][4];
        #pragma unroll
        for (int ks = 0; ks < 4; ks++) {
            ap[ks][0] = pkbf(s[2*ks][0],     s[2*ks][1]);
            ap[ks][1] = pkbf(s[2*ks][2],     s[2*ks][3]);
            ap[ks][2] = pkbf(s[2*ks + 1][0], s[2*ks + 1][1]);
            ap[ks][3] = pkbf(s[2*ks + 1][2], s[2*ks + 1][3]);
        }

        #pragma unroll
        for (int ks = 0; ks < 4; ks++) {
            #pragma unroll
            for (int dn2 = 0; dn2 < 4; dn2++) {
                unsigned bv[4];
                LDSM4T(bv, Vb + ((ks*16 + vrow) * 72 + dn2*16 + kcol) * 2);
                MMA16816(acc[dn2*2],     ap[ks], bv[0], bv[2]);
                MMA16816(acc[dn2*2 + 1], ap[ks], bv[1], bv[3]);
            }
        }
        __syncthreads();
    }

    const float inv0 = 1.f / l0, inv1 = 1.f / l1;
    const size_t orow0 = (size_t)(qrow_g + r0) * 512 + h*64;
    const size_t orow1 = orow0 + (size_t)8 * 512;
    #pragma unroll
    for (int dn = 0; dn < 8; dn++) {
        int col = dn*8 + (lane & 3)*2;
        unsigned h2, l2;
        split2(acc[dn][0]*inv0, acc[dn][1]*inv0, h2, l2);
        *(unsigned*)(ohi + orow0 + col) = h2;
        *(unsigned*)(olo + orow0 + col) = l2;
        split2(acc[dn][2]*inv1, acc[dn][3]*inv1, h2, l2);
        *(unsigned*)(ohi + orow1 + col) = h2;
        *(unsigned*)(olo + orow1 + col) = l2;
    }
}

// ---------------- semantic-aware cross-attention (HMMA flash) ---------------
#define SA_QU   17408
#define SA_KVST 8704
#define SA_SMEM_BYTES ((SA_QU + 4*SA_KVST)*2)

__global__ void __launch_bounds__(256, 1)
sa_attn_mma(const u16* __restrict__ q, const u16* __restrict__ kv,
            const float* __restrict__ prior, u16* __restrict__ smh,
            u16* __restrict__ sml) {
    extern __shared__ __align__(16) u16 smu[];
    const unsigned sb = smem_u32(smu);
    const int tid = threadIdx.x;
    const int lane = tid & 31;
    const int wid = tid >> 5;
    const int b = blockIdx.y >> 2;
    const int h = blockIdx.y & 3;
    const int q0 = blockIdx.x * 128;

    {
        const u16* qb = q + (size_t)b*262144 + h*65536 + (size_t)q0*128;
        #pragma unroll
        for (int i = 0; i < 8; i++) {
            int u = tid + i * 256;
            int r = u >> 4, c = (u & 15) * 8;
            cp16(sb + (r*136 + c)*2, qb + (size_t)r*128 + c);
        }
        CP_COMMIT();
    }

    auto loadKV = [&](int kt, int st) {
        const u16* kb = kv + ((size_t)(b*4096 + kt*64))*1024 + h*128;
        unsigned kbase = sb + (SA_QU + st * 2 * SA_KVST) * 2;
        unsigned vbase = kbase + SA_KVST * 2;
        #pragma unroll
        for (int i = 0; i < 4; i++) {
            int u = tid + i * 256;
            int r = u >> 4, c = (u & 15) * 8;
            size_t so = (size_t)r * 1024 + c;
            cp16(kbase + (r*136 + c)*2, kb + so);
            cp16(vbase + (r*136 + c)*2, kb + so + 512);
        }
        CP_COMMIT();
    };

    loadKV(0, 0);

    float m0r = -1e30f, m1r = -1e30f, l0 = 0.f, l1 = 0.f;
    float acc[16][4];
    #pragma unroll
    for (int dn = 0; dn < 16; dn++)
        #pragma unroll
        for (int e = 0; e < 4; e++) acc[dn][e] = 0.f;

    const int r0 = lane >> 2;
    const int qrow_g = b*512 + q0 + wid*16;
    const unsigned qoff =
        (unsigned)((wid*16 + (lane & 15)) * 136 + (lane >> 4) * 8) * 2;
    const unsigned koff_row = (unsigned)((lane >> 4) * 8 + (lane & 7));
    const unsigned kcol = (unsigned)(((lane >> 3) & 1) * 8);
    const unsigned vrow = (unsigned)((lane & 7) + ((lane >> 4) << 3));

    for (int kt = 0; kt < 64; kt++) {
        const int st = kt & 1;
        if (kt + 1 < 64) { loadKV(kt + 1, st ^ 1); CP_WAIT1(); }
        else CP_WAIT0();
        __syncthreads();

        const unsigned Kb = sb + (SA_QU + st * 2 * SA_KVST) * 2;
        const unsigned Vb = Kb + SA_KVST * 2;

        float s[8][4];
        {
            const float* pb = prior + (size_t)(qrow_g + r0) * 4096
                              + kt*64 + (lane & 3) * 2;
            const float* pb2 = pb + (size_t)8 * 4096;
            #pragma unroll
            for (int jn = 0; jn < 8; jn++) {
                float2 a = *(const float2*)(pb + jn * 8);
                float2 c = *(const float2*)(pb2 + jn * 8);
                s[jn][0] = a.x; s[jn][1] = a.y;
                s[jn][2] = c.x; s[jn][3] = c.y;
            }
        }
        #pragma unroll
        for (int kk = 0; kk < 8; kk++) {
            unsigned aq[4];
            LDSM4(aq, sb + qoff + kk * 32);
            #pragma unroll
            for (int jn2 = 0; jn2 < 4; jn2++) {
                unsigned bk[4];
                LDSM4(bk, Kb + ((jn2*16 + koff_row) * 136 + kk*16 + kcol) * 2);
                MMA16816(s[jn2*2],     aq, bk[0], bk[1]);
                MMA16816(s[jn2*2 + 1], aq, bk[2], bk[3]);
            }
        }

        float mx0 = s[0][0], mx1 = s[0][2];
        #pragma unroll
        for (int jn = 0; jn < 8; jn++) {
            mx0 = fmaxf(mx0, fmaxf(s[jn][0], s[jn][1]));
            mx1 = fmaxf(mx1, fmaxf(s[jn][2], s[jn][3]));
        }
        mx0 = fmaxf(mx0, __shfl_xor_sync(0xffffffffu, mx0, 1));
        mx0 = fmaxf(mx0, __shfl_xor_sync(0xffffffffu, mx0, 2));
        mx1 = fmaxf(mx1, __shfl_xor_sync(0xffffffffu, mx1, 1));
        mx1 = fmaxf(mx1, __shfl_xor_sync(0xffffffffu, mx1, 2));
        float mn0 = fmaxf(m0r, mx0), mn1 = fmaxf(m1r, mx1);
        float c0 = __expf(m0r - mn0), c1 = __expf(m1r - mn1);
        float sum0 = 0.f, sum1 = 0.f;
        #pragma unroll
        for (int jn = 0; jn < 8; jn++) {
            s[jn][0] = __expf(s[jn][0] - mn0);
            s[jn][1] = __expf(s[jn][1] - mn0);
            s[jn][2] = __expf(s[jn][2] - mn1);
            s[jn][3] = __expf(s[jn][3] - mn1);
            sum0 += s[jn][0] + s[jn][1];
            sum1 += s[jn][2] + s[jn][3];
        }
        sum0 += __shfl_xor_sync(0xffffffffu, sum0, 1);
        sum0 += __shfl_xor_sync(0xffffffffu, sum0, 2);
        sum1 += __shfl_xor_sync(0xffffffffu, sum1, 1);
        sum1 += __shfl_xor_sync(0xffffffffu, sum1, 2);
        l0 = l0 * c0 + sum0;  l1 = l1 * c1 + sum1;
        m0r = mn0;  m1r = mn1;
        #pragma unroll
        for (int dn = 0; dn < 16; dn++) {
            acc[dn][0] *= c0; acc[dn][1] *= c0;
            acc[dn][2] *= c1; acc[dn][3] *= c1;
        }

        unsigned ap[4][4];
        #pragma unroll
        for (int ks = 0; ks < 4; ks++) {
            ap[ks][0] = pkbf(s[2*ks][0],     s[2*ks][1]);
            ap[ks][1] = pkbf(s[2*ks][2],     s[2*ks][3]);
            ap[ks][2] = pkbf(s[2*ks + 1][0], s[2*ks + 1][1]);
            ap[ks][3] = pkbf(s[2*ks + 1][2], s[2*ks + 1][3]);
        }

        #pragma unroll
        for (int ks = 0; ks < 4; ks++) {
            #pragma unroll
            for (int dn2 = 0; dn2 < 8; dn2++) {
                unsigned bv[4];
                LDSM4T(bv, Vb + ((ks*16 + vrow) * 136 + dn2*16 + kcol) * 2);
                MMA16816(acc[dn2*2],     ap[ks], bv[0], bv[2]);
                MMA16816(acc[dn2*2 + 1], ap[ks], bv[1], bv[3]);
            }
        }
        __syncthreads();
    }

    const float inv0 = 1.f / l0, inv1 = 1.f / l1;
    const size_t orow0 = (size_t)(qrow_g + r0) * 512 + h*128;
    const size_t orow1 = orow0 + (size_t)8 * 512;
    #pragma unroll
    for (int dn = 0; dn < 16; dn++) {
        int col = dn*8 + (lane & 3)*2;
        unsigned h2, l2;
        split2(acc[dn][0]*inv0, acc[dn][1]*inv0, h2, l2);
        *(unsigned*)(smh + orow0 + col) = h2;
        *(unsigned*)(sml + orow0 + col) = l2;
        split2(acc[dn][2]*inv1, acc[dn][3]*inv1, h2, l2);
        *(unsigned*)(smh + orow1 + col) = h2;
        *(unsigned*)(sml + orow1 + col) = l2;
    }
}

// ---------------- launch --------------------------------------------------
extern "C" void kernel_launch(void* const* d_in, const int* in_sizes, int n_in,
                              void* d_out, int out_size) {
    const float* motion      = (const float*)d_in[0];
    const float* scene_feats = (const float*)d_in[2];
    const float* prior       = (const float*)d_in[3];
    const float* ln1g = (const float*)d_in[4];
    const float* ln1b = (const float*)d_in[5];
    const float* qkvw = (const float*)d_in[6];
    const float* qkvb = (const float*)d_in[7];
    const float* outw = (const float*)d_in[8];
    const float* outb = (const float*)d_in[9];
    const float* ln2g = (const float*)d_in[10];
    const float* ln2b = (const float*)d_in[11];
    const float* ff1w = (const float*)d_in[12];
    const float* ff1b = (const float*)d_in[13];
    const float* ff2w = (const float*)d_in[14];
    const float* ff2b = (const float*)d_in[15];
    const float* saqw = (const float*)d_in[16];
    const float* saqb = (const float*)d_in[17];
    const float* sakvw = (const float*)d_in[18];
    const float* sakvb = (const float*)d_in[19];
    const float* saow = (const float*)d_in[20];
    const float* saob = (const float*)d_in[21];
    const float* fc1w = (const float*)d_in[22];
    const float* fc1b = (const float*)d_in[23];
    const float* fc2w = (const float*)d_in[24];
    const float* fc2b = (const float*)d_in[25];
    float* out = (float*)d_out;

    float* p_x;
    u16 *p_whi, *p_wlo, *p_ahi, *p_alo, *p_b16;
    cudaGetSymbolAddress((void**)&p_x,   g_x);
    cudaGetSymbolAddress((void**)&p_whi, w_hi);
    cudaGetSymbolAddress((void**)&p_wlo, w_lo);
    cudaGetSymbolAddress((void**)&p_ahi, a_hi);
    cudaGetSymbolAddress((void**)&p_alo, a_lo);
    cudaGetSymbolAddress((void**)&p_b16, a_b16);

    const int G_SMEM3 = 61440, G_SMEM2 = 40960;
    cudaFuncSetAttribute(gemm_bf16<0, false, false, 3>,
        cudaFuncAttributeMaxDynamicSharedMemorySize, G_SMEM3);
    cudaFuncSetAttribute(gemm_bf16<1, false, false, 3>,
        cudaFuncAttributeMaxDynamicSharedMemorySize, G_SMEM3);
    cudaFuncSetAttribute(gemm_bf16<1, true, false, 3>,
        cudaFuncAttributeMaxDynamicSharedMemorySize, G_SMEM3);
    cudaFuncSetAttribute(gemm_bf16<1, true, true, 3>,
        cudaFuncAttributeMaxDynamicSharedMemorySize, G_SMEM3);
    cudaFuncSetAttribute(gemm_bf16<2, false, false, 2>,
        cudaFuncAttributeMaxDynamicSharedMemorySize, G_SMEM2);
    cudaFuncSetAttribute(enc_attn_mma,
        cudaFuncAttributeMaxDynamicSharedMemorySize, ENC_SMEM_BYTES);
    cudaFuncSetAttribute(sa_attn_mma,
        cudaFuncAttributeMaxDynamicSharedMemorySize, SA_SMEM_BYTES);

    const float sa_scale = 0.044194173824159216f;  // 512^-0.5

    // ---- merged weight + scene_feats split conversion ----
    {
        ConvTab t;
        int blk = 0, i = 0;
        auto add = [&](const float* src, u16* hi, u16* lo, int n) {
            t.s[i] = ConvSeg{src, hi, lo, n / 4, blk};
            blk += (n / 4 + 255) / 256;
            i++;
        };
        add(qkvw,  p_whi + WO_QKV,   p_wlo + WO_QKV,   1536*512);
        add(outw,  p_whi + WO_OUT,   p_wlo + WO_OUT,   512*512);
        add(ff1w,  p_whi + WO_FF1,   p_wlo + WO_FF1,   512*512);
        add(ff2w,  p_whi + WO_FF2,   p_wlo + WO_FF2,   512*512);
        add(saqw,  p_whi + WO_SAQ,   p_wlo + WO_SAQ,   512*512);
        add(sakvw, p_whi + WO_SAKV,  p_wlo + WO_SAKV,  1024*512);
        add(saow,  p_whi + WO_SAOUT, p_wlo + WO_SAOUT, 512*512);
        add(fc1w,  p_whi + WO_FC1,   p_wlo + WO_FC1,   2048*1024);
        add(fc2w,  p_whi + WO_FC2,   p_wlo + WO_FC2,   512*2048);
        add(scene_feats, p_ahi + AO_SF, p_alo + AO_SF, KVROWS*512);
        conv_multi<<<blk, 256>>>(t, i);
    }

    // ---- motion encoder: pre-norm MHA + residual ----
    ln_split<<<ROWS, 128>>>(motion, ln1g, ln1b, p_ahi + AO_H, p_alo + AO_H);
    gemm_bf16<2, false, false, 2><<<dim3(1536/64, ROWS/128), 256, G_SMEM2>>>(
        p_ahi + AO_H, p_alo + AO_H, nullptr, nullptr,
        p_whi + WO_QKV, p_wlo + WO_QKV, qkvb, nullptr,
        nullptr, p_b16 + BO_QKV, nullptr, ROWS, 1536, 512, 0.125f, 512);
    enc_attn_mma<<<dim3(4, 64), 256, ENC_SMEM_BYTES>>>(
        p_b16 + BO_QKV, p_ahi + AO_O, p_alo + AO_O);
    gemm_bf16<0, false, false, 3><<<dim3(512/64, ROWS/128), 256, G_SMEM3>>>(
        p_ahi + AO_O, p_alo + AO_O, nullptr, nullptr,
        p_whi + WO_OUT, p_wlo + WO_OUT, outb, motion,
        p_x, nullptr, nullptr, ROWS, 512, 512, 1.f, 512);

    // ---- pre-norm MLP + residual ----
    ln_split<<<ROWS, 128>>>(p_x, ln2g, ln2b, p_ahi + AO_H2, p_alo + AO_H2);
    gemm_bf16<1, true, false, 3><<<dim3(512/64, ROWS/128), 256, G_SMEM3>>>(
        p_ahi + AO_H2, p_alo + AO_H2, nullptr, nullptr,
        p_whi + WO_FF1, p_wlo + WO_FF1, ff1b, nullptr,
        nullptr, p_ahi + AO_FF, p_alo + AO_FF, ROWS, 512, 512, 1.f, 512);
    gemm_bf16<1, false, false, 3><<<dim3(512/64, ROWS/128), 256, G_SMEM3>>>(
        p_ahi + AO_FF, p_alo + AO_FF, nullptr, nullptr,
        p_whi + WO_FF2, p_wlo + WO_FF2, ff2b, p_x,
        nullptr, p_ahi + AO_MSCA, p_alo + AO_MSCA, ROWS, 512, 512, 1.f, 512);

    // ---- semantic-aware attention ----
    gemm_bf16<2, false, false, 2><<<dim3(512/64, ROWS/128), 256, G_SMEM2>>>(
        p_ahi + AO_MSCA, p_alo + AO_MSCA, nullptr, nullptr,
        p_whi + WO_SAQ, p_wlo + WO_SAQ, saqb, nullptr,
        nullptr, p_b16 + BO_QSA, nullptr, ROWS, 512, 512, sa_scale, 512);
    gemm_bf16<2, false, false, 2><<<dim3(1024/64, KVROWS/128), 256, G_SMEM2>>>(
        p_ahi + AO_SF, p_alo + AO_SF, nullptr, nullptr,
        p_whi + WO_SAKV, p_wlo + WO_SAKV, sakvb, nullptr,
        nullptr, p_b16 + BO_KV, nullptr, KVROWS, 1024, 512, 1.f, 1024);
    sa_attn_mma<<<dim3(4, 32), 256, SA_SMEM_BYTES>>>(
        p_b16 + BO_QSA, p_b16 + BO_KV, prior,
        p_ahi + AO_SM, p_alo + AO_SM);
    gemm_bf16<1, false, false, 3><<<dim3(512/64, ROWS/128), 256, G_SMEM3>>>(
        p_ahi + AO_SM, p_alo + AO_SM, nullptr, nullptr,
        p_whi + WO_SAOUT, p_wlo + WO_SAOUT, saob, nullptr,
        nullptr, p_ahi + AO_SMF, p_alo + AO_SMF, ROWS, 512, 512, 1.f, 512);

    // ---- concat-free fc1 + fc2 ----
    gemm_bf16<1, true, true, 3><<<dim3(2048/64, ROWS/128), 256, G_SMEM3>>>(
        p_ahi + AO_MSCA, p_alo + AO_MSCA, p_ahi + AO_SMF, p_alo + AO_SMF,
        p_whi + WO_FC1, p_wlo + WO_FC1, fc1b, nullptr,
        nullptr, p_ahi + AO_MH, p_alo + AO_MH, ROWS, 2048, 1024, 1.f, 2048);
    gemm_bf16<0, false, false, 3><<<dim3(512/64, ROWS/128), 256, G_SMEM3>>>(
        p_ahi + AO_MH, p_alo + AO_MH, nullptr, nullptr,
        p_whi + WO_FC2, p_wlo + WO_FC2, fc2b, nullptr,
        out, nullptr, nullptr, ROWS, 512, 2048, 1.f, 512);
}

// round 7
// speedup vs baseline: 3.4996x; 1.0024x over previous
#include <cuda_runtime.h>
#include <cuda_bf16.h>
#include <math.h>

typedef unsigned short u16;

// ---------------- problem constants ----------------
#define BSZ   8
#define SEQL  512
#define NSC   4096
#define FD    512
#define ROWS  (BSZ*SEQL)        // 4096
#define KVROWS (BSZ*NSC)        // 32768

// ---------------- scratch (device globals; no allocation allowed) ----------
__device__ float g_x[ROWS*FD];

// split bf16 plane bundles (hi/lo)
#define WO_QKV   0
#define WO_OUT   786432
#define WO_FF1   1048576
#define WO_FF2   1310720
#define WO_SAQ   1572864
#define WO_SAKV  1835008
#define WO_SAOUT 2359296
#define WO_FC1   2621440
#define WO_FC2   4718592
__device__ u16 w_hi[5767168];
__device__ u16 w_lo[5767168];

#define AO_H    0
#define AO_O    2097152
#define AO_H2   4194304
#define AO_FF   6291456
#define AO_MSCA 8388608
#define AO_SM   10485760
#define AO_SMF  12582912
#define AO_MH   14680064
#define AO_SF   23068672
__device__ u16 a_hi[39845888];
__device__ u16 a_lo[39845888];

// single-bf16 planes
#define BO_QSA 0
#define BO_KV  2097152
#define BO_QKV 35651584           // ROWS*1536
__device__ u16 a_b16[41943040];

// ---------------- helpers ----------------
__device__ __forceinline__ unsigned smem_u32(const void* p) {
    unsigned r;
    asm("{ .reg .u64 t; cvta.to.shared.u64 t, %1; cvt.u32.u64 %0, t; }"
        : "=r"(r) : "l"(p));
    return r;
}
__device__ __forceinline__ void split2(float x0, float x1,
                                       unsigned& hi2, unsigned& lo2) {
    asm("cvt.rn.bf16x2.f32 %0, %1, %2;" : "=r"(hi2) : "f"(x1), "f"(x0));
    float h0 = __uint_as_float(hi2 << 16);
    float h1 = __uint_as_float(hi2 & 0xffff0000u);
    float l0 = x0 - h0;
    float l1 = x1 - h1;
    asm("cvt.rn.bf16x2.f32 %0, %1, %2;" : "=r"(lo2) : "f"(l1), "f"(l0));
}
__device__ __forceinline__ unsigned pkbf(float lo, float hi) {
    unsigned r;
    asm("cvt.rn.bf16x2.f32 %0, %1, %2;" : "=r"(r) : "f"(hi), "f"(lo));
    return r;
}
__device__ __forceinline__ float gelu_exact(float x) {
    return 0.5f * x * (1.0f + erff(x * 0.70710678118654752f));
}
__device__ __forceinline__ void cp16(unsigned dst, const void* src) {
    asm volatile("cp.async.cg.shared.global [%0], [%1], 16;" :: "r"(dst), "l"(src));
}
#define CP_COMMIT() asm volatile("cp.async.commit_group;" ::: "memory")
#define CP_WAIT2()  asm volatile("cp.async.wait_group 2;" ::: "memory")
#define CP_WAIT1()  asm volatile("cp.async.wait_group 1;" ::: "memory")
#define CP_WAIT0()  asm volatile("cp.async.wait_group 0;" ::: "memory")

#define LDSM4(r, addr) \
    asm volatile("ldmatrix.sync.aligned.m8n8.x4.shared.b16 {%0,%1,%2,%3}, [%4];" \
        : "=r"((r)[0]), "=r"((r)[1]), "=r"((r)[2]), "=r"((r)[3]) : "r"(addr))
#define LDSM4T(r, addr) \
    asm volatile("ldmatrix.sync.aligned.m8n8.x4.trans.shared.b16 {%0,%1,%2,%3}, [%4];" \
        : "=r"((r)[0]), "=r"((r)[1]), "=r"((r)[2]), "=r"((r)[3]) : "r"(addr))
#define MMA16816(d, a, b0, b1) \
    asm volatile("mma.sync.aligned.m16n8k16.row.col.f32.bf16.bf16.f32 " \
        "{%0,%1,%2,%3}, {%4,%5,%6,%7}, {%8,%9}, {%0,%1,%2,%3};" \
        : "+f"((d)[0]), "+f"((d)[1]), "+f"((d)[2]), "+f"((d)[3]) \
        : "r"((a)[0]), "r"((a)[1]), "r"((a)[2]), "r"((a)[3]), \
          "r"(b0), "r"(b1))

// ---------------- merged fp32 -> split planes converter --------------------
struct ConvSeg { const float* src; u16* hi; u16* lo; int n4; int blk0; };
struct ConvTab { ConvSeg s[10]; };

__global__ void __launch_bounds__(256)
conv_multi(ConvTab t, int nseg) {
    const int blk = blockIdx.x;
    int si = 0;
    #pragma unroll
    for (int k = 1; k < 10; k++)
        if (k < nseg && blk >= t.s[k].blk0) si = k;
    const ConvSeg sg = t.s[si];
    int i = (blk - sg.blk0) * 256 + threadIdx.x;
    if (i >= sg.n4) return;
    float4 v = *(const float4*)(sg.src + (size_t)i * 4);
    unsigned h01, l01, h23, l23;
    split2(v.x, v.y, h01, l01);
    split2(v.z, v.w, h23, l23);
    *(uint2*)(sg.hi + (size_t)i * 4) = make_uint2(h01, h23);
    if (sg.lo)
        *(uint2*)(sg.lo + (size_t)i * 4) = make_uint2(l01, l23);
}

// ====== pipelined HMMA bf16-split GEMM:  C[M,N] = epi( A @ W^T ) ============
// PASSES=3: AhBh + AhBl + AlBh.  PASSES=2: AhBh + AhBl (A-lo never loaded).
// 3-stage cp.async pipeline. OMODE: 0 fp32 out, 1 split-plane, 2 single-bf16.
// alpha applies to cols < ncut (else 1).
#define PADW 40

template<int OMODE, bool GELU, bool CAT, int PASSES>
__global__ void __launch_bounds__(256, 2)
gemm_bf16(const u16* __restrict__ Ah, const u16* __restrict__ Al,
          const u16* __restrict__ A2h, const u16* __restrict__ A2l,
          const u16* __restrict__ Wh, const u16* __restrict__ Wl,
          const float* __restrict__ bias, const float* __restrict__ res,
          float* __restrict__ Cf, u16* __restrict__ Chi, u16* __restrict__ Clo,
          int M, int N, int K, float alpha, int ncut) {
    constexpr unsigned ALB  = 10240;                          // bytes
    constexpr unsigned BHB  = (PASSES == 3) ? 20480u : 10240u;
    constexpr unsigned STGB = BHB + 10240u;

    extern __shared__ __align__(16) u16 smu[];
    const unsigned sb = smem_u32(smu);
    const int tid = threadIdx.x;
    const int lane = tid & 31;
    const int wid = tid >> 5;
    const int wm = wid & 3;
    const int wn = wid >> 2;
    const int m0 = blockIdx.y * 128;
    const int n0 = blockIdx.x * 64;

    float acc[2][4][4];
    #pragma unroll
    for (int mt = 0; mt < 2; mt++)
        #pragma unroll
        for (int nt = 0; nt < 4; nt++)
            #pragma unroll
            for (int e = 0; e < 4; e++) acc[mt][nt][e] = 0.f;

    const int lr = lane & 7;
    const int arow = lr + ((lane >> 3) & 1) * 8;
    const int acol = (lane >> 4) * 8;
    const int brow = (lane >> 4) * 8 + lr;
    const int bcol = ((lane >> 3) & 1) * 8;

    auto issue = [&](int ch, int st) {
        const int k0 = ch * 32;
        const unsigned base = sb + st * STGB;
        const u16 *pAh, *pAl;
        int astr, ac;
        if (CAT) {
            if (k0 < 512) { pAh = Ah;  pAl = Al;  ac = k0; }
            else          { pAh = A2h; pAl = A2l; ac = k0 - 512; }
            astr = 512;
        } else { pAh = Ah; pAl = Al; ac = k0; astr = K; }
        #pragma unroll
        for (int i = 0; i < 2; i++) {
            int u = tid + i * 256;
            int r = u >> 2, q = u & 3;
            unsigned d = base + (r * PADW + q * 8) * 2;
            size_t so = (size_t)(m0 + r) * astr + ac + q * 8;
            cp16(d, pAh + so);
            if (PASSES == 3) cp16(d + ALB, pAl + so);
        }
        {
            int r = tid >> 2, q = tid & 3;
            unsigned d = base + BHB + (r * PADW + q * 8) * 2;
            size_t so = (size_t)(n0 + r) * K + k0 + q * 8;
            cp16(d, Wh + so);
            cp16(d + 5120, Wl + so);
        }
        CP_COMMIT();
    };

    const int chunks = K >> 5;
    issue(0, 0);
    if (chunks > 1) issue(1, 1);
    for (int ch = 0; ch < chunks; ch++) {
        const int st = ch % 3;
        if (ch + 2 < chunks) { issue(ch + 2, (ch + 2) % 3); CP_WAIT2(); }
        else if (ch + 1 < chunks) CP_WAIT1();
        else CP_WAIT0();
        __syncthreads();

        const unsigned aH = sb + st * STGB;
        const unsigned aL = aH + ALB;
        const unsigned bH = aH + BHB;
        const unsigned bL = bH + 5120;

        #pragma unroll
        for (int ks = 0; ks < 2; ks++) {
            unsigned ah[2][4], al[2][4], bh[2][4], bl[2][4];
            #pragma unroll
            for (int mt = 0; mt < 2; mt++) {
                unsigned off =
                    (unsigned)((wm*32 + mt*16 + arow) * PADW + ks*16 + acol) * 2u;
                LDSM4(ah[mt], aH + off);
                if (PASSES == 3) LDSM4(al[mt], aL + off);
            }
            #pragma unroll
            for (int np = 0; np < 2; np++) {
                unsigned off =
                    (unsigned)((wn*32 + np*16 + brow) * PADW + ks*16 + bcol) * 2u;
                LDSM4(bh[np], bH + off);
                LDSM4(bl[np], bL + off);
            }
            #pragma unroll
            for (int mt = 0; mt < 2; mt++) {
                #pragma unroll
                for (int nt = 0; nt < 4; nt++) {
                    const int p = nt >> 1, o = (nt & 1) * 2;
                    MMA16816(acc[mt][nt], ah[mt], bh[p][o], bh[p][o+1]);
                    MMA16816(acc[mt][nt], ah[mt], bl[p][o], bl[p][o+1]);
                    if (PASSES == 3)
                        MMA16816(acc[mt][nt], al[mt], bh[p][o], bh[p][o+1]);
                }
            }
        }
        __syncthreads();
    }

    // epilogue
    const int erow = lane >> 2;
    const int ecol = (lane & 3) * 2;
    #pragma unroll
    for (int mt = 0; mt < 2; mt++) {
        #pragma unroll
        for (int nt = 0; nt < 4; nt++) {
            int row = m0 + wm*32 + mt*16 + erow;
            int col = n0 + wn*32 + nt*8 + ecol;
            float aeff = (col < ncut) ? alpha : 1.f;
            float2 bv = *(const float2*)(bias + col);
            #pragma unroll
            for (int half = 0; half < 2; half++) {
                int r = row + half * 8;
                float v0 = (acc[mt][nt][half*2 + 0] + bv.x) * aeff;
                float v1 = (acc[mt][nt][half*2 + 1] + bv.y) * aeff;
                if (GELU) { v0 = gelu_exact(v0); v1 = gelu_exact(v1); }
                if (res) {
                    float2 rv = *(const float2*)(res + (size_t)r * N + col);
                    v0 += rv.x; v1 += rv.y;
                }
                if (OMODE == 0) {
                    *(float2*)(Cf + (size_t)r * N + col) = make_float2(v0, v1);
                } else if (OMODE == 1) {
                    unsigned h2, l2;
                    split2(v0, v1, h2, l2);
                    *(unsigned*)(Chi + (size_t)r * N + col) = h2;
                    *(unsigned*)(Clo + (size_t)r * N + col) = l2;
                } else {
                    *(unsigned*)(Chi + (size_t)r * N + col) = pkbf(v0, v1);
                }
            }
        }
    }
}

// ---------------- LayerNorm (512) -> split planes (ol may be null) ----------
__global__ void __launch_bounds__(128)
ln_split(const float* __restrict__ x, const float* __restrict__ g,
         const float* __restrict__ b, u16* __restrict__ oh,
         u16* __restrict__ ol) {
    __shared__ float red[4];
    const int row = blockIdx.x;
    const int t = threadIdx.x;
    const float* xr = x + (size_t)row * 512;
    float4 v = *(const float4*)(xr + t * 4);
    float s = v.x + v.y + v.z + v.w;
    #pragma unroll
    for (int off = 16; off; off >>= 1) s += __shfl_xor_sync(0xffffffffu, s, off);
    if ((t & 31) == 0) red[t >> 5] = s;
    __syncthreads();
    s = red[0] + red[1] + red[2] + red[3];
    const float mean = s * (1.f / 512.f);
    __syncthreads();
    float d0 = v.x - mean, d1 = v.y - mean, d2 = v.z - mean, d3 = v.w - mean;
    float ss = d0*d0 + d1*d1 + d2*d2 + d3*d3;
    #pragma unroll
    for (int off = 16; off; off >>= 1) ss += __shfl_xor_sync(0xffffffffu, ss, off);
    if ((t & 31) == 0) red[t >> 5] = ss;
    __syncthreads();
    ss = red[0] + red[1] + red[2] + red[3];
    const float rstd = rsqrtf(ss * (1.f / 512.f) + 1e-5f);
    float4 g4 = *(const float4*)(g + t * 4);
    float4 b4 = *(const float4*)(b + t * 4);
    float n0 = d0 * rstd * g4.x + b4.x;
    float n1 = d1 * rstd * g4.y + b4.y;
    float n2 = d2 * rstd * g4.z + b4.z;
    float n3 = d3 * rstd * g4.w + b4.w;
    size_t off = (size_t)row * 512 + t * 4;
    if (ol) {
        unsigned h2, l2;
        split2(n0, n1, h2, l2);
        *(unsigned*)(oh + off) = h2;  *(unsigned*)(ol + off) = l2;
        split2(n2, n3, h2, l2);
        *(unsigned*)(oh + off + 2) = h2;  *(unsigned*)(ol + off + 2) = l2;
    } else {
        *(unsigned*)(oh + off)     = pkbf(n0, n1);
        *(unsigned*)(oh + off + 2) = pkbf(n2, n3);
    }
}

// ---------------- encoder self-attention (HMMA flash, dh=64) ----------------
// BQ=128 (8 warps x 16 rows), BKV=64. q pre-scaled by 0.125 at qkv GEMM.
#define ENC_QU   (128*72)
#define ENC_KVST (64*72)
#define ENC_SMEM_BYTES ((ENC_QU + 4*ENC_KVST)*2)

__global__ void __launch_bounds__(256, 2)
enc_attn_mma(const u16* __restrict__ qkv, u16* __restrict__ ohi,
             u16* __restrict__ olo) {
    extern __shared__ __align__(16) u16 smu[];
    const unsigned sb = smem_u32(smu);
    const int tid = threadIdx.x;
    const int lane = tid & 31;
    const int wid = tid >> 5;
    const int b = blockIdx.y >> 3;
    const int h = blockIdx.y & 7;
    const int q0 = blockIdx.x * 128;

    {
        const u16* qb = qkv + (size_t)(b*512 + q0) * 1536 + h*64;
        #pragma unroll
        for (int i = 0; i < 4; i++) {
            int u = tid + i * 256;
            int r = u >> 3, c = (u & 7) * 8;
            cp16(sb + (r*72 + c)*2, qb + (size_t)r*1536 + c);
        }
        CP_COMMIT();
    }

    auto loadKV = [&](int kt, int st) {
        const u16* kb = qkv + (size_t)(b*512 + kt*64) * 1536 + 512 + h*64;
        unsigned kbase = sb + (ENC_QU + st * 2 * ENC_KVST) * 2;
        unsigned vbase = kbase + ENC_KVST * 2;
        #pragma unroll
        for (int i = 0; i < 2; i++) {
            int u = tid + i * 256;
            int r = u >> 3, c = (u & 7) * 8;
            size_t so = (size_t)r * 1536 + c;
            cp16(kbase + (r*72 + c)*2, kb + so);
            cp16(vbase + (r*72 + c)*2, kb + so + 512);
        }
        CP_COMMIT();
    };

    loadKV(0, 0);

    float m0r = -1e30f, m1r = -1e30f, l0 = 0.f, l1 = 0.f;
    float acc[8][4];
    #pragma unroll
    for (int dn = 0; dn < 8; dn++)
        #pragma unroll
        for (int e = 0; e < 4; e++) acc[dn][e] = 0.f;

    const int r0 = lane >> 2;
    const int qrow_g = b*512 + q0 + wid*16;
    const unsigned qoff =
        (unsigned)((wid*16 + (lane & 15)) * 72 + (lane >> 4) * 8) * 2;
    const unsigned koff_row = (unsigned)((lane >> 4) * 8 + (lane & 7));
    const unsigned kcol = (unsigned)(((lane >> 3) & 1) * 8);
    const unsigned vrow = (unsigned)((lane & 7) + ((lane >> 4) << 3));

    for (int kt = 0; kt < 8; kt++) {
        const int st = kt & 1;
        if (kt + 1 < 8) { loadKV(kt + 1, st ^ 1); CP_WAIT1(); }
        else CP_WAIT0();
        __syncthreads();

        const unsigned Kb = sb + (ENC_QU + st * 2 * ENC_KVST) * 2;
        const unsigned Vb = Kb + ENC_KVST * 2;

        float s[8][4];
        #pragma unroll
        for (int jn = 0; jn < 8; jn++)
            #pragma unroll
            for (int e = 0; e < 4; e++) s[jn][e] = 0.f;

        #pragma unroll
        for (int kk = 0; kk < 4; kk++) {
            unsigned aq[4];
            LDSM4(aq, sb + qoff + kk * 32);
            #pragma unroll
            for (int jn2 = 0; jn2 < 4; jn2++) {
                unsigned bk[4];
                LDSM4(bk, Kb + ((jn2*16 + koff_row) * 72 + kk*16 + kcol) * 2);
                MMA16816(s[jn2*2],     aq, bk[0], bk[1]);
                MMA16816(s[jn2*2 + 1], aq, bk[2], bk[3]);
            }
        }

        float mx0 = s[0][0], mx1 = s[0][2];
        #pragma unroll
        for (int jn = 0; jn < 8; jn++) {
            mx0 = fmaxf(mx0, fmaxf(s[jn][0], s[jn][1]));
            mx1 = fmaxf(mx1, fmaxf(s[jn][2], s[jn][3]));
        }
        mx0 = fmaxf(mx0, __shfl_xor_sync(0xffffffffu, mx0, 1));
        mx0 = fmaxf(mx0, __shfl_xor_sync(0xffffffffu, mx0, 2));
        mx1 = fmaxf(mx1, __shfl_xor_sync(0xffffffffu, mx1, 1));
        mx1 = fmaxf(mx1, __shfl_xor_sync(0xffffffffu, mx1, 2));
        float mn0 = fmaxf(m0r, mx0), mn1 = fmaxf(m1r, mx1);
        float c0 = __expf(m0r - mn0), c1 = __expf(m1r - mn1);
        float sum0 = 0.f, sum1 = 0.f;
        #pragma unroll
        for (int jn = 0; jn < 8; jn++) {
            s[jn][0] = __expf(s[jn][0] - mn0);
            s[jn][1] = __expf(s[jn][1] - mn0);
            s[jn][2] = __expf(s[jn][2] - mn1);
            s[jn][3] = __expf(s[jn][3] - mn1);
            sum0 += s[jn][0] + s[jn][1];
            sum1 += s[jn][2] + s[jn][3];
        }
        sum0 += __shfl_xor_sync(0xffffffffu, sum0, 1);
        sum0 += __shfl_xor_sync(0xffffffffu, sum0, 2);
        sum1 += __shfl_xor_sync(0xffffffffu, sum1, 1);
        sum1 += __shfl_xor_sync(0xffffffffu, sum1, 2);
        l0 = l0 * c0 + sum0;  l1 = l1 * c1 + sum1;
        m0r = mn0;  m1r = mn1;
        #pragma unroll
        for (int dn = 0; dn < 8; dn++) {
            acc[dn][0] *= c0; acc[dn][1] *= c0;
            acc[dn][2] *= c1; acc[dn][3] *= c1;
        }

        unsigned ap[4][4];
        #pragma unroll
        for (int ks = 0; ks < 4; ks++) {
            ap[ks][0] = pkbf(s[2*ks][0],     s[2*ks][1]);
            ap[ks][1] = pkbf(s[2*ks][2],     s[2*ks][3]);
            ap[ks][2] = pkbf(s[2*ks + 1][0], s[2*ks + 1][1]);
            ap[ks][3] = pkbf(s[2*ks + 1][2], s[2*ks + 1][3]);
        }

        #pragma unroll
        for (int ks = 0; ks < 4; ks++) {
            #pragma unroll
            for (int dn2 = 0; dn2 < 4; dn2++) {
                unsigned bv[4];
                LDSM4T(bv, Vb + ((ks*16 + vrow) * 72 + dn2*16 + kcol) * 2);
                MMA16816(acc[dn2*2],     ap[ks], bv[0], bv[2]);
                MMA16816(acc[dn2*2 + 1], ap[ks], bv[1], bv[3]);
            }
        }
        __syncthreads();
    }

    const float inv0 = 1.f / l0, inv1 = 1.f / l1;
    const size_t orow0 = (size_t)(qrow_g + r0) * 512 + h*64;
    const size_t orow1 = orow0 + (size_t)8 * 512;
    #pragma unroll
    for (int dn = 0; dn < 8; dn++) {
        int col = dn*8 + (lane & 3)*2;
        unsigned h2, l2;
        split2(acc[dn][0]*inv0, acc[dn][1]*inv0, h2, l2);
        *(unsigned*)(ohi + orow0 + col) = h2;
        *(unsigned*)(olo + orow0 + col) = l2;
        split2(acc[dn][2]*inv1, acc[dn][3]*inv1, h2, l2);
        *(unsigned*)(ohi + orow1 + col) = h2;
        *(unsigned*)(olo + orow1 + col) = l2;
    }
}

// ---------------- semantic-aware cross-attention (HMMA flash) ---------------
// BQ=64 (4 warps x 16 rows), BKV=64, dh=128. 256 CTAs, 2 per SM.
#define SA_QU   (64*136)
#define SA_KVST (64*136)
#define SA_SMEM_BYTES ((SA_QU + 4*SA_KVST)*2)   // 87040

__global__ void __launch_bounds__(128, 2)
sa_attn_mma(const u16* __restrict__ q, const u16* __restrict__ kv,
            const float* __restrict__ prior, u16* __restrict__ smh,
            u16* __restrict__ sml) {
    extern __shared__ __align__(16) u16 smu[];
    const unsigned sb = smem_u32(smu);
    const int tid = threadIdx.x;
    const int lane = tid & 31;
    const int wid = tid >> 5;          // 0..3
    const int b = blockIdx.y >> 2;
    const int h = blockIdx.y & 3;
    const int q0 = blockIdx.x * 64;

    // stage Q (64 x 128)
    {
        const u16* qb = q + (size_t)b*262144 + h*65536 + (size_t)q0*128;
        #pragma unroll
        for (int i = 0; i < 8; i++) {
            int u = tid + i * 128;
            int r = u >> 4, c = (u & 15) * 8;
            cp16(sb + (r*136 + c)*2, qb + (size_t)r*128 + c);
        }
        CP_COMMIT();
    }

    auto loadKV = [&](int kt, int st) {
        const u16* kb = kv + ((size_t)(b*4096 + kt*64))*1024 + h*128;
        unsigned kbase = sb + (SA_QU + st * 2 * SA_KVST) * 2;
        unsigned vbase = kbase + SA_KVST * 2;
        #pragma unroll
        for (int i = 0; i < 8; i++) {
            int u = tid + i * 128;
            int r = u >> 4, c = (u & 15) * 8;
            size_t so = (size_t)r * 1024 + c;
            cp16(kbase + (r*136 + c)*2, kb + so);
            cp16(vbase + (r*136 + c)*2, kb + so + 512);
        }
        CP_COMMIT();
    };

    loadKV(0, 0);

    float m0r = -1e30f, m1r = -1e30f, l0 = 0.f, l1 = 0.f;
    float acc[16][4];
    #pragma unroll
    for (int dn = 0; dn < 16; dn++)
        #pragma unroll
        for (int e = 0; e < 4; e++) acc[dn][e] = 0.f;

    const int r0 = lane >> 2;
    const int qrow_g = b*512 + q0 + wid*16;
    const unsigned qoff =
        (unsigned)((wid*16 + (lane & 15)) * 136 + (lane >> 4) * 8) * 2;
    const unsigned koff_row = (unsigned)((lane >> 4) * 8 + (lane & 7));
    const unsigned kcol = (unsigned)(((lane >> 3) & 1) * 8);
    const unsigned vrow = (unsigned)((lane & 7) + ((lane >> 4) << 3));

    for (int kt = 0; kt < 64; kt++) {
        const int st = kt & 1;
        if (kt + 1 < 64) { loadKV(kt + 1, st ^ 1); CP_WAIT1(); }
        else CP_WAIT0();
        __syncthreads();

        const unsigned Kb = sb + (SA_QU + st * 2 * SA_KVST) * 2;
        const unsigned Vb = Kb + SA_KVST * 2;

        float s[8][4];
        {
            const float* pb = prior + (size_t)(qrow_g + r0) * 4096
                              + kt*64 + (lane & 3) * 2;
            const float* pb2 = pb + (size_t)8 * 4096;
            #pragma unroll
            for (int jn = 0; jn < 8; jn++) {
                float2 a = *(const float2*)(pb + jn * 8);
                float2 c = *(const float2*)(pb2 + jn * 8);
                s[jn][0] = a.x; s[jn][1] = a.y;
                s[jn][2] = c.x; s[jn][3] = c.y;
            }
        }
        #pragma unroll
        for (int kk = 0; kk < 8; kk++) {
            unsigned aq[4];
            LDSM4(aq, sb + qoff + kk * 32);
            #pragma unroll
            for (int jn2 = 0; jn2 < 4; jn2++) {
                unsigned bk[4];
                LDSM4(bk, Kb + ((jn2*16 + koff_row) * 136 + kk*16 + kcol) * 2);
                MMA16816(s[jn2*2],     aq, bk[0], bk[1]);
                MMA16816(s[jn2*2 + 1], aq, bk[2], bk[3]);
            }
        }

        float mx0 = s[0][0], mx1 = s[0][2];
        #pragma unroll
        for (int jn = 0; jn < 8; jn++) {
            mx0 = fmaxf(mx0, fmaxf(s[jn][0], s[jn][1]));
            mx1 = fmaxf(mx1, fmaxf(s[jn][2], s[jn][3]));
        }
        mx0 = fmaxf(mx0, __shfl_xor_sync(0xffffffffu, mx0, 1));
        mx0 = fmaxf(mx0, __shfl_xor_sync(0xffffffffu, mx0, 2));
        mx1 = fmaxf(mx1, __shfl_xor_sync(0xffffffffu, mx1, 1));
        mx1 = fmaxf(mx1, __shfl_xor_sync(0xffffffffu, mx1, 2));
        float mn0 = fmaxf(m0r, mx0), mn1 = fmaxf(m1r, mx1);
        float c0 = __expf(m0r - mn0), c1 = __expf(m1r - mn1);
        float sum0 = 0.f, sum1 = 0.f;
        #pragma unroll
        for (int jn = 0; jn < 8; jn++) {
            s[jn][0] = __expf(s[jn][0] - mn0);
            s[jn][1] = __expf(s[jn][1] - mn0);
            s[jn][2] = __expf(s[jn][2] - mn1);
            s[jn][3] = __expf(s[jn][3] - mn1);
            sum0 += s[jn][0] + s[jn][1];
            sum1 += s[jn][2] + s[jn][3];
        }
        sum0 += __shfl_xor_sync(0xffffffffu, sum0, 1);
        sum0 += __shfl_xor_sync(0xffffffffu, sum0, 2);
        sum1 += __shfl_xor_sync(0xffffffffu, sum1, 1);
        sum1 += __shfl_xor_sync(0xffffffffu, sum1, 2);
        l0 = l0 * c0 + sum0;  l1 = l1 * c1 + sum1;
        m0r = mn0;  m1r = mn1;
        #pragma unroll
        for (int dn = 0; dn < 16; dn++) {
            acc[dn][0] *= c0; acc[dn][1] *= c0;
            acc[dn][2] *= c1; acc[dn][3] *= c1;
        }

        unsigned ap[4][4];
        #pragma unroll
        for (int ks = 0; ks < 4; ks++) {
            ap[ks][0] = pkbf(s[2*ks][0],     s[2*ks][1]);
            ap[ks][1] = pkbf(s[2*ks][2],     s[2*ks][3]);
            ap[ks][2] = pkbf(s[2*ks + 1][0], s[2*ks + 1][1]);
            ap[ks][3] = pkbf(s[2*ks + 1][2], s[2*ks + 1][3]);
        }

        #pragma unroll
        for (int ks = 0; ks < 4; ks++) {
            #pragma unroll
            for (int dn2 = 0; dn2 < 8; dn2++) {
                unsigned bv[4];
                LDSM4T(bv, Vb + ((ks*16 + vrow) * 136 + dn2*16 + kcol) * 2);
                MMA16816(acc[dn2*2],     ap[ks], bv[0], bv[2]);
                MMA16816(acc[dn2*2 + 1], ap[ks], bv[1], bv[3]);
            }
        }
        __syncthreads();
    }

    const float inv0 = 1.f / l0, inv1 = 1.f / l1;
    const size_t orow0 = (size_t)(qrow_g + r0) * 512 + h*128;
    const size_t orow1 = orow0 + (size_t)8 * 512;
    #pragma unroll
    for (int dn = 0; dn < 16; dn++) {
        int col = dn*8 + (lane & 3)*2;
        unsigned h2, l2;
        split2(acc[dn][0]*inv0, acc[dn][1]*inv0, h2, l2);
        *(unsigned*)(smh + orow0 + col) = h2;
        *(unsigned*)(sml + orow0 + col) = l2;
        split2(acc[dn][2]*inv1, acc[dn][3]*inv1, h2, l2);
        *(unsigned*)(smh + orow1 + col) = h2;
        *(unsigned*)(sml + orow1 + col) = l2;
    }
}

// ---------------- launch --------------------------------------------------
extern "C" void kernel_launch(void* const* d_in, const int* in_sizes, int n_in,
                              void* d_out, int out_size) {
    const float* motion      = (const float*)d_in[0];
    const float* scene_feats = (const float*)d_in[2];
    const float* prior       = (const float*)d_in[3];
    const float* ln1g = (const float*)d_in[4];
    const float* ln1b = (const float*)d_in[5];
    const float* qkvw = (const float*)d_in[6];
    const float* qkvb = (const float*)d_in[7];
    const float* outw = (const float*)d_in[8];
    const float* outb = (const float*)d_in[9];
    const float* ln2g = (const float*)d_in[10];
    const float* ln2b = (const float*)d_in[11];
    const float* ff1w = (const float*)d_in[12];
    const float* ff1b = (const float*)d_in[13];
    const float* ff2w = (const float*)d_in[14];
    const float* ff2b = (const float*)d_in[15];
    const float* saqw = (const float*)d_in[16];
    const float* saqb = (const float*)d_in[17];
    const float* sakvw = (const float*)d_in[18];
    const float* sakvb = (const float*)d_in[19];
    const float* saow = (const float*)d_in[20];
    const float* saob = (const float*)d_in[21];
    const float* fc1w = (const float*)d_in[22];
    const float* fc1b = (const float*)d_in[23];
    const float* fc2w = (const float*)d_in[24];
    const float* fc2b = (const float*)d_in[25];
    float* out = (float*)d_out;

    float* p_x;
    u16 *p_whi, *p_wlo, *p_ahi, *p_alo, *p_b16;
    cudaGetSymbolAddress((void**)&p_x,   g_x);
    cudaGetSymbolAddress((void**)&p_whi, w_hi);
    cudaGetSymbolAddress((void**)&p_wlo, w_lo);
    cudaGetSymbolAddress((void**)&p_ahi, a_hi);
    cudaGetSymbolAddress((void**)&p_alo, a_lo);
    cudaGetSymbolAddress((void**)&p_b16, a_b16);

    const int G_SMEM3 = 92160, G_SMEM2 = 61440;
    cudaFuncSetAttribute(gemm_bf16<0, false, false, 3>,
        cudaFuncAttributeMaxDynamicSharedMemorySize, G_SMEM3);
    cudaFuncSetAttribute(gemm_bf16<1, false, false, 3>,
        cudaFuncAttributeMaxDynamicSharedMemorySize, G_SMEM3);
    cudaFuncSetAttribute(gemm_bf16<1, true, false, 3>,
        cudaFuncAttributeMaxDynamicSharedMemorySize, G_SMEM3);
    cudaFuncSetAttribute(gemm_bf16<1, true, true, 3>,
        cudaFuncAttributeMaxDynamicSharedMemorySize, G_SMEM3);
    cudaFuncSetAttribute(gemm_bf16<2, false, false, 2>,
        cudaFuncAttributeMaxDynamicSharedMemorySize, G_SMEM2);
    cudaFuncSetAttribute(enc_attn_mma,
        cudaFuncAttributeMaxDynamicSharedMemorySize, ENC_SMEM_BYTES);
    cudaFuncSetAttribute(sa_attn_mma,
        cudaFuncAttributeMaxDynamicSharedMemorySize, SA_SMEM_BYTES);

    const float sa_scale = 0.044194173824159216f;  // 512^-0.5

    // ---- merged weight + scene_feats split conversion ----
    {
        ConvTab t;
        int blk = 0, i = 0;
        auto add = [&](const float* src, u16* hi, u16* lo, int n) {
            t.s[i] = ConvSeg{src, hi, lo, n / 4, blk};
            blk += (n / 4 + 255) / 256;
            i++;
        };
        add(qkvw,  p_whi + WO_QKV,   p_wlo + WO_QKV,   1536*512);
        add(outw,  p_whi + WO_OUT,   p_wlo + WO_OUT,   512*512);
        add(ff1w,  p_whi + WO_FF1,   p_wlo + WO_FF1,   512*512);
        add(ff2w,  p_whi + WO_FF2,   p_wlo + WO_FF2,   512*512);
        add(saqw,  p_whi + WO_SAQ,   p_wlo + WO_SAQ,   512*512);
        add(sakvw, p_whi + WO_SAKV,  p_wlo + WO_SAKV,  1024*512);
        add(saow,  p_whi + WO_SAOUT, p_wlo + WO_SAOUT, 512*512);
        add(fc1w,  p_whi + WO_FC1,   p_wlo + WO_FC1,   2048*1024);
        add(fc2w,  p_whi + WO_FC2,   p_wlo + WO_FC2,   512*2048);
        add(scene_feats, p_ahi + AO_SF, nullptr, KVROWS*512);   // lo unused (2-pass)
        conv_multi<<<blk, 256>>>(t, i);
    }

    // ---- motion encoder: pre-norm MHA + residual ----
    ln_split<<<ROWS, 128>>>(motion, ln1g, ln1b, p_ahi + AO_H, nullptr);
    gemm_bf16<2, false, false, 2><<<dim3(1536/64, ROWS/128), 256, G_SMEM2>>>(
        p_ahi + AO_H, nullptr, nullptr, nullptr,
        p_whi + WO_QKV, p_wlo + WO_QKV, qkvb, nullptr,
        nullptr, p_b16 + BO_QKV, nullptr, ROWS, 1536, 512, 0.125f, 512);
    enc_attn_mma<<<dim3(4, 64), 256, ENC_SMEM_BYTES>>>(
        p_b16 + BO_QKV, p_ahi + AO_O, p_alo + AO_O);
    gemm_bf16<0, false, false, 3><<<dim3(512/64, ROWS/128), 256, G_SMEM3>>>(
        p_ahi + AO_O, p_alo + AO_O, nullptr, nullptr,
        p_whi + WO_OUT, p_wlo + WO_OUT, outb, motion,
        p_x, nullptr, nullptr, ROWS, 512, 512, 1.f, 512);

    // ---- pre-norm MLP + residual ----
    ln_split<<<ROWS, 128>>>(p_x, ln2g, ln2b, p_ahi + AO_H2, p_alo + AO_H2);
    gemm_bf16<1, true, false, 3><<<dim3(512/64, ROWS/128), 256, G_SMEM3>>>(
        p_ahi + AO_H2, p_alo + AO_H2, nullptr, nullptr,
        p_whi + WO_FF1, p_wlo + WO_FF1, ff1b, nullptr,
        nullptr, p_ahi + AO_FF, p_alo + AO_FF, ROWS, 512, 512, 1.f, 512);
    gemm_bf16<1, false, false, 3><<<dim3(512/64, ROWS/128), 256, G_SMEM3>>>(
        p_ahi + AO_FF, p_alo + AO_FF, nullptr, nullptr,
        p_whi + WO_FF2, p_wlo + WO_FF2, ff2b, p_x,
        nullptr, p_ahi + AO_MSCA, p_alo + AO_MSCA, ROWS, 512, 512, 1.f, 512);

    // ---- semantic-aware attention ----
    gemm_bf16<2, false, false, 2><<<dim3(512/64, ROWS/128), 256, G_SMEM2>>>(
        p_ahi + AO_MSCA, nullptr, nullptr, nullptr,
        p_whi + WO_SAQ, p_wlo + WO_SAQ, saqb, nullptr,
        nullptr, p_b16 + BO_QSA, nullptr, ROWS, 512, 512, sa_scale, 512);
    gemm_bf16<2, false, false, 2><<<dim3(1024/64, KVROWS/128), 256, G_SMEM2>>>(
        p_ahi + AO_SF, nullptr, nullptr, nullptr,
        p_whi + WO_SAKV, p_wlo + WO_SAKV, sakvb, nullptr,
        nullptr, p_b16 + BO_KV, nullptr, KVROWS, 1024, 512, 1.f, 1024);
    sa_attn_mma<<<dim3(8, 32), 128, SA_SMEM_BYTES>>>(
        p_b16 + BO_QSA, p_b16 + BO_KV, prior,
        p_ahi + AO_SM, p_alo + AO_SM);
    gemm_bf16<1, false, false, 3><<<dim3(512/64, ROWS/128), 256, G_SMEM3>>>(
        p_ahi + AO_SM, p_alo + AO_SM, nullptr, nullptr,
        p_whi + WO_SAOUT, p_wlo + WO_SAOUT, saob, nullptr,
        nullptr, p_ahi + AO_SMF, p_alo + AO_SMF, ROWS, 512, 512, 1.f, 512);

    // ---- concat-free fc1 + fc2 ----
    gemm_bf16<1, true, true, 3><<<dim3(2048/64, ROWS/128), 256, G_SMEM3>>>(
        p_ahi + AO_MSCA, p_alo + AO_MSCA, p_ahi + AO_SMF, p_alo + AO_SMF,
        p_whi + WO_FC1, p_wlo + WO_FC1, fc1b, nullptr,
        nullptr, p_ahi + AO_MH, p_alo + AO_MH, ROWS, 2048, 1024, 1.f, 2048);
    gemm_bf16<0, false, false, 3><<<dim3(512/64, ROWS/128), 256, G_SMEM3>>>(
        p_ahi + AO_MH, p_alo + AO_MH, nullptr, nullptr,
        p_whi + WO_FC2, p_wlo + WO_FC2, fc2b, nullptr,
        out, nullptr, nullptr, ROWS, 512, 2048, 1.f, 512);
}

// round 8
// speedup vs baseline: 3.9096x; 1.1172x over previous
#include <cuda_runtime.h>
#include <cuda_bf16.h>
#include <math.h>

typedef unsigned short u16;

// ---------------- problem constants ----------------
#define BSZ   8
#define SEQL  512
#define NSC   4096
#define FD    512
#define ROWS  (BSZ*SEQL)        // 4096
#define KVROWS (BSZ*NSC)        // 32768

// ---------------- scratch (device globals; no allocation allowed) ----------
__device__ float g_x[ROWS*FD];

// split bf16 plane bundles (hi/lo)
#define WO_QKV   0
#define WO_OUT   786432
#define WO_FF1   1048576
#define WO_FF2   1310720
#define WO_SAQ   1572864
#define WO_SAKV  1835008
#define WO_SAOUT 2359296
#define WO_FC1   2621440
#define WO_FC2   4718592
__device__ u16 w_hi[5767168];
__device__ u16 w_lo[5767168];

#define AO_H    0
#define AO_O    2097152
#define AO_H2   4194304
#define AO_FF   6291456
#define AO_MSCA 8388608
#define AO_SM   10485760
#define AO_SMF  12582912
#define AO_MH   14680064
#define AO_SF   23068672
__device__ u16 a_hi[39845888];
__device__ u16 a_lo[39845888];

// single-bf16 planes
#define BO_QSA 0
#define BO_KV  2097152
#define BO_QKV 35651584           // ROWS*1536
__device__ u16 a_b16[41943040];

// ---------------- helpers ----------------
__device__ __forceinline__ unsigned smem_u32(const void* p) {
    unsigned r;
    asm("{ .reg .u64 t; cvta.to.shared.u64 t, %1; cvt.u32.u64 %0, t; }"
        : "=r"(r) : "l"(p));
    return r;
}
__device__ __forceinline__ void split2(float x0, float x1,
                                       unsigned& hi2, unsigned& lo2) {
    asm("cvt.rn.bf16x2.f32 %0, %1, %2;" : "=r"(hi2) : "f"(x1), "f"(x0));
    float h0 = __uint_as_float(hi2 << 16);
    float h1 = __uint_as_float(hi2 & 0xffff0000u);
    float l0 = x0 - h0;
    float l1 = x1 - h1;
    asm("cvt.rn.bf16x2.f32 %0, %1, %2;" : "=r"(lo2) : "f"(l1), "f"(l0));
}
__device__ __forceinline__ unsigned pkbf(float lo, float hi) {
    unsigned r;
    asm("cvt.rn.bf16x2.f32 %0, %1, %2;" : "=r"(r) : "f"(hi), "f"(lo));
    return r;
}
__device__ __forceinline__ float gelu_exact(float x) {
    return 0.5f * x * (1.0f + erff(x * 0.70710678118654752f));
}
__device__ __forceinline__ void cp16(unsigned dst, const void* src) {
    asm volatile("cp.async.cg.shared.global [%0], [%1], 16;" :: "r"(dst), "l"(src));
}
#define CP_COMMIT() asm volatile("cp.async.commit_group;" ::: "memory")
#define CP_WAIT1()  asm volatile("cp.async.wait_group 1;" ::: "memory")
#define CP_WAIT0()  asm volatile("cp.async.wait_group 0;" ::: "memory")

#define LDSM4(r, addr) \
    asm volatile("ldmatrix.sync.aligned.m8n8.x4.shared.b16 {%0,%1,%2,%3}, [%4];" \
        : "=r"((r)[0]), "=r"((r)[1]), "=r"((r)[2]), "=r"((r)[3]) : "r"(addr))
#define LDSM4T(r, addr) \
    asm volatile("ldmatrix.sync.aligned.m8n8.x4.trans.shared.b16 {%0,%1,%2,%3}, [%4];" \
        : "=r"((r)[0]), "=r"((r)[1]), "=r"((r)[2]), "=r"((r)[3]) : "r"(addr))
#define MMA16816(d, a, b0, b1) \
    asm volatile("mma.sync.aligned.m16n8k16.row.col.f32.bf16.bf16.f32 " \
        "{%0,%1,%2,%3}, {%4,%5,%6,%7}, {%8,%9}, {%0,%1,%2,%3};" \
        : "+f"((d)[0]), "+f"((d)[1]), "+f"((d)[2]), "+f"((d)[3]) \
        : "r"((a)[0]), "r"((a)[1]), "r"((a)[2]), "r"((a)[3]), \
          "r"(b0), "r"(b1))

// ---------------- merged fp32 -> split planes converter --------------------
struct ConvSeg { const float* src; u16* hi; u16* lo; int n4; int blk0; };
struct ConvTab { ConvSeg s[10]; };

__global__ void __launch_bounds__(256)
conv_multi(ConvTab t, int nseg) {
    const int blk = blockIdx.x;
    int si = 0;
    #pragma unroll
    for (int k = 1; k < 10; k++)
        if (k < nseg && blk >= t.s[k].blk0) si = k;
    const ConvSeg sg = t.s[si];
    int i = (blk - sg.blk0) * 256 + threadIdx.x;
    if (i >= sg.n4) return;
    float4 v = *(const float4*)(sg.src + (size_t)i * 4);
    unsigned h01, l01, h23, l23;
    split2(v.x, v.y, h01, l01);
    split2(v.z, v.w, h23, l23);
    *(uint2*)(sg.hi + (size_t)i * 4) = make_uint2(h01, h23);
    if (sg.lo)
        *(uint2*)(sg.lo + (size_t)i * 4) = make_uint2(l01, l23);
}

// ====== pipelined HMMA bf16-split GEMM:  C[M,N] = epi( A @ W^T ) ============
// BK=64, 2-stage cp.async double buffer, block 128x64, 8 warps.
// PASSES=3: AhBh + AhBl + AlBh.  PASSES=2: AhBh + AhBl (A-lo never loaded).
// OMODE: 0 fp32 out, 1 split-plane, 2 single-bf16. alpha on cols < ncut.
#define PADW 72   // u16 stride per row (144 B) -> conflict-free ldmatrix phases

template<int OMODE, bool GELU, bool CAT, int PASSES>
__global__ void __launch_bounds__(256, 2)
gemm_bf16(const u16* __restrict__ Ah, const u16* __restrict__ Al,
          const u16* __restrict__ A2h, const u16* __restrict__ A2l,
          const u16* __restrict__ Wh, const u16* __restrict__ Wl,
          const float* __restrict__ bias, const float* __restrict__ res,
          float* __restrict__ Cf, u16* __restrict__ Chi, u16* __restrict__ Clo,
          int M, int N, int K, float alpha, int ncut) {
    constexpr unsigned ALB  = 18432u;                           // A plane bytes
    constexpr unsigned BHB  = (PASSES == 3) ? 36864u : 18432u;  // B-hi offset
    constexpr unsigned BPL  = 9216u;                            // B plane bytes
    constexpr unsigned STGB = BHB + 2u * BPL;

    extern __shared__ __align__(16) u16 smu[];
    const unsigned sb = smem_u32(smu);
    const int tid = threadIdx.x;
    const int lane = tid & 31;
    const int wid = tid >> 5;
    const int wm = wid & 3;
    const int wn = wid >> 2;
    const int m0 = blockIdx.y * 128;
    const int n0 = blockIdx.x * 64;

    float acc[2][4][4];
    #pragma unroll
    for (int mt = 0; mt < 2; mt++)
        #pragma unroll
        for (int nt = 0; nt < 4; nt++)
            #pragma unroll
            for (int e = 0; e < 4; e++) acc[mt][nt][e] = 0.f;

    const int lr = lane & 7;
    const int arow = lr + ((lane >> 3) & 1) * 8;
    const int acol = (lane >> 4) * 8;
    const int brow = (lane >> 4) * 8 + lr;
    const int bcol = ((lane >> 3) & 1) * 8;

    auto issue = [&](int ch, int st) {
        const int k0 = ch * 64;
        const unsigned base = sb + st * STGB;
        const u16 *pAh, *pAl;
        int astr, ac;
        if (CAT) {
            if (k0 < 512) { pAh = Ah;  pAl = Al;  ac = k0; }
            else          { pAh = A2h; pAl = A2l; ac = k0 - 512; }
            astr = 512;
        } else { pAh = Ah; pAl = Al; ac = k0; astr = K; }
        #pragma unroll
        for (int i = 0; i < 4; i++) {
            int u = tid + i * 256;
            int r = u >> 3, q = u & 7;
            unsigned d = base + (r * PADW + q * 8) * 2;
            size_t so = (size_t)(m0 + r) * astr + ac + q * 8;
            cp16(d, pAh + so);
            if (PASSES == 3) cp16(d + ALB, pAl + so);
        }
        #pragma unroll
        for (int i = 0; i < 2; i++) {
            int u = tid + i * 256;
            int r = u >> 3, q = u & 7;
            unsigned d = base + BHB + (r * PADW + q * 8) * 2;
            size_t so = (size_t)(n0 + r) * K + k0 + q * 8;
            cp16(d, Wh + so);
            cp16(d + BPL, Wl + so);
        }
        CP_COMMIT();
    };

    const int chunks = K >> 6;
    issue(0, 0);
    for (int ch = 0; ch < chunks; ch++) {
        const int st = ch & 1;
        if (ch + 1 < chunks) { issue(ch + 1, st ^ 1); CP_WAIT1(); }
        else CP_WAIT0();
        __syncthreads();

        const unsigned aH = sb + st * STGB;
        const unsigned aL = aH + ALB;
        const unsigned bH = aH + BHB;
        const unsigned bL = bH + BPL;

        #pragma unroll
        for (int ks = 0; ks < 4; ks++) {
            unsigned ah[2][4], al[2][4], bh[2][4], bl[2][4];
            #pragma unroll
            for (int mt = 0; mt < 2; mt++) {
                unsigned off =
                    (unsigned)((wm*32 + mt*16 + arow) * PADW + ks*16 + acol) * 2u;
                LDSM4(ah[mt], aH + off);
                if (PASSES == 3) LDSM4(al[mt], aL + off);
            }
            #pragma unroll
            for (int np = 0; np < 2; np++) {
                unsigned off =
                    (unsigned)((wn*32 + np*16 + brow) * PADW + ks*16 + bcol) * 2u;
                LDSM4(bh[np], bH + off);
                LDSM4(bl[np], bL + off);
            }
            #pragma unroll
            for (int mt = 0; mt < 2; mt++) {
                #pragma unroll
                for (int nt = 0; nt < 4; nt++) {
                    const int p = nt >> 1, o = (nt & 1) * 2;
                    MMA16816(acc[mt][nt], ah[mt], bh[p][o], bh[p][o+1]);
                    MMA16816(acc[mt][nt], ah[mt], bl[p][o], bl[p][o+1]);
                    if (PASSES == 3)
                        MMA16816(acc[mt][nt], al[mt], bh[p][o], bh[p][o+1]);
                }
            }
        }
        __syncthreads();
    }

    // epilogue
    const int erow = lane >> 2;
    const int ecol = (lane & 3) * 2;
    #pragma unroll
    for (int mt = 0; mt < 2; mt++) {
        #pragma unroll
        for (int nt = 0; nt < 4; nt++) {
            int row = m0 + wm*32 + mt*16 + erow;
            int col = n0 + wn*32 + nt*8 + ecol;
            float aeff = (col < ncut) ? alpha : 1.f;
            float2 bv = *(const float2*)(bias + col);
            #pragma unroll
            for (int half = 0; half < 2; half++) {
                int r = row + half * 8;
                float v0 = (acc[mt][nt][half*2 + 0] + bv.x) * aeff;
                float v1 = (acc[mt][nt][half*2 + 1] + bv.y) * aeff;
                if (GELU) { v0 = gelu_exact(v0); v1 = gelu_exact(v1); }
                if (res) {
                    float2 rv = *(const float2*)(res + (size_t)r * N + col);
                    v0 += rv.x; v1 += rv.y;
                }
                if (OMODE == 0) {
                    *(float2*)(Cf + (size_t)r * N + col) = make_float2(v0, v1);
                } else if (OMODE == 1) {
                    unsigned h2, l2;
                    split2(v0, v1, h2, l2);
                    *(unsigned*)(Chi + (size_t)r * N + col) = h2;
                    *(unsigned*)(Clo + (size_t)r * N + col) = l2;
                } else {
                    *(unsigned*)(Chi + (size_t)r * N + col) = pkbf(v0, v1);
                }
            }
        }
    }
}

// ---------------- LayerNorm (512) -> split planes (ol may be null) ----------
__global__ void __launch_bounds__(128)
ln_split(const float* __restrict__ x, const float* __restrict__ g,
         const float* __restrict__ b, u16* __restrict__ oh,
         u16* __restrict__ ol) {
    __shared__ float red[4];
    const int row = blockIdx.x;
    const int t = threadIdx.x;
    const float* xr = x + (size_t)row * 512;
    float4 v = *(const float4*)(xr + t * 4);
    float s = v.x + v.y + v.z + v.w;
    #pragma unroll
    for (int off = 16; off; off >>= 1) s += __shfl_xor_sync(0xffffffffu, s, off);
    if ((t & 31) == 0) red[t >> 5] = s;
    __syncthreads();
    s = red[0] + red[1] + red[2] + red[3];
    const float mean = s * (1.f / 512.f);
    __syncthreads();
    float d0 = v.x - mean, d1 = v.y - mean, d2 = v.z - mean, d3 = v.w - mean;
    float ss = d0*d0 + d1*d1 + d2*d2 + d3*d3;
    #pragma unroll
    for (int off = 16; off; off >>= 1) ss += __shfl_xor_sync(0xffffffffu, ss, off);
    if ((t & 31) == 0) red[t >> 5] = ss;
    __syncthreads();
    ss = red[0] + red[1] + red[2] + red[3];
    const float rstd = rsqrtf(ss * (1.f / 512.f) + 1e-5f);
    float4 g4 = *(const float4*)(g + t * 4);
    float4 b4 = *(const float4*)(b + t * 4);
    float n0 = d0 * rstd * g4.x + b4.x;
    float n1 = d1 * rstd * g4.y + b4.y;
    float n2 = d2 * rstd * g4.z + b4.z;
    float n3 = d3 * rstd * g4.w + b4.w;
    size_t off = (size_t)row * 512 + t * 4;
    if (ol) {
        unsigned h2, l2;
        split2(n0, n1, h2, l2);
        *(unsigned*)(oh + off) = h2;  *(unsigned*)(ol + off) = l2;
        split2(n2, n3, h2, l2);
        *(unsigned*)(oh + off + 2) = h2;  *(unsigned*)(ol + off + 2) = l2;
    } else {
        *(unsigned*)(oh + off)     = pkbf(n0, n1);
        *(unsigned*)(oh + off + 2) = pkbf(n2, n3);
    }
}

// ---------------- encoder self-attention (HMMA flash, dh=64) ----------------
// BQ=128 (8 warps x 16 rows), BKV=64. q pre-scaled by 0.125 at qkv GEMM.
#define ENC_QU   (128*72)
#define ENC_KVST (64*72)
#define ENC_SMEM_BYTES ((ENC_QU + 4*ENC_KVST)*2)

__global__ void __launch_bounds__(256, 2)
enc_attn_mma(const u16* __restrict__ qkv, u16* __restrict__ ohi,
             u16* __restrict__ olo) {
    extern __shared__ __align__(16) u16 smu[];
    const unsigned sb = smem_u32(smu);
    const int tid = threadIdx.x;
    const int lane = tid & 31;
    const int wid = tid >> 5;
    const int b = blockIdx.y >> 3;
    const int h = blockIdx.y & 7;
    const int q0 = blockIdx.x * 128;

    {
        const u16* qb = qkv + (size_t)(b*512 + q0) * 1536 + h*64;
        #pragma unroll
        for (int i = 0; i < 4; i++) {
            int u = tid + i * 256;
            int r = u >> 3, c = (u & 7) * 8;
            cp16(sb + (r*72 + c)*2, qb + (size_t)r*1536 + c);
        }
        CP_COMMIT();
    }

    auto loadKV = [&](int kt, int st) {
        const u16* kb = qkv + (size_t)(b*512 + kt*64) * 1536 + 512 + h*64;
        unsigned kbase = sb + (ENC_QU + st * 2 * ENC_KVST) * 2;
        unsigned vbase = kbase + ENC_KVST * 2;
        #pragma unroll
        for (int i = 0; i < 2; i++) {
            int u = tid + i * 256;
            int r = u >> 3, c = (u & 7) * 8;
            size_t so = (size_t)r * 1536 + c;
            cp16(kbase + (r*72 + c)*2, kb + so);
            cp16(vbase + (r*72 + c)*2, kb + so + 512);
        }
        CP_COMMIT();
    };

    loadKV(0, 0);

    float m0r = -1e30f, m1r = -1e30f, l0 = 0.f, l1 = 0.f;
    float acc[8][4];
    #pragma unroll
    for (int dn = 0; dn < 8; dn++)
        #pragma unroll
        for (int e = 0; e < 4; e++) acc[dn][e] = 0.f;

    const int r0 = lane >> 2;
    const int qrow_g = b*512 + q0 + wid*16;
    const unsigned qoff =
        (unsigned)((wid*16 + (lane & 15)) * 72 + (lane >> 4) * 8) * 2;
    const unsigned koff_row = (unsigned)((lane >> 4) * 8 + (lane & 7));
    const unsigned kcol = (unsigned)(((lane >> 3) & 1) * 8);
    const unsigned vrow = (unsigned)((lane & 7) + ((lane >> 4) << 3));

    for (int kt = 0; kt < 8; kt++) {
        const int st = kt & 1;
        if (kt + 1 < 8) { loadKV(kt + 1, st ^ 1); CP_WAIT1(); }
        else CP_WAIT0();
        __syncthreads();

        const unsigned Kb = sb + (ENC_QU + st * 2 * ENC_KVST) * 2;
        const unsigned Vb = Kb + ENC_KVST * 2;

        float s[8][4];
        #pragma unroll
        for (int jn = 0; jn < 8; jn++)
            #pragma unroll
            for (int e = 0; e < 4; e++) s[jn][e] = 0.f;

        #pragma unroll
        for (int kk = 0; kk < 4; kk++) {
            unsigned aq[4];
            LDSM4(aq, sb + qoff + kk * 32);
            #pragma unroll
            for (int jn2 = 0; jn2 < 4; jn2++) {
                unsigned bk[4];
                LDSM4(bk, Kb + ((jn2*16 + koff_row) * 72 + kk*16 + kcol) * 2);
                MMA16816(s[jn2*2],     aq, bk[0], bk[1]);
                MMA16816(s[jn2*2 + 1], aq, bk[2], bk[3]);
            }
        }

        float mx0 = s[0][0], mx1 = s[0][2];
        #pragma unroll
        for (int jn = 0; jn < 8; jn++) {
            mx0 = fmaxf(mx0, fmaxf(s[jn][0], s[jn][1]));
            mx1 = fmaxf(mx1, fmaxf(s[jn][2], s[jn][3]));
        }
        mx0 = fmaxf(mx0, __shfl_xor_sync(0xffffffffu, mx0, 1));
        mx0 = fmaxf(mx0, __shfl_xor_sync(0xffffffffu, mx0, 2));
        mx1 = fmaxf(mx1, __shfl_xor_sync(0xffffffffu, mx1, 1));
        mx1 = fmaxf(mx1, __shfl_xor_sync(0xffffffffu, mx1, 2));
        float mn0 = fmaxf(m0r, mx0), mn1 = fmaxf(m1r, mx1);
        float c0 = __expf(m0r - mn0), c1 = __expf(m1r - mn1);
        float sum0 = 0.f, sum1 = 0.f;
        #pragma unroll
        for (int jn = 0; jn < 8; jn++) {
            s[jn][0] = __expf(s[jn][0] - mn0);
            s[jn][1] = __expf(s[jn][1] - mn0);
            s[jn][2] = __expf(s[jn][2] - mn1);
            s[jn][3] = __expf(s[jn][3] - mn1);
            sum0 += s[jn][0] + s[jn][1];
            sum1 += s[jn][2] + s[jn][3];
        }
        sum0 += __shfl_xor_sync(0xffffffffu, sum0, 1);
        sum0 += __shfl_xor_sync(0xffffffffu, sum0, 2);
        sum1 += __shfl_xor_sync(0xffffffffu, sum1, 1);
        sum1 += __shfl_xor_sync(0xffffffffu, sum1, 2);
        l0 = l0 * c0 + sum0;  l1 = l1 * c1 + sum1;
        m0r = mn0;  m1r = mn1;
        #pragma unroll
        for (int dn = 0; dn < 8; dn++) {
            acc[dn][0] *= c0; acc[dn][1] *= c0;
            acc[dn][2] *= c1; acc[dn][3] *= c1;
        }

        unsigned ap[4][4];
        #pragma unroll
        for (int ks = 0; ks < 4; ks++) {
            ap[ks][0] = pkbf(s[2*ks][0],     s[2*ks][1]);
            ap[ks][1] = pkbf(s[2*ks][2],     s[2*ks][3]);
            ap[ks][2] = pkbf(s[2*ks + 1][0], s[2*ks + 1][1]);
            ap[ks][3] = pkbf(s[2*ks + 1][2], s[2*ks + 1][3]);
        }

        #pragma unroll
        for (int ks = 0; ks < 4; ks++) {
            #pragma unroll
            for (int dn2 = 0; dn2 < 4; dn2++) {
                unsigned bv[4];
                LDSM4T(bv, Vb + ((ks*16 + vrow) * 72 + dn2*16 + kcol) * 2);
                MMA16816(acc[dn2*2],     ap[ks], bv[0], bv[2]);
                MMA16816(acc[dn2*2 + 1], ap[ks], bv[1], bv[3]);
            }
        }
        __syncthreads();
    }

    const float inv0 = 1.f / l0, inv1 = 1.f / l1;
    const size_t orow0 = (size_t)(qrow_g + r0) * 512 + h*64;
    const size_t orow1 = orow0 + (size_t)8 * 512;
    #pragma unroll
    for (int dn = 0; dn < 8; dn++) {
        int col = dn*8 + (lane & 3)*2;
        unsigned h2, l2;
        split2(acc[dn][0]*inv0, acc[dn][1]*inv0, h2, l2);
        *(unsigned*)(ohi + orow0 + col) = h2;
        *(unsigned*)(olo + orow0 + col) = l2;
        split2(acc[dn][2]*inv1, acc[dn][3]*inv1, h2, l2);
        *(unsigned*)(ohi + orow1 + col) = h2;
        *(unsigned*)(olo + orow1 + col) = l2;
    }
}

// ---------------- semantic-aware cross-attention (HMMA flash) ---------------
// BQ=64 (4 warps x 16 rows), BKV=64, dh=128. 256 CTAs, 2 per SM.
#define SA_QU   (64*136)
#define SA_KVST (64*136)
#define SA_SMEM_BYTES ((SA_QU + 4*SA_KVST)*2)   // 87040

__global__ void __launch_bounds__(128, 2)
sa_attn_mma(const u16* __restrict__ q, const u16* __restrict__ kv,
            const float* __restrict__ prior, u16* __restrict__ smh,
            u16* __restrict__ sml) {
    extern __shared__ __align__(16) u16 smu[];
    const unsigned sb = smem_u32(smu);
    const int tid = threadIdx.x;
    const int lane = tid & 31;
    const int wid = tid >> 5;          // 0..3
    const int b = blockIdx.y >> 2;
    const int h = blockIdx.y & 3;
    const int q0 = blockIdx.x * 64;

    // stage Q (64 x 128)
    {
        const u16* qb = q + (size_t)b*262144 + h*65536 + (size_t)q0*128;
        #pragma unroll
        for (int i = 0; i < 8; i++) {
            int u = tid + i * 128;
            int r = u >> 4, c = (u & 15) * 8;
            cp16(sb + (r*136 + c)*2, qb + (size_t)r*128 + c);
        }
        CP_COMMIT();
    }

    auto loadKV = [&](int kt, int st) {
        const u16* kb = kv + ((size_t)(b*4096 + kt*64))*1024 + h*128;
        unsigned kbase = sb + (SA_QU + st * 2 * SA_KVST) * 2;
        unsigned vbase = kbase + SA_KVST * 2;
        #pragma unroll
        for (int i = 0; i < 8; i++) {
            int u = tid + i * 128;
            int r = u >> 4, c = (u & 15) * 8;
            size_t so = (size_t)r * 1024 + c;
            cp16(kbase + (r*136 + c)*2, kb + so);
            cp16(vbase + (r*136 + c)*2, kb + so + 512);
        }
        CP_COMMIT();
    };

    loadKV(0, 0);

    float m0r = -1e30f, m1r = -1e30f, l0 = 0.f, l1 = 0.f;
    float acc[16][4];
    #pragma unroll
    for (int dn = 0; dn < 16; dn++)
        #pragma unroll
        for (int e = 0; e < 4; e++) acc[dn][e] = 0.f;

    const int r0 = lane >> 2;
    const int qrow_g = b*512 + q0 + wid*16;
    const unsigned qoff =
        (unsigned)((wid*16 + (lane & 15)) * 136 + (lane >> 4) * 8) * 2;
    const unsigned koff_row = (unsigned)((lane >> 4) * 8 + (lane & 7));
    const unsigned kcol = (unsigned)(((lane >> 3) & 1) * 8);
    const unsigned vrow = (unsigned)((lane & 7) + ((lane >> 4) << 3));

    for (int kt = 0; kt < 64; kt++) {
        const int st = kt & 1;
        if (kt + 1 < 64) { loadKV(kt + 1, st ^ 1); CP_WAIT1(); }
        else CP_WAIT0();
        __syncthreads();

        const unsigned Kb = sb + (SA_QU + st * 2 * SA_KVST) * 2;
        const unsigned Vb = Kb + SA_KVST * 2;

        float s[8][4];
        {
            const float* pb = prior + (size_t)(qrow_g + r0) * 4096
                              + kt*64 + (lane & 3) * 2;
            const float* pb2 = pb + (size_t)8 * 4096;
            #pragma unroll
            for (int jn = 0; jn < 8; jn++) {
                float2 a = *(const float2*)(pb + jn * 8);
                float2 c = *(const float2*)(pb2 + jn * 8);
                s[jn][0] = a.x; s[jn][1] = a.y;
                s[jn][2] = c.x; s[jn][3] = c.y;
            }
        }
        #pragma unroll
        for (int kk = 0; kk < 8; kk++) {
            unsigned aq[4];
            LDSM4(aq, sb + qoff + kk * 32);
            #pragma unroll
            for (int jn2 = 0; jn2 < 4; jn2++) {
                unsigned bk[4];
                LDSM4(bk, Kb + ((jn2*16 + koff_row) * 136 + kk*16 + kcol) * 2);
                MMA16816(s[jn2*2],     aq, bk[0], bk[1]);
                MMA16816(s[jn2*2 + 1], aq, bk[2], bk[3]);
            }
        }

        float mx0 = s[0][0], mx1 = s[0][2];
        #pragma unroll
        for (int jn = 0; jn < 8; jn++) {
            mx0 = fmaxf(mx0, fmaxf(s[jn][0], s[jn][1]));
            mx1 = fmaxf(mx1, fmaxf(s[jn][2], s[jn][3]));
        }
        mx0 = fmaxf(mx0, __shfl_xor_sync(0xffffffffu, mx0, 1));
        mx0 = fmaxf(mx0, __shfl_xor_sync(0xffffffffu, mx0, 2));
        mx1 = fmaxf(mx1, __shfl_xor_sync(0xffffffffu, mx1, 1));
        mx1 = fmaxf(mx1, __shfl_xor_sync(0xffffffffu, mx1, 2));
        float mn0 = fmaxf(m0r, mx0), mn1 = fmaxf(m1r, mx1);
        float c0 = __expf(m0r - mn0), c1 = __expf(m1r - mn1);
        float sum0 = 0.f, sum1 = 0.f;
        #pragma unroll
        for (int jn = 0; jn < 8; jn++) {
            s[jn][0] = __expf(s[jn][0] - mn0);
            s[jn][1] = __expf(s[jn][1] - mn0);
            s[jn][2] = __expf(s[jn][2] - mn1);
            s[jn][3] = __expf(s[jn][3] - mn1);
            sum0 += s[jn][0] + s[jn][1];
            sum1 += s[jn][2] + s[jn][3];
        }
        sum0 += __shfl_xor_sync(0xffffffffu, sum0, 1);
        sum0 += __shfl_xor_sync(0xffffffffu, sum0, 2);
        sum1 += __shfl_xor_sync(0xffffffffu, sum1, 1);
        sum1 += __shfl_xor_sync(0xffffffffu, sum1, 2);
        l0 = l0 * c0 + sum0;  l1 = l1 * c1 + sum1;
        m0r = mn0;  m1r = mn1;
        #pragma unroll
        for (int dn = 0; dn < 16; dn++) {
            acc[dn][0] *= c0; acc[dn][1] *= c0;
            acc[dn][2] *= c1; acc[dn][3] *= c1;
        }

        unsigned ap[4][4];
        #pragma unroll
        for (int ks = 0; ks < 4; ks++) {
            ap[ks][0] = pkbf(s[2*ks][0],     s[2*ks][1]);
            ap[ks][1] = pkbf(s[2*ks][2],     s[2*ks][3]);
            ap[ks][2] = pkbf(s[2*ks + 1][0], s[2*ks + 1][1]);
            ap[ks][3] = pkbf(s[2*ks + 1][2], s[2*ks + 1][3]);
        }

        #pragma unroll
        for (int ks = 0; ks < 4; ks++) {
            #pragma unroll
            for (int dn2 = 0; dn2 < 8; dn2++) {
                unsigned bv[4];
                LDSM4T(bv, Vb + ((ks*16 + vrow) * 136 + dn2*16 + kcol) * 2);
                MMA16816(acc[dn2*2],     ap[ks], bv[0], bv[2]);
                MMA16816(acc[dn2*2 + 1], ap[ks], bv[1], bv[3]);
            }
        }
        __syncthreads();
    }

    const float inv0 = 1.f / l0, inv1 = 1.f / l1;
    const size_t orow0 = (size_t)(qrow_g + r0) * 512 + h*128;
    const size_t orow1 = orow0 + (size_t)8 * 512;
    #pragma unroll
    for (int dn = 0; dn < 16; dn++) {
        int col = dn*8 + (lane & 3)*2;
        unsigned h2, l2;
        split2(acc[dn][0]*inv0, acc[dn][1]*inv0, h2, l2);
        *(unsigned*)(smh + orow0 + col) = h2;
        *(unsigned*)(sml + orow0 + col) = l2;
        split2(acc[dn][2]*inv1, acc[dn][3]*inv1, h2, l2);
        *(unsigned*)(smh + orow1 + col) = h2;
        *(unsigned*)(sml + orow1 + col) = l2;
    }
}

// ---------------- launch --------------------------------------------------
extern "C" void kernel_launch(void* const* d_in, const int* in_sizes, int n_in,
                              void* d_out, int out_size) {
    const float* motion      = (const float*)d_in[0];
    const float* scene_feats = (const float*)d_in[2];
    const float* prior       = (const float*)d_in[3];
    const float* ln1g = (const float*)d_in[4];
    const float* ln1b = (const float*)d_in[5];
    const float* qkvw = (const float*)d_in[6];
    const float* qkvb = (const float*)d_in[7];
    const float* outw = (const float*)d_in[8];
    const float* outb = (const float*)d_in[9];
    const float* ln2g = (const float*)d_in[10];
    const float* ln2b = (const float*)d_in[11];
    const float* ff1w = (const float*)d_in[12];
    const float* ff1b = (const float*)d_in[13];
    const float* ff2w = (const float*)d_in[14];
    const float* ff2b = (const float*)d_in[15];
    const float* saqw = (const float*)d_in[16];
    const float* saqb = (const float*)d_in[17];
    const float* sakvw = (const float*)d_in[18];
    const float* sakvb = (const float*)d_in[19];
    const float* saow = (const float*)d_in[20];
    const float* saob = (const float*)d_in[21];
    const float* fc1w = (const float*)d_in[22];
    const float* fc1b = (const float*)d_in[23];
    const float* fc2w = (const float*)d_in[24];
    const float* fc2b = (const float*)d_in[25];
    float* out = (float*)d_out;

    float* p_x;
    u16 *p_whi, *p_wlo, *p_ahi, *p_alo, *p_b16;
    cudaGetSymbolAddress((void**)&p_x,   g_x);
    cudaGetSymbolAddress((void**)&p_whi, w_hi);
    cudaGetSymbolAddress((void**)&p_wlo, w_lo);
    cudaGetSymbolAddress((void**)&p_ahi, a_hi);
    cudaGetSymbolAddress((void**)&p_alo, a_lo);
    cudaGetSymbolAddress((void**)&p_b16, a_b16);

    const int G_SMEM3 = 110592, G_SMEM2 = 73728;
    cudaFuncSetAttribute(gemm_bf16<0, false, false, 3>,
        cudaFuncAttributeMaxDynamicSharedMemorySize, G_SMEM3);
    cudaFuncSetAttribute(gemm_bf16<1, false, false, 3>,
        cudaFuncAttributeMaxDynamicSharedMemorySize, G_SMEM3);
    cudaFuncSetAttribute(gemm_bf16<1, true, false, 3>,
        cudaFuncAttributeMaxDynamicSharedMemorySize, G_SMEM3);
    cudaFuncSetAttribute(gemm_bf16<1, true, true, 3>,
        cudaFuncAttributeMaxDynamicSharedMemorySize, G_SMEM3);
    cudaFuncSetAttribute(gemm_bf16<2, false, false, 2>,
        cudaFuncAttributeMaxDynamicSharedMemorySize, G_SMEM2);
    cudaFuncSetAttribute(enc_attn_mma,
        cudaFuncAttributeMaxDynamicSharedMemorySize, ENC_SMEM_BYTES);
    cudaFuncSetAttribute(sa_attn_mma,
        cudaFuncAttributeMaxDynamicSharedMemorySize, SA_SMEM_BYTES);

    const float sa_scale = 0.044194173824159216f;  // 512^-0.5

    // ---- merged weight + scene_feats split conversion ----
    {
        ConvTab t;
        int blk = 0, i = 0;
        auto add = [&](const float* src, u16* hi, u16* lo, int n) {
            t.s[i] = ConvSeg{src, hi, lo, n / 4, blk};
            blk += (n / 4 + 255) / 256;
            i++;
        };
        add(qkvw,  p_whi + WO_QKV,   p_wlo + WO_QKV,   1536*512);
        add(outw,  p_whi + WO_OUT,   p_wlo + WO_OUT,   512*512);
        add(ff1w,  p_whi + WO_FF1,   p_wlo + WO_FF1,   512*512);
        add(ff2w,  p_whi + WO_FF2,   p_wlo + WO_FF2,   512*512);
        add(saqw,  p_whi + WO_SAQ,   p_wlo + WO_SAQ,   512*512);
        add(sakvw, p_whi + WO_SAKV,  p_wlo + WO_SAKV,  1024*512);
        add(saow,  p_whi + WO_SAOUT, p_wlo + WO_SAOUT, 512*512);
        add(fc1w,  p_whi + WO_FC1,   p_wlo + WO_FC1,   2048*1024);
        add(fc2w,  p_whi + WO_FC2,   p_wlo + WO_FC2,   512*2048);
        add(scene_feats, p_ahi + AO_SF, nullptr, KVROWS*512);   // lo unused (2-pass)
        conv_multi<<<blk, 256>>>(t, i);
    }

    // ---- motion encoder: pre-norm MHA + residual ----
    ln_split<<<ROWS, 128>>>(motion, ln1g, ln1b, p_ahi + AO_H, nullptr);
    gemm_bf16<2, false, false, 2><<<dim3(1536/64, ROWS/128), 256, G_SMEM2>>>(
        p_ahi + AO_H, nullptr, nullptr, nullptr,
        p_whi + WO_QKV, p_wlo + WO_QKV, qkvb, nullptr,
        nullptr, p_b16 + BO_QKV, nullptr, ROWS, 1536, 512, 0.125f, 512);
    enc_attn_mma<<<dim3(4, 64), 256, ENC_SMEM_BYTES>>>(
        p_b16 + BO_QKV, p_ahi + AO_O, p_alo + AO_O);
    gemm_bf16<0, false, false, 3><<<dim3(512/64, ROWS/128), 256, G_SMEM3>>>(
        p_ahi + AO_O, p_alo + AO_O, nullptr, nullptr,
        p_whi + WO_OUT, p_wlo + WO_OUT, outb, motion,
        p_x, nullptr, nullptr, ROWS, 512, 512, 1.f, 512);

    // ---- pre-norm MLP + residual ----
    ln_split<<<ROWS, 128>>>(p_x, ln2g, ln2b, p_ahi + AO_H2, p_alo + AO_H2);
    gemm_bf16<1, true, false, 3><<<dim3(512/64, ROWS/128), 256, G_SMEM3>>>(
        p_ahi + AO_H2, p_alo + AO_H2, nullptr, nullptr,
        p_whi + WO_FF1, p_wlo + WO_FF1, ff1b, nullptr,
        nullptr, p_ahi + AO_FF, p_alo + AO_FF, ROWS, 512, 512, 1.f, 512);
    gemm_bf16<1, false, false, 3><<<dim3(512/64, ROWS/128), 256, G_SMEM3>>>(
        p_ahi + AO_FF, p_alo + AO_FF, nullptr, nullptr,
        p_whi + WO_FF2, p_wlo + WO_FF2, ff2b, p_x,
        nullptr, p_ahi + AO_MSCA, p_alo + AO_MSCA, ROWS, 512, 512, 1.f, 512);

    // ---- semantic-aware attention ----
    gemm_bf16<2, false, false, 2><<<dim3(512/64, ROWS/128), 256, G_SMEM2>>>(
        p_ahi + AO_MSCA, nullptr, nullptr, nullptr,
        p_whi + WO_SAQ, p_wlo + WO_SAQ, saqb, nullptr,
        nullptr, p_b16 + BO_QSA, nullptr, ROWS, 512, 512, sa_scale, 512);
    gemm_bf16<2, false, false, 2><<<dim3(1024/64, KVROWS/128), 256, G_SMEM2>>>(
        p_ahi + AO_SF, nullptr, nullptr, nullptr,
        p_whi + WO_SAKV, p_wlo + WO_SAKV, sakvb, nullptr,
        nullptr, p_b16 + BO_KV, nullptr, KVROWS, 1024, 512, 1.f, 1024);
    sa_attn_mma<<<dim3(8, 32), 128, SA_SMEM_BYTES>>>(
        p_b16 + BO_QSA, p_b16 + BO_KV, prior,
        p_ahi + AO_SM, p_alo + AO_SM);
    gemm_bf16<1, false, false, 3><<<dim3(512/64, ROWS/128), 256, G_SMEM3>>>(
        p_ahi + AO_SM, p_alo + AO_SM, nullptr, nullptr,
        p_whi + WO_SAOUT, p_wlo + WO_SAOUT, saob, nullptr,
        nullptr, p_ahi + AO_SMF, p_alo + AO_SMF, ROWS, 512, 512, 1.f, 512);

    // ---- concat-free fc1 + fc2 ----
    gemm_bf16<1, true, true, 3><<<dim3(2048/64, ROWS/128), 256, G_SMEM3>>>(
        p_ahi + AO_MSCA, p_alo + AO_MSCA, p_ahi + AO_SMF, p_alo + AO_SMF,
        p_whi + WO_FC1, p_wlo + WO_FC1, fc1b, nullptr,
        nullptr, p_ahi + AO_MH, p_alo + AO_MH, ROWS, 2048, 1024, 1.f, 2048);
    gemm_bf16<0, false, false, 3><<<dim3(512/64, ROWS/128), 256, G_SMEM3>>>(
        p_ahi + AO_MH, p_alo + AO_MH, nullptr, nullptr,
        p_whi + WO_FC2, p_wlo + WO_FC2, fc2b, nullptr,
        out, nullptr, nullptr, ROWS, 512, 2048, 1.f, 512);
}

// round 9
// speedup vs baseline: 4.1647x; 1.0652x over previous
#include <cuda_runtime.h>
#include <cuda_bf16.h>
#include <math.h>

typedef unsigned short u16;

// ---------------- problem constants ----------------
#define BSZ   8
#define SEQL  512
#define NSC   4096
#define FD    512
#define ROWS  (BSZ*SEQL)        // 4096
#define KVROWS (BSZ*NSC)        // 32768

// ---------------- scratch (device globals; no allocation allowed) ----------
__device__ float g_x[ROWS*FD];

// split bf16 plane bundles (hi/lo)
#define WO_QKV   0
#define WO_OUT   786432
#define WO_FF1   1048576
#define WO_FF2   1310720
#define WO_SAQ   1572864
#define WO_SAKV  1835008
#define WO_SAOUT 2359296
#define WO_FC1   2621440
#define WO_FC2   4718592
__device__ u16 w_hi[5767168];
__device__ u16 w_lo[5767168];

#define AO_H    0
#define AO_O    2097152
#define AO_H2   4194304
#define AO_FF   6291456
#define AO_MSCA 8388608
#define AO_SM   10485760
#define AO_SMF  12582912
#define AO_MH   14680064
#define AO_SF   23068672
__device__ u16 a_hi[39845888];
__device__ u16 a_lo[39845888];

// single-bf16 planes
#define BO_QSA 0
#define BO_KV  2097152
#define BO_QKV 35651584           // ROWS*1536
__device__ u16 a_b16[41943040];

// ---------------- helpers ----------------
__device__ __forceinline__ unsigned smem_u32(const void* p) {
    unsigned r;
    asm("{ .reg .u64 t; cvta.to.shared.u64 t, %1; cvt.u32.u64 %0, t; }"
        : "=r"(r) : "l"(p));
    return r;
}
__device__ __forceinline__ void split2(float x0, float x1,
                                       unsigned& hi2, unsigned& lo2) {
    asm("cvt.rn.bf16x2.f32 %0, %1, %2;" : "=r"(hi2) : "f"(x1), "f"(x0));
    float h0 = __uint_as_float(hi2 << 16);
    float h1 = __uint_as_float(hi2 & 0xffff0000u);
    float l0 = x0 - h0;
    float l1 = x1 - h1;
    asm("cvt.rn.bf16x2.f32 %0, %1, %2;" : "=r"(lo2) : "f"(l1), "f"(l0));
}
__device__ __forceinline__ unsigned pkbf(float lo, float hi) {
    unsigned r;
    asm("cvt.rn.bf16x2.f32 %0, %1, %2;" : "=r"(r) : "f"(hi), "f"(lo));
    return r;
}
__device__ __forceinline__ float gelu_exact(float x) {
    return 0.5f * x * (1.0f + erff(x * 0.70710678118654752f));
}
__device__ __forceinline__ void cp16(unsigned dst, const void* src) {
    asm volatile("cp.async.cg.shared.global [%0], [%1], 16;" :: "r"(dst), "l"(src));
}
#define CP_COMMIT() asm volatile("cp.async.commit_group;" ::: "memory")
#define CP_WAIT1()  asm volatile("cp.async.wait_group 1;" ::: "memory")
#define CP_WAIT0()  asm volatile("cp.async.wait_group 0;" ::: "memory")

#define LDSM4(r, addr) \
    asm volatile("ldmatrix.sync.aligned.m8n8.x4.shared.b16 {%0,%1,%2,%3}, [%4];" \
        : "=r"((r)[0]), "=r"((r)[1]), "=r"((r)[2]), "=r"((r)[3]) : "r"(addr))
#define LDSM4T(r, addr) \
    asm volatile("ldmatrix.sync.aligned.m8n8.x4.trans.shared.b16 {%0,%1,%2,%3}, [%4];" \
        : "=r"((r)[0]), "=r"((r)[1]), "=r"((r)[2]), "=r"((r)[3]) : "r"(addr))
#define MMA16816(d, a, b0, b1) \
    asm volatile("mma.sync.aligned.m16n8k16.row.col.f32.bf16.bf16.f32 " \
        "{%0,%1,%2,%3}, {%4,%5,%6,%7}, {%8,%9}, {%0,%1,%2,%3};" \
        : "+f"((d)[0]), "+f"((d)[1]), "+f"((d)[2]), "+f"((d)[3]) \
        : "r"((a)[0]), "r"((a)[1]), "r"((a)[2]), "r"((a)[3]), \
          "r"(b0), "r"(b1))

// ---------------- merged fp32 -> split planes converter --------------------
struct ConvSeg { const float* src; u16* hi; u16* lo; int n4; int blk0; };
struct ConvTab { ConvSeg s[10]; };

__global__ void __launch_bounds__(256)
conv_multi(ConvTab t, int nseg) {
    const int blk = blockIdx.x;
    int si = 0;
    #pragma unroll
    for (int k = 1; k < 10; k++)
        if (k < nseg && blk >= t.s[k].blk0) si = k;
    const ConvSeg sg = t.s[si];
    int i = (blk - sg.blk0) * 256 + threadIdx.x;
    if (i >= sg.n4) return;
    float4 v = *(const float4*)(sg.src + (size_t)i * 4);
    unsigned h01, l01, h23, l23;
    split2(v.x, v.y, h01, l01);
    split2(v.z, v.w, h23, l23);
    *(uint2*)(sg.hi + (size_t)i * 4) = make_uint2(h01, h23);
    if (sg.lo)
        *(uint2*)(sg.lo + (size_t)i * 4) = make_uint2(l01, l23);
}

#define PADW 72   // u16 stride per row (144 B) -> conflict-free ldmatrix phases

// ====== narrow HMMA bf16-split GEMM (BN=64): C[M,N] = epi( A @ W^T ) ========
// BK=64, 2-stage cp.async double buffer, block 128x64, 8 warps.
// PASSES=3: AhBh + AhBl + AlBh.  PASSES=2: AhBh + AhBl (A-lo never loaded).
// OMODE: 0 fp32 out, 1 split-plane, 2 single-bf16. alpha on cols < ncut.
template<int OMODE, bool GELU, bool CAT, int PASSES>
__global__ void __launch_bounds__(256, 2)
gemm_bf16(const u16* __restrict__ Ah, const u16* __restrict__ Al,
          const u16* __restrict__ A2h, const u16* __restrict__ A2l,
          const u16* __restrict__ Wh, const u16* __restrict__ Wl,
          const float* __restrict__ bias, const float* __restrict__ res,
          float* __restrict__ Cf, u16* __restrict__ Chi, u16* __restrict__ Clo,
          int M, int N, int K, float alpha, int ncut) {
    constexpr unsigned ALB  = 18432u;                           // A plane bytes
    constexpr unsigned BHB  = (PASSES == 3) ? 36864u : 18432u;  // B-hi offset
    constexpr unsigned BPL  = 9216u;                            // B plane bytes
    constexpr unsigned STGB = BHB + 2u * BPL;

    extern __shared__ __align__(16) u16 smu[];
    const unsigned sb = smem_u32(smu);
    const int tid = threadIdx.x;
    const int lane = tid & 31;
    const int wid = tid >> 5;
    const int wm = wid & 3;
    const int wn = wid >> 2;
    const int m0 = blockIdx.y * 128;
    const int n0 = blockIdx.x * 64;

    float acc[2][4][4];
    #pragma unroll
    for (int mt = 0; mt < 2; mt++)
        #pragma unroll
        for (int nt = 0; nt < 4; nt++)
            #pragma unroll
            for (int e = 0; e < 4; e++) acc[mt][nt][e] = 0.f;

    const int lr = lane & 7;
    const int arow = lr + ((lane >> 3) & 1) * 8;
    const int acol = (lane >> 4) * 8;
    const int brow = (lane >> 4) * 8 + lr;
    const int bcol = ((lane >> 3) & 1) * 8;

    auto issue = [&](int ch, int st) {
        const int k0 = ch * 64;
        const unsigned base = sb + st * STGB;
        const u16 *pAh, *pAl;
        int astr, ac;
        if (CAT) {
            if (k0 < 512) { pAh = Ah;  pAl = Al;  ac = k0; }
            else          { pAh = A2h; pAl = A2l; ac = k0 - 512; }
            astr = 512;
        } else { pAh = Ah; pAl = Al; ac = k0; astr = K; }
        #pragma unroll
        for (int i = 0; i < 4; i++) {
            int u = tid + i * 256;
            int r = u >> 3, q = u & 7;
            unsigned d = base + (r * PADW + q * 8) * 2;
            size_t so = (size_t)(m0 + r) * astr + ac + q * 8;
            cp16(d, pAh + so);
            if (PASSES == 3) cp16(d + ALB, pAl + so);
        }
        #pragma unroll
        for (int i = 0; i < 2; i++) {
            int u = tid + i * 256;
            int r = u >> 3, q = u & 7;
            unsigned d = base + BHB + (r * PADW + q * 8) * 2;
            size_t so = (size_t)(n0 + r) * K + k0 + q * 8;
            cp16(d, Wh + so);
            cp16(d + BPL, Wl + so);
        }
        CP_COMMIT();
    };

    const int chunks = K >> 6;
    issue(0, 0);
    for (int ch = 0; ch < chunks; ch++) {
        const int st = ch & 1;
        if (ch + 1 < chunks) { issue(ch + 1, st ^ 1); CP_WAIT1(); }
        else CP_WAIT0();
        __syncthreads();

        const unsigned aH = sb + st * STGB;
        const unsigned aL = aH + ALB;
        const unsigned bH = aH + BHB;
        const unsigned bL = bH + BPL;

        #pragma unroll
        for (int ks = 0; ks < 4; ks++) {
            unsigned ah[2][4], al[2][4], bh[2][4], bl[2][4];
            #pragma unroll
            for (int mt = 0; mt < 2; mt++) {
                unsigned off =
                    (unsigned)((wm*32 + mt*16 + arow) * PADW + ks*16 + acol) * 2u;
                LDSM4(ah[mt], aH + off);
                if (PASSES == 3) LDSM4(al[mt], aL + off);
            }
            #pragma unroll
            for (int np = 0; np < 2; np++) {
                unsigned off =
                    (unsigned)((wn*32 + np*16 + brow) * PADW + ks*16 + bcol) * 2u;
                LDSM4(bh[np], bH + off);
                LDSM4(bl[np], bL + off);
            }
            #pragma unroll
            for (int mt = 0; mt < 2; mt++) {
                #pragma unroll
                for (int nt = 0; nt < 4; nt++) {
                    const int p = nt >> 1, o = (nt & 1) * 2;
                    MMA16816(acc[mt][nt], ah[mt], bh[p][o], bh[p][o+1]);
                    MMA16816(acc[mt][nt], ah[mt], bl[p][o], bl[p][o+1]);
                    if (PASSES == 3)
                        MMA16816(acc[mt][nt], al[mt], bh[p][o], bh[p][o+1]);
                }
            }
        }
        __syncthreads();
    }

    // epilogue
    const int erow = lane >> 2;
    const int ecol = (lane & 3) * 2;
    #pragma unroll
    for (int mt = 0; mt < 2; mt++) {
        #pragma unroll
        for (int nt = 0; nt < 4; nt++) {
            int row = m0 + wm*32 + mt*16 + erow;
            int col = n0 + wn*32 + nt*8 + ecol;
            float aeff = (col < ncut) ? alpha : 1.f;
            float2 bv = *(const float2*)(bias + col);
            #pragma unroll
            for (int half = 0; half < 2; half++) {
                int r = row + half * 8;
                float v0 = (acc[mt][nt][half*2 + 0] + bv.x) * aeff;
                float v1 = (acc[mt][nt][half*2 + 1] + bv.y) * aeff;
                if (GELU) { v0 = gelu_exact(v0); v1 = gelu_exact(v1); }
                if (res) {
                    float2 rv = *(const float2*)(res + (size_t)r * N + col);
                    v0 += rv.x; v1 += rv.y;
                }
                if (OMODE == 0) {
                    *(float2*)(Cf + (size_t)r * N + col) = make_float2(v0, v1);
                } else if (OMODE == 1) {
                    unsigned h2, l2;
                    split2(v0, v1, h2, l2);
                    *(unsigned*)(Chi + (size_t)r * N + col) = h2;
                    *(unsigned*)(Clo + (size_t)r * N + col) = l2;
                } else {
                    *(unsigned*)(Chi + (size_t)r * N + col) = pkbf(v0, v1);
                }
            }
        }
    }
}

// ====== wide HMMA GEMM (BN=128, 2-pass, bf16 out): big N GEMMs ==============
// Block 128x128, BK=64, 8 warps (4m x 2n), warp tile 32x64, 2-stage.
// Halves A/B global+L2 traffic per FLOP vs BN=64.
__global__ void __launch_bounds__(256, 2)
gemm_w(const u16* __restrict__ Ah, const u16* __restrict__ Wh,
       const u16* __restrict__ Wl, const float* __restrict__ bias,
       u16* __restrict__ Chi, int M, int N, int K, float alpha, int ncut) {
    constexpr unsigned APL  = 18432u;       // 128 x 72 u16
    constexpr unsigned STGB = 3u * APL;     // A-hi | B-hi | B-lo

    extern __shared__ __align__(16) u16 smu[];
    const unsigned sb = smem_u32(smu);
    const int tid = threadIdx.x;
    const int lane = tid & 31;
    const int wid = tid >> 5;
    const int wm = wid & 3;
    const int wn = wid >> 2;
    const int m0 = blockIdx.y * 128;
    const int n0 = blockIdx.x * 128;

    float acc[2][8][4];
    #pragma unroll
    for (int mt = 0; mt < 2; mt++)
        #pragma unroll
        for (int nt = 0; nt < 8; nt++)
            #pragma unroll
            for (int e = 0; e < 4; e++) acc[mt][nt][e] = 0.f;

    const int lr = lane & 7;
    const int arow = lr + ((lane >> 3) & 1) * 8;
    const int acol = (lane >> 4) * 8;
    const int brow = (lane >> 4) * 8 + lr;
    const int bcol = ((lane >> 3) & 1) * 8;

    auto issue = [&](int ch, int st) {
        const int k0 = ch * 64;
        const unsigned base = sb + st * STGB;
        #pragma unroll
        for (int i = 0; i < 4; i++) {
            int u = tid + i * 256;
            int r = u >> 3, q = u & 7;
            unsigned d = base + (r * PADW + q * 8) * 2;
            cp16(d, Ah + (size_t)(m0 + r) * K + k0 + q * 8);
        }
        #pragma unroll
        for (int i = 0; i < 4; i++) {
            int u = tid + i * 256;
            int r = u >> 3, q = u & 7;
            unsigned d = base + APL + (r * PADW + q * 8) * 2;
            size_t so = (size_t)(n0 + r) * K + k0 + q * 8;
            cp16(d, Wh + so);
            cp16(d + APL, Wl + so);
        }
        CP_COMMIT();
    };

    const int chunks = K >> 6;
    issue(0, 0);
    for (int ch = 0; ch < chunks; ch++) {
        const int st = ch & 1;
        if (ch + 1 < chunks) { issue(ch + 1, st ^ 1); CP_WAIT1(); }
        else CP_WAIT0();
        __syncthreads();

        const unsigned aH = sb + st * STGB;
        const unsigned bH = aH + APL;
        const unsigned bL = bH + APL;

        #pragma unroll
        for (int ks = 0; ks < 4; ks++) {
            unsigned ah[2][4], bh[4][4], bl[4][4];
            #pragma unroll
            for (int mt = 0; mt < 2; mt++) {
                unsigned off =
                    (unsigned)((wm*32 + mt*16 + arow) * PADW + ks*16 + acol) * 2u;
                LDSM4(ah[mt], aH + off);
            }
            #pragma unroll
            for (int np = 0; np < 4; np++) {
                unsigned off =
                    (unsigned)((wn*64 + np*16 + brow) * PADW + ks*16 + bcol) * 2u;
                LDSM4(bh[np], bH + off);
                LDSM4(bl[np], bL + off);
            }
            #pragma unroll
            for (int mt = 0; mt < 2; mt++) {
                #pragma unroll
                for (int nt = 0; nt < 8; nt++) {
                    const int p = nt >> 1, o = (nt & 1) * 2;
                    MMA16816(acc[mt][nt], ah[mt], bh[p][o], bh[p][o+1]);
                    MMA16816(acc[mt][nt], ah[mt], bl[p][o], bl[p][o+1]);
                }
            }
        }
        __syncthreads();
    }

    const int erow = lane >> 2;
    const int ecol = (lane & 3) * 2;
    #pragma unroll
    for (int mt = 0; mt < 2; mt++) {
        #pragma unroll
        for (int nt = 0; nt < 8; nt++) {
            int row = m0 + wm*32 + mt*16 + erow;
            int col = n0 + wn*64 + nt*8 + ecol;
            float aeff = (col < ncut) ? alpha : 1.f;
            float2 bv = *(const float2*)(bias + col);
            #pragma unroll
            for (int half = 0; half < 2; half++) {
                int r = row + half * 8;
                float v0 = (acc[mt][nt][half*2 + 0] + bv.x) * aeff;
                float v1 = (acc[mt][nt][half*2 + 1] + bv.y) * aeff;
                *(unsigned*)(Chi + (size_t)r * N + col) = pkbf(v0, v1);
            }
        }
    }
}

// ---------------- LayerNorm (512) -> split planes (ol may be null) ----------
__global__ void __launch_bounds__(128)
ln_split(const float* __restrict__ x, const float* __restrict__ g,
         const float* __restrict__ b, u16* __restrict__ oh,
         u16* __restrict__ ol) {
    __shared__ float red[4];
    const int row = blockIdx.x;
    const int t = threadIdx.x;
    const float* xr = x + (size_t)row * 512;
    float4 v = *(const float4*)(xr + t * 4);
    float s = v.x + v.y + v.z + v.w;
    #pragma unroll
    for (int off = 16; off; off >>= 1) s += __shfl_xor_sync(0xffffffffu, s, off);
    if ((t & 31) == 0) red[t >> 5] = s;
    __syncthreads();
    s = red[0] + red[1] + red[2] + red[3];
    const float mean = s * (1.f / 512.f);
    __syncthreads();
    float d0 = v.x - mean, d1 = v.y - mean, d2 = v.z - mean, d3 = v.w - mean;
    float ss = d0*d0 + d1*d1 + d2*d2 + d3*d3;
    #pragma unroll
    for (int off = 16; off; off >>= 1) ss += __shfl_xor_sync(0xffffffffu, ss, off);
    if ((t & 31) == 0) red[t >> 5] = ss;
    __syncthreads();
    ss = red[0] + red[1] + red[2] + red[3];
    const float rstd = rsqrtf(ss * (1.f / 512.f) + 1e-5f);
    float4 g4 = *(const float4*)(g + t * 4);
    float4 b4 = *(const float4*)(b + t * 4);
    float n0 = d0 * rstd * g4.x + b4.x;
    float n1 = d1 * rstd * g4.y + b4.y;
    float n2 = d2 * rstd * g4.z + b4.z;
    float n3 = d3 * rstd * g4.w + b4.w;
    size_t off = (size_t)row * 512 + t * 4;
    if (ol) {
        unsigned h2, l2;
        split2(n0, n1, h2, l2);
        *(unsigned*)(oh + off) = h2;  *(unsigned*)(ol + off) = l2;
        split2(n2, n3, h2, l2);
        *(unsigned*)(oh + off + 2) = h2;  *(unsigned*)(ol + off + 2) = l2;
    } else {
        *(unsigned*)(oh + off)     = pkbf(n0, n1);
        *(unsigned*)(oh + off + 2) = pkbf(n2, n3);
    }
}

// ---------------- encoder self-attention (HMMA flash, dh=64) ----------------
#define ENC_QU   (128*72)
#define ENC_KVST (64*72)
#define ENC_SMEM_BYTES ((ENC_QU + 4*ENC_KVST)*2)

__global__ void __launch_bounds__(256, 2)
enc_attn_mma(const u16* __restrict__ qkv, u16* __restrict__ ohi,
             u16* __restrict__ olo) {
    extern __shared__ __align__(16) u16 smu[];
    const unsigned sb = smem_u32(smu);
    const int tid = threadIdx.x;
    const int lane = tid & 31;
    const int wid = tid >> 5;
    const int b = blockIdx.y >> 3;
    const int h = blockIdx.y & 7;
    const int q0 = blockIdx.x * 128;

    {
        const u16* qb = qkv + (size_t)(b*512 + q0) * 1536 + h*64;
        #pragma unroll
        for (int i = 0; i < 4; i++) {
            int u = tid + i * 256;
            int r = u >> 3, c = (u & 7) * 8;
            cp16(sb + (r*72 + c)*2, qb + (size_t)r*1536 + c);
        }
        CP_COMMIT();
    }

    auto loadKV = [&](int kt, int st) {
        const u16* kb = qkv + (size_t)(b*512 + kt*64) * 1536 + 512 + h*64;
        unsigned kbase = sb + (ENC_QU + st * 2 * ENC_KVST) * 2;
        unsigned vbase = kbase + ENC_KVST * 2;
        #pragma unroll
        for (int i = 0; i < 2; i++) {
            int u = tid + i * 256;
            int r = u >> 3, c = (u & 7) * 8;
            size_t so = (size_t)r * 1536 + c;
            cp16(kbase + (r*72 + c)*2, kb + so);
            cp16(vbase + (r*72 + c)*2, kb + so + 512);
        }
        CP_COMMIT();
    };

    loadKV(0, 0);

    float m0r = -1e30f, m1r = -1e30f, l0 = 0.f, l1 = 0.f;
    float acc[8][4];
    #pragma unroll
    for (int dn = 0; dn < 8; dn++)
        #pragma unroll
        for (int e = 0; e < 4; e++) acc[dn][e] = 0.f;

    const int r0 = lane >> 2;
    const int qrow_g = b*512 + q0 + wid*16;
    const unsigned qoff =
        (unsigned)((wid*16 + (lane & 15)) * 72 + (lane >> 4) * 8) * 2;
    const unsigned koff_row = (unsigned)((lane >> 4) * 8 + (lane & 7));
    const unsigned kcol = (unsigned)(((lane >> 3) & 1) * 8);
    const unsigned vrow = (unsigned)((lane & 7) + ((lane >> 4) << 3));

    for (int kt = 0; kt < 8; kt++) {
        const int st = kt & 1;
        if (kt + 1 < 8) { loadKV(kt + 1, st ^ 1); CP_WAIT1(); }
        else CP_WAIT0();
        __syncthreads();

        const unsigned Kb = sb + (ENC_QU + st * 2 * ENC_KVST) * 2;
        const unsigned Vb = Kb + ENC_KVST * 2;

        float s[8][4];
        #pragma unroll
        for (int jn = 0; jn < 8; jn++)
            #pragma unroll
            for (int e = 0; e < 4; e++) s[jn][e] = 0.f;

        #pragma unroll
        for (int kk = 0; kk < 4; kk++) {
            unsigned aq[4];
            LDSM4(aq, sb + qoff + kk * 32);
            #pragma unroll
            for (int jn2 = 0; jn2 < 4; jn2++) {
                unsigned bk[4];
                LDSM4(bk, Kb + ((jn2*16 + koff_row) * 72 + kk*16 + kcol) * 2);
                MMA16816(s[jn2*2],     aq, bk[0], bk[1]);
                MMA16816(s[jn2*2 + 1], aq, bk[2], bk[3]);
            }
        }

        float mx0 = s[0][0], mx1 = s[0][2];
        #pragma unroll
        for (int jn = 0; jn < 8; jn++) {
            mx0 = fmaxf(mx0, fmaxf(s[jn][0], s[jn][1]));
            mx1 = fmaxf(mx1, fmaxf(s[jn][2], s[jn][3]));
        }
        mx0 = fmaxf(mx0, __shfl_xor_sync(0xffffffffu, mx0, 1));
        mx0 = fmaxf(mx0, __shfl_xor_sync(0xffffffffu, mx0, 2));
        mx1 = fmaxf(mx1, __shfl_xor_sync(0xffffffffu, mx1, 1));
        mx1 = fmaxf(mx1, __shfl_xor_sync(0xffffffffu, mx1, 2));
        float mn0 = fmaxf(m0r, mx0), mn1 = fmaxf(m1r, mx1);
        float c0 = __expf(m0r - mn0), c1 = __expf(m1r - mn1);
        float sum0 = 0.f, sum1 = 0.f;
        #pragma unroll
        for (int jn = 0; jn < 8; jn++) {
            s[jn][0] = __expf(s[jn][0] - mn0);
            s[jn][1] = __expf(s[jn][1] - mn0);
            s[jn][2] = __expf(s[jn][2] - mn1);
            s[jn][3] = __expf(s[jn][3] - mn1);
            sum0 += s[jn][0] + s[jn][1];
            sum1 += s[jn][2] + s[jn][3];
        }
        sum0 += __shfl_xor_sync(0xffffffffu, sum0, 1);
        sum0 += __shfl_xor_sync(0xffffffffu, sum0, 2);
        sum1 += __shfl_xor_sync(0xffffffffu, sum1, 1);
        sum1 += __shfl_xor_sync(0xffffffffu, sum1, 2);
        l0 = l0 * c0 + sum0;  l1 = l1 * c1 + sum1;
        m0r = mn0;  m1r = mn1;
        #pragma unroll
        for (int dn = 0; dn < 8; dn++) {
            acc[dn][0] *= c0; acc[dn][1] *= c0;
            acc[dn][2] *= c1; acc[dn][3] *= c1;
        }

        unsigned ap[4][4];
        #pragma unroll
        for (int ks = 0; ks < 4; ks++) {
            ap[ks][0] = pkbf(s[2*ks][0],     s[2*ks][1]);
            ap[ks][1] = pkbf(s[2*ks][2],     s[2*ks][3]);
            ap[ks][2] = pkbf(s[2*ks + 1][0], s[2*ks + 1][1]);
            ap[ks][3] = pkbf(s[2*ks + 1][2], s[2*ks + 1][3]);
        }

        #pragma unroll
        for (int ks = 0; ks < 4; ks++) {
            #pragma unroll
            for (int dn2 = 0; dn2 < 4; dn2++) {
                unsigned bv[4];
                LDSM4T(bv, Vb + ((ks*16 + vrow) * 72 + dn2*16 + kcol) * 2);
                MMA16816(acc[dn2*2],     ap[ks], bv[0], bv[2]);
                MMA16816(acc[dn2*2 + 1], ap[ks], bv[1], bv[3]);
            }
        }
        __syncthreads();
    }

    const float inv0 = 1.f / l0, inv1 = 1.f / l1;
    const size_t orow0 = (size_t)(qrow_g + r0) * 512 + h*64;
    const size_t orow1 = orow0 + (size_t)8 * 512;
    #pragma unroll
    for (int dn = 0; dn < 8; dn++) {
        int col = dn*8 + (lane & 3)*2;
        unsigned h2, l2;
        split2(acc[dn][0]*inv0, acc[dn][1]*inv0, h2, l2);
        *(unsigned*)(ohi + orow0 + col) = h2;
        *(unsigned*)(olo + orow0 + col) = l2;
        split2(acc[dn][2]*inv1, acc[dn][3]*inv1, h2, l2);
        *(unsigned*)(ohi + orow1 + col) = h2;
        *(unsigned*)(olo + orow1 + col) = l2;
    }
}

// ---------------- semantic-aware cross-attention (HMMA flash) ---------------
// BQ=64 (4 warps x 16 rows), BKV=64, dh=128. 256 CTAs, 2 per SM.
// Prior prefetched into registers one KV-tile ahead (hides DRAM latency).
#define SA_QU   (64*136)
#define SA_KVST (64*136)
#define SA_SMEM_BYTES ((SA_QU + 4*SA_KVST)*2)   // 87040

__global__ void __launch_bounds__(128, 2)
sa_attn_mma(const u16* __restrict__ q, const u16* __restrict__ kv,
            const float* __restrict__ prior, u16* __restrict__ smh,
            u16* __restrict__ sml) {
    extern __shared__ __align__(16) u16 smu[];
    const unsigned sb = smem_u32(smu);
    const int tid = threadIdx.x;
    const int lane = tid & 31;
    const int wid = tid >> 5;          // 0..3
    const int b = blockIdx.y >> 2;
    const int h = blockIdx.y & 3;
    const int q0 = blockIdx.x * 64;

    // stage Q (64 x 128)
    {
        const u16* qb = q + (size_t)b*262144 + h*65536 + (size_t)q0*128;
        #pragma unroll
        for (int i = 0; i < 8; i++) {
            int u = tid + i * 128;
            int r = u >> 4, c = (u & 15) * 8;
            cp16(sb + (r*136 + c)*2, qb + (size_t)r*128 + c);
        }
        CP_COMMIT();
    }

    auto loadKV = [&](int kt, int st) {
        const u16* kb = kv + ((size_t)(b*4096 + kt*64))*1024 + h*128;
        unsigned kbase = sb + (SA_QU + st * 2 * SA_KVST) * 2;
        unsigned vbase = kbase + SA_KVST * 2;
        #pragma unroll
        for (int i = 0; i < 8; i++) {
            int u = tid + i * 128;
            int r = u >> 4, c = (u & 15) * 8;
            size_t so = (size_t)r * 1024 + c;
            cp16(kbase + (r*136 + c)*2, kb + so);
            cp16(vbase + (r*136 + c)*2, kb + so + 512);
        }
        CP_COMMIT();
    };

    loadKV(0, 0);

    float m0r = -1e30f, m1r = -1e30f, l0 = 0.f, l1 = 0.f;
    float acc[16][4];
    #pragma unroll
    for (int dn = 0; dn < 16; dn++)
        #pragma unroll
        for (int e = 0; e < 4; e++) acc[dn][e] = 0.f;

    const int r0 = lane >> 2;
    const int qrow_g = b*512 + q0 + wid*16;
    const unsigned qoff =
        (unsigned)((wid*16 + (lane & 15)) * 136 + (lane >> 4) * 8) * 2;
    const unsigned koff_row = (unsigned)((lane >> 4) * 8 + (lane & 7));
    const unsigned kcol = (unsigned)(((lane >> 3) & 1) * 8);
    const unsigned vrow = (unsigned)((lane & 7) + ((lane >> 4) << 3));

    // prior prefetch registers (16 floats = this thread's 64-wide slice)
    const float* prbase = prior + (size_t)(qrow_g + r0) * 4096 + (lane & 3) * 2;
    float pr[8][4];
    auto loadPrior = [&](int kt, float dst[8][4]) {
        const float* pb = prbase + kt * 64;
        const float* pb2 = pb + (size_t)8 * 4096;
        #pragma unroll
        for (int jn = 0; jn < 8; jn++) {
            float2 a = *(const float2*)(pb + jn * 8);
            float2 c = *(const float2*)(pb2 + jn * 8);
            dst[jn][0] = a.x; dst[jn][1] = a.y;
            dst[jn][2] = c.x; dst[jn][3] = c.y;
        }
    };
    loadPrior(0, pr);

    for (int kt = 0; kt < 64; kt++) {
        const int st = kt & 1;
        if (kt + 1 < 64) { loadKV(kt + 1, st ^ 1); CP_WAIT1(); }
        else CP_WAIT0();
        __syncthreads();

        const unsigned Kb = sb + (SA_QU + st * 2 * SA_KVST) * 2;
        const unsigned Vb = Kb + SA_KVST * 2;

        // S initialized from prefetched prior; immediately prefetch next tile
        float s[8][4];
        #pragma unroll
        for (int jn = 0; jn < 8; jn++)
            #pragma unroll
            for (int e = 0; e < 4; e++) s[jn][e] = pr[jn][e];
        if (kt + 1 < 64) loadPrior(kt + 1, pr);   // LDGs overlap QK MMAs below

        #pragma unroll
        for (int kk = 0; kk < 8; kk++) {
            unsigned aq[4];
            LDSM4(aq, sb + qoff + kk * 32);
            #pragma unroll
            for (int jn2 = 0; jn2 < 4; jn2++) {
                unsigned bk[4];
                LDSM4(bk, Kb + ((jn2*16 + koff_row) * 136 + kk*16 + kcol) * 2);
                MMA16816(s[jn2*2],     aq, bk[0], bk[1]);
                MMA16816(s[jn2*2 + 1], aq, bk[2], bk[3]);
            }
        }

        float mx0 = s[0][0], mx1 = s[0][2];
        #pragma unroll
        for (int jn = 0; jn < 8; jn++) {
            mx0 = fmaxf(mx0, fmaxf(s[jn][0], s[jn][1]));
            mx1 = fmaxf(mx1, fmaxf(s[jn][2], s[jn][3]));
        }
        mx0 = fmaxf(mx0, __shfl_xor_sync(0xffffffffu, mx0, 1));
        mx0 = fmaxf(mx0, __shfl_xor_sync(0xffffffffu, mx0, 2));
        mx1 = fmaxf(mx1, __shfl_xor_sync(0xffffffffu, mx1, 1));
        mx1 = fmaxf(mx1, __shfl_xor_sync(0xffffffffu, mx1, 2));
        float mn0 = fmaxf(m0r, mx0), mn1 = fmaxf(m1r, mx1);
        float c0 = __expf(m0r - mn0), c1 = __expf(m1r - mn1);
        float sum0 = 0.f, sum1 = 0.f;
        #pragma unroll
        for (int jn = 0; jn < 8; jn++) {
            s[jn][0] = __expf(s[jn][0] - mn0);
            s[jn][1] = __expf(s[jn][1] - mn0);
            s[jn][2] = __expf(s[jn][2] - mn1);
            s[jn][3] = __expf(s[jn][3] - mn1);
            sum0 += s[jn][0] + s[jn][1];
            sum1 += s[jn][2] + s[jn][3];
        }
        sum0 += __shfl_xor_sync(0xffffffffu, sum0, 1);
        sum0 += __shfl_xor_sync(0xffffffffu, sum0, 2);
        sum1 += __shfl_xor_sync(0xffffffffu, sum1, 1);
        sum1 += __shfl_xor_sync(0xffffffffu, sum1, 2);
        l0 = l0 * c0 + sum0;  l1 = l1 * c1 + sum1;
        m0r = mn0;  m1r = mn1;
        #pragma unroll
        for (int dn = 0; dn < 16; dn++) {
            acc[dn][0] *= c0; acc[dn][1] *= c0;
            acc[dn][2] *= c1; acc[dn][3] *= c1;
        }

        unsigned ap[4][4];
        #pragma unroll
        for (int ks = 0; ks < 4; ks++) {
            ap[ks][0] = pkbf(s[2*ks][0],     s[2*ks][1]);
            ap[ks][1] = pkbf(s[2*ks][2],     s[2*ks][3]);
            ap[ks][2] = pkbf(s[2*ks + 1][0], s[2*ks + 1][1]);
            ap[ks][3] = pkbf(s[2*ks + 1][2], s[2*ks + 1][3]);
        }

        #pragma unroll
        for (int ks = 0; ks < 4; ks++) {
            #pragma unroll
            for (int dn2 = 0; dn2 < 8; dn2++) {
                unsigned bv[4];
                LDSM4T(bv, Vb + ((ks*16 + vrow) * 136 + dn2*16 + kcol) * 2);
                MMA16816(acc[dn2*2],     ap[ks], bv[0], bv[2]);
                MMA16816(acc[dn2*2 + 1], ap[ks], bv[1], bv[3]);
            }
        }
        __syncthreads();
    }

    const float inv0 = 1.f / l0, inv1 = 1.f / l1;
    const size_t orow0 = (size_t)(qrow_g + r0) * 512 + h*128;
    const size_t orow1 = orow0 + (size_t)8 * 512;
    #pragma unroll
    for (int dn = 0; dn < 16; dn++) {
        int col = dn*8 + (lane & 3)*2;
        unsigned h2, l2;
        split2(acc[dn][0]*inv0, acc[dn][1]*inv0, h2, l2);
        *(unsigned*)(smh + orow0 + col) = h2;
        *(unsigned*)(sml + orow0 + col) = l2;
        split2(acc[dn][2]*inv1, acc[dn][3]*inv1, h2, l2);
        *(unsigned*)(smh + orow1 + col) = h2;
        *(unsigned*)(sml + orow1 + col) = l2;
    }
}

// ---------------- launch --------------------------------------------------
extern "C" void kernel_launch(void* const* d_in, const int* in_sizes, int n_in,
                              void* d_out, int out_size) {
    const float* motion      = (const float*)d_in[0];
    const float* scene_feats = (const float*)d_in[2];
    const float* prior       = (const float*)d_in[3];
    const float* ln1g = (const float*)d_in[4];
    const float* ln1b = (const float*)d_in[5];
    const float* qkvw = (const float*)d_in[6];
    const float* qkvb = (const float*)d_in[7];
    const float* outw = (const float*)d_in[8];
    const float* outb = (const float*)d_in[9];
    const float* ln2g = (const float*)d_in[10];
    const float* ln2b = (const float*)d_in[11];
    const float* ff1w = (const float*)d_in[12];
    const float* ff1b = (const float*)d_in[13];
    const float* ff2w = (const float*)d_in[14];
    const float* ff2b = (const float*)d_in[15];
    const float* saqw = (const float*)d_in[16];
    const float* saqb = (const float*)d_in[17];
    const float* sakvw = (const float*)d_in[18];
    const float* sakvb = (const float*)d_in[19];
    const float* saow = (const float*)d_in[20];
    const float* saob = (const float*)d_in[21];
    const float* fc1w = (const float*)d_in[22];
    const float* fc1b = (const float*)d_in[23];
    const float* fc2w = (const float*)d_in[24];
    const float* fc2b = (const float*)d_in[25];
    float* out = (float*)d_out;

    float* p_x;
    u16 *p_whi, *p_wlo, *p_ahi, *p_alo, *p_b16;
    cudaGetSymbolAddress((void**)&p_x,   g_x);
    cudaGetSymbolAddress((void**)&p_whi, w_hi);
    cudaGetSymbolAddress((void**)&p_wlo, w_lo);
    cudaGetSymbolAddress((void**)&p_ahi, a_hi);
    cudaGetSymbolAddress((void**)&p_alo, a_lo);
    cudaGetSymbolAddress((void**)&p_b16, a_b16);

    const int G_SMEM3 = 110592, G_SMEM2 = 73728, G_SMEMW = 110592;
    cudaFuncSetAttribute(gemm_bf16<0, false, false, 3>,
        cudaFuncAttributeMaxDynamicSharedMemorySize, G_SMEM3);
    cudaFuncSetAttribute(gemm_bf16<1, false, false, 3>,
        cudaFuncAttributeMaxDynamicSharedMemorySize, G_SMEM3);
    cudaFuncSetAttribute(gemm_bf16<1, true, false, 3>,
        cudaFuncAttributeMaxDynamicSharedMemorySize, G_SMEM3);
    cudaFuncSetAttribute(gemm_bf16<1, true, true, 3>,
        cudaFuncAttributeMaxDynamicSharedMemorySize, G_SMEM3);
    cudaFuncSetAttribute(gemm_bf16<2, false, false, 2>,
        cudaFuncAttributeMaxDynamicSharedMemorySize, G_SMEM2);
    cudaFuncSetAttribute(gemm_w,
        cudaFuncAttributeMaxDynamicSharedMemorySize, G_SMEMW);
    cudaFuncSetAttribute(enc_attn_mma,
        cudaFuncAttributeMaxDynamicSharedMemorySize, ENC_SMEM_BYTES);
    cudaFuncSetAttribute(sa_attn_mma,
        cudaFuncAttributeMaxDynamicSharedMemorySize, SA_SMEM_BYTES);

    const float sa_scale = 0.044194173824159216f;  // 512^-0.5

    // ---- merged weight + scene_feats split conversion ----
    {
        ConvTab t;
        int blk = 0, i = 0;
        auto add = [&](const float* src, u16* hi, u16* lo, int n) {
            t.s[i] = ConvSeg{src, hi, lo, n / 4, blk};
            blk += (n / 4 + 255) / 256;
            i++;
        };
        add(qkvw,  p_whi + WO_QKV,   p_wlo + WO_QKV,   1536*512);
        add(outw,  p_whi + WO_OUT,   p_wlo + WO_OUT,   512*512);
        add(ff1w,  p_whi + WO_FF1,   p_wlo + WO_FF1,   512*512);
        add(ff2w,  p_whi + WO_FF2,   p_wlo + WO_FF2,   512*512);
        add(saqw,  p_whi + WO_SAQ,   p_wlo + WO_SAQ,   512*512);
        add(sakvw, p_whi + WO_SAKV,  p_wlo + WO_SAKV,  1024*512);
        add(saow,  p_whi + WO_SAOUT, p_wlo + WO_SAOUT, 512*512);
        add(fc1w,  p_whi + WO_FC1,   p_wlo + WO_FC1,   2048*1024);
        add(fc2w,  p_whi + WO_FC2,   p_wlo + WO_FC2,   512*2048);
        add(scene_feats, p_ahi + AO_SF, nullptr, KVROWS*512);   // lo unused (2-pass)
        conv_multi<<<blk, 256>>>(t, i);
    }

    // ---- motion encoder: pre-norm MHA + residual ----
    ln_split<<<ROWS, 128>>>(motion, ln1g, ln1b, p_ahi + AO_H, nullptr);
    gemm_w<<<dim3(1536/128, ROWS/128), 256, G_SMEMW>>>(
        p_ahi + AO_H, p_whi + WO_QKV, p_wlo + WO_QKV, qkvb,
        p_b16 + BO_QKV, ROWS, 1536, 512, 0.125f, 512);
    enc_attn_mma<<<dim3(4, 64), 256, ENC_SMEM_BYTES>>>(
        p_b16 + BO_QKV, p_ahi + AO_O, p_alo + AO_O);
    gemm_bf16<0, false, false, 3><<<dim3(512/64, ROWS/128), 256, G_SMEM3>>>(
        p_ahi + AO_O, p_alo + AO_O, nullptr, nullptr,
        p_whi + WO_OUT, p_wlo + WO_OUT, outb, motion,
        p_x, nullptr, nullptr, ROWS, 512, 512, 1.f, 512);

    // ---- pre-norm MLP + residual ----
    ln_split<<<ROWS, 128>>>(p_x, ln2g, ln2b, p_ahi + AO_H2, p_alo + AO_H2);
    gemm_bf16<1, true, false, 3><<<dim3(512/64, ROWS/128), 256, G_SMEM3>>>(
        p_ahi + AO_H2, p_alo + AO_H2, nullptr, nullptr,
        p_whi + WO_FF1, p_wlo + WO_FF1, ff1b, nullptr,
        nullptr, p_ahi + AO_FF, p_alo + AO_FF, ROWS, 512, 512, 1.f, 512);
    gemm_bf16<1, false, false, 3><<<dim3(512/64, ROWS/128), 256, G_SMEM3>>>(
        p_ahi + AO_FF, p_alo + AO_FF, nullptr, nullptr,
        p_whi + WO_FF2, p_wlo + WO_FF2, ff2b, p_x,
        nullptr, p_ahi + AO_MSCA, p_alo + AO_MSCA, ROWS, 512, 512, 1.f, 512);

    // ---- semantic-aware attention ----
    gemm_bf16<2, false, false, 2><<<dim3(512/64, ROWS/128), 256, G_SMEM2>>>(
        p_ahi + AO_MSCA, nullptr, nullptr, nullptr,
        p_whi + WO_SAQ, p_wlo + WO_SAQ, saqb, nullptr,
        nullptr, p_b16 + BO_QSA, nullptr, ROWS, 512, 512, sa_scale, 512);
    gemm_w<<<dim3(1024/128, KVROWS/128), 256, G_SMEMW>>>(
        p_ahi + AO_SF, p_whi + WO_SAKV, p_wlo + WO_SAKV, sakvb,
        p_b16 + BO_KV, KVROWS, 1024, 512, 1.f, 1024);
    sa_attn_mma<<<dim3(8, 32), 128, SA_SMEM_BYTES>>>(
        p_b16 + BO_QSA, p_b16 + BO_KV, prior,
        p_ahi + AO_SM, p_alo + AO_SM);
    gemm_bf16<1, false, false, 3><<<dim3(512/64, ROWS/128), 256, G_SMEM3>>>(
        p_ahi + AO_SM, p_alo + AO_SM, nullptr, nullptr,
        p_whi + WO_SAOUT, p_wlo + WO_SAOUT, saob, nullptr,
        nullptr, p_ahi + AO_SMF, p_alo + AO_SMF, ROWS, 512, 512, 1.f, 512);

    // ---- concat-free fc1 + fc2 ----
    gemm_bf16<1, true, true, 3><<<dim3(2048/64, ROWS/128), 256, G_SMEM3>>>(
        p_ahi + AO_MSCA, p_alo + AO_MSCA, p_ahi + AO_SMF, p_alo + AO_SMF,
        p_whi + WO_FC1, p_wlo + WO_FC1, fc1b, nullptr,
        nullptr, p_ahi + AO_MH, p_alo + AO_MH, ROWS, 2048, 1024, 1.f, 2048);
    gemm_bf16<0, false, false, 3><<<dim3(512/64, ROWS/128), 256, G_SMEM3>>>(
        p_ahi + AO_MH, p_alo + AO_MH, nullptr, nullptr,
        p_whi + WO_FC2, p_wlo + WO_FC2, fc2b, nullptr,
        out, nullptr, nullptr, ROWS, 512, 2048, 1.f, 512);
}